// round 7
// baseline (speedup 1.0000x reference)
#include <cuda_runtime.h>
#include <math.h>
#include <cstdint>

#define NN 8192
#define EE 131072

// ---------------- scratch (device globals; no allocations allowed) ----------------
__device__ __align__(16) float g_featp[EE * 64];   // bessel+attrs, padded K 40->64
__device__ __align__(16) float g_u[EE];
__device__ __align__(16) float g_Y[EE * 16];
__device__ __align__(16) float g_x[EE * 256];
__device__ __align__(16) float g_t[EE * 256];
__device__ __align__(16) float g_s16[EE * 16];     // xv (x @ Wv0)
__device__ __align__(16) float g_V[EE * 256];      // V after layer-0 rotation
__device__ __align__(16) float g_VV0p[EE * 32];    // VV[:, :, 0] padded 16->32
__device__ __align__(16) float g_wY[NN * 256];
__device__ __align__(16) float g_Bt[360448];       // transposed [N][Kp] tf32 weights

// ---------------- helpers ----------------
__device__ __forceinline__ float tf32r(float v) {
    uint32_t r;
    asm("cvt.rna.tf32.f32 %0, %1;" : "=r"(r) : "f"(v));
    return __uint_as_float(r);
}
__device__ __forceinline__ uint32_t smem_u32(const void* p) {
    uint32_t a;
    asm("{ .reg .u64 t; cvta.to.shared.u64 t, %1; cvt.u32.u64 %0, t; }" : "=r"(a) : "l"(p));
    return a;
}
__device__ __forceinline__ void cp16(uint32_t dst, const void* src) {
    asm volatile("cp.async.cg.shared.global [%0], [%1], 16;" :: "r"(dst), "l"(src));
}
#define CP_COMMIT() asm volatile("cp.async.commit_group;" ::: "memory")
#define CP_WAIT(n)  asm volatile("cp.async.wait_group %0;" :: "n"(n) : "memory")

__device__ __forceinline__ void mma8(float* d, const uint32_t* a, const uint32_t* b) {
    asm volatile(
        "mma.sync.aligned.m16n8k8.row.col.f32.tf32.tf32.f32 "
        "{%0,%1,%2,%3}, {%4,%5,%6,%7}, {%8,%9}, {%0,%1,%2,%3};"
        : "+f"(d[0]), "+f"(d[1]), "+f"(d[2]), "+f"(d[3])
        : "r"(a[0]), "r"(a[1]), "r"(a[2]), "r"(a[3]), "r"(b[0]), "r"(b[1]));
}

__device__ __forceinline__ float silu_f(float t) { return t / (1.0f + __expf(-t)); }

// smem layout (floats): A[128][36], Bt[256][36] per stage, 3 stages
static constexpr int APAD = 36;
static constexpr int BPADT = 36;
static constexpr int STG_A = 128 * APAD;                  // 4608
static constexpr int STG_B = 256 * BPADT;                 // 9216
static constexpr int STG_FLOATS = STG_A + STG_B;          // 13824
static constexpr int SM_FLOATS = 3 * STG_FLOATS;          // 41472 (165888 B)

// ---------------- mma.sync tf32 GEMM: C[E,256] = A[E,K] @ B[K,256] ----------------
// One CTA computes a full 128x256 tile.  B is pre-transposed [256][Kp].
// EPI: 1 = silu, 2 = u*silu, 3 = C = (C + u*silu)/sqrt(2),
//      4 = like 3 but NO C write; instead out[rcv[row]] += dot(row, Wout)*u*inv
template<int EPI>
__global__ __launch_bounds__(256, 1) void mgemm(
    const float* __restrict__ A1, int sA1, int ntA1,   // main A source, stride, #k-tiles
    const float* __restrict__ A2,                      // stride-32 tail source or null
    const float* __restrict__ Bt, int Kp, int nt,      // transposed weights [256][Kp]
    const float* __restrict__ bias, const float* __restrict__ u,
    float* __restrict__ C,
    const float* __restrict__ Wout, const int* __restrict__ rcv,
    float* __restrict__ out)
{
    extern __shared__ float smf[];
    uint32_t sb = smem_u32(smf);
    int tid = threadIdx.x, lane = tid & 31, wid = tid >> 5;
    int warp_m = wid & 1, warp_n = wid >> 1;     // 2 x 4 warp grid, 64x64 warp tile
    int rowBase = blockIdx.x * 128;

    // ---- async tile loader ----
    auto load_tile = [&](int kt, int buf) {
        uint32_t stBase = sb + buf * STG_FLOATS * 4;
        const float* Ap;
        int stride;
        if (kt < ntA1) { Ap = A1 + (size_t)rowBase * sA1 + kt * 32; stride = sA1; }
        else           { Ap = A2 + (size_t)rowBase * 32;            stride = 32;  }
        #pragma unroll
        for (int i = 0; i < 4; i++) {
            int f = tid + i * 256;
            int r = f >> 3, q = f & 7;
            cp16(stBase + (r * APAD + q * 4) * 4, Ap + (size_t)r * stride + q * 4);
        }
        const float* Bp = Bt + kt * 32;
        uint32_t bBase = stBase + STG_A * 4;
        #pragma unroll
        for (int i = 0; i < 8; i++) {
            int f = tid + i * 256;
            int n = f >> 3, q = f & 7;
            cp16(bBase + (n * BPADT + q * 4) * 4, Bp + (size_t)n * Kp + q * 4);
        }
        CP_COMMIT();
    };

    float acc[4][8][4];
    #pragma unroll
    for (int i = 0; i < 4; i++)
        #pragma unroll
        for (int j = 0; j < 8; j++)
            #pragma unroll
            for (int q = 0; q < 4; q++) acc[i][j][q] = 0.f;

    load_tile(0, 0);
    if (nt > 1) load_tile(1, 1);

    for (int kt = 0; kt < nt; kt++) {
        if (kt + 1 < nt) CP_WAIT(1); else CP_WAIT(0);
        __syncthreads();

        const float* As = smf + (kt % 3) * STG_FLOATS;
        const float* Bs = As + STG_A;
        #pragma unroll
        for (int s = 0; s < 4; s++) {
            uint32_t a[4][4], b[8][2];
            int r1 = lane >> 2, c1 = s * 8 + (lane & 3);
            #pragma unroll
            for (int i = 0; i < 4; i++) {
                int rb = warp_m * 64 + i * 16 + r1;
                a[i][0] = __float_as_uint(As[rb * APAD + c1]);
                a[i][1] = __float_as_uint(As[(rb + 8) * APAD + c1]);
                a[i][2] = __float_as_uint(As[rb * APAD + c1 + 4]);
                a[i][3] = __float_as_uint(As[(rb + 8) * APAD + c1 + 4]);
            }
            int kb = s * 8 + (lane & 3), nq = lane >> 2;
            #pragma unroll
            for (int j = 0; j < 8; j++) {
                int cb = warp_n * 64 + j * 8 + nq;
                b[j][0] = __float_as_uint(Bs[cb * BPADT + kb]);
                b[j][1] = __float_as_uint(Bs[cb * BPADT + kb + 4]);
            }
            #pragma unroll
            for (int i = 0; i < 4; i++)
                #pragma unroll
                for (int j = 0; j < 8; j++)
                    mma8(acc[i][j], a[i], b[j]);
        }
        __syncthreads();
        if (kt + 2 < nt) load_tile(kt + 2, (kt + 2) % 3);
    }

    // ---- fused epilogue ----
    const float RS2 = 0.7071067811865476f;
    float wo0[8], wo1[8];
    if (EPI == 4) {
        #pragma unroll
        for (int j = 0; j < 8; j++) {
            int col = warp_n * 64 + j * 8 + 2 * (lane & 3);
            wo0[j] = __ldg(Wout + col);
            wo1[j] = __ldg(Wout + col + 1);
        }
    }
    #pragma unroll
    for (int i = 0; i < 4; i++) {
        int ra = rowBase + warp_m * 64 + i * 16 + (lane >> 2);
        int rb = ra + 8;
        float ua = 0.f, ub = 0.f;
        if (EPI >= 2) { ua = u[ra]; ub = u[rb]; }
        float pa = 0.f, pb = 0.f;
        #pragma unroll
        for (int j = 0; j < 8; j++) {
            int col = warp_n * 64 + j * 8 + 2 * (lane & 3);
            float b0 = __ldg(bias + col), b1 = __ldg(bias + col + 1);
            float t0 = acc[i][j][0] + b0, t1 = acc[i][j][1] + b1;
            float t2 = acc[i][j][2] + b0, t3 = acc[i][j][3] + b1;
            float o0, o1, o2, o3;
            if (EPI == 1) {
                o0 = silu_f(t0); o1 = silu_f(t1); o2 = silu_f(t2); o3 = silu_f(t3);
            } else {
                o0 = ua * silu_f(t0); o1 = ua * silu_f(t1);
                o2 = ub * silu_f(t2); o3 = ub * silu_f(t3);
            }
            if (EPI <= 2) {
                float* pa_ = C + (size_t)ra * 256 + col;
                float* pb_ = C + (size_t)rb * 256 + col;
                *(float2*)pa_ = make_float2(tf32r(o0), tf32r(o1));
                *(float2*)pb_ = make_float2(tf32r(o2), tf32r(o3));
            } else {
                const float* qa = C + (size_t)ra * 256 + col;
                const float* qb = C + (size_t)rb * 256 + col;
                float2 oa = *(const float2*)qa;
                float2 ob = *(const float2*)qb;
                o0 = (oa.x + o0) * RS2; o1 = (oa.y + o1) * RS2;
                o2 = (ob.x + o2) * RS2; o3 = (ob.y + o3) * RS2;
                if (EPI == 3) {
                    *(float2*)(C + (size_t)ra * 256 + col) = make_float2(tf32r(o0), tf32r(o1));
                    *(float2*)(C + (size_t)rb * 256 + col) = make_float2(tf32r(o2), tf32r(o3));
                } else {
                    pa += o0 * wo0[j] + o1 * wo1[j];
                    pb += o2 * wo0[j] + o3 * wo1[j];
                }
            }
        }
        if (EPI == 4) {
            pa += __shfl_xor_sync(0xffffffffu, pa, 1);
            pa += __shfl_xor_sync(0xffffffffu, pa, 2);
            pb += __shfl_xor_sync(0xffffffffu, pb, 1);
            pb += __shfl_xor_sync(0xffffffffu, pb, 2);
            if ((lane & 3) == 0) {
                atomicAdd(out + __ldg(rcv + ra), pa * ua * 0.25f);
                atomicAdd(out + __ldg(rcv + rb), pb * ub * 0.25f);
            }
        }
    }
}

// ---------------- weight transpose+pad+round: Bt[n, k] = tf32(W[k, n]) ----------------
__global__ void k_wprep(const float* __restrict__ W, float* __restrict__ Bt, int K, int Kp)
{
    int idx = blockIdx.x * 256 + threadIdx.x;     // 256*Kp total
    int n = idx / Kp, k = idx % Kp;
    Bt[idx] = (k < K) ? tf32r(W[(size_t)k * 256 + n]) : 0.f;
}

// ---------------- geometry ----------------
__global__ void k_geom(const float* __restrict__ vec, const float* __restrict__ attrs,
                       const int* __restrict__ snd, const int* __restrict__ rcv,
                       float* __restrict__ feat, float* __restrict__ uo, float* __restrict__ Yo)
{
    int e = blockIdx.x * blockDim.x + threadIdx.x;
    if (e >= EE) return;
    float vx = vec[3*e+0], vy = vec[3*e+1], vz = vec[3*e+2];
    float d2 = vx*vx + vy*vy + vz*vz;
    float d  = sqrtf(d2);
    float d6 = d2 * d2 * d2;
    float env = 1.0f + d6 * (-28.0f + d * (48.0f - 21.0f * d));
    uo[e] = env;
    float invd = 1.0f / d;
    const float S2 = 1.4142135623730951f;
    float* fp = feat + (size_t)e * 64;
    #pragma unroll
    for (int k = 1; k <= 8; k++)
        fp[k-1] = tf32r(S2 * sinpif((float)k * d) * invd);
    int s = snd[e], r = rcv[e];
    #pragma unroll
    for (int i = 0; i < 16; i++) fp[8 + i]  = tf32r(attrs[s*16 + i]);
    #pragma unroll
    for (int i = 0; i < 16; i++) fp[24 + i] = tf32r(attrs[r*16 + i]);
    #pragma unroll
    for (int i = 40; i < 64; i++) fp[i] = 0.f;

    float x = vx*invd, y = vy*invd, z = vz*invd;
    const float s3  = 1.7320508075688772f;
    const float s5  = 2.2360679774997896f;
    const float s15 = 3.8729833462074170f;
    const float s7  = 2.6457513110645907f;
    const float c33 = 2.0916500663351885f;
    const float c32 = 10.246950765959598f;
    const float c31 = 1.6201851746019649f;
    float* Yp = Yo + (size_t)e * 16;
    Yp[0]  = 1.0f;
    Yp[1]  = s3 * x;  Yp[2]  = s3 * y;  Yp[3]  = s3 * z;
    Yp[4]  = s15 * x * y;  Yp[5]  = s15 * y * z;
    Yp[6]  = 0.5f * s5 * (3.0f*z*z - 1.0f);
    Yp[7]  = s15 * x * z;
    Yp[8]  = 0.5f * s15 * (x*x - y*y);
    Yp[9]  = c33 * y * (3.0f*x*x - y*y);
    Yp[10] = c32 * x * y * z;
    Yp[11] = c31 * y * (5.0f*z*z - 1.0f);
    Yp[12] = 0.5f * s7 * (5.0f*z*z*z - 3.0f*z);
    Yp[13] = c31 * x * (5.0f*z*z - 1.0f);
    Yp[14] = 0.5f * c32 * z * (x*x - y*y);
    Yp[15] = c33 * x * (x*x - 3.0f*y*y);
}

// ---------------- (E,256) @ (256,16): thread-per-edge, W broadcast from smem ----------
__global__ __launch_bounds__(128) void gemm_n16(const float* __restrict__ X,
                                                const float* __restrict__ W,
                                                float* __restrict__ S)
{
    __shared__ __align__(16) float Ws[4096];
    int tid = threadIdx.x;
    #pragma unroll
    for (int i = 0; i < 8; i++)
        ((float4*)Ws)[tid + i * 128] = ((const float4*)W)[tid + i * 128];
    __syncthreads();
    size_t e = (size_t)blockIdx.x * 128 + tid;
    const float4* xr = (const float4*)(X + e * 256);
    float acc[16];
    #pragma unroll
    for (int c = 0; c < 16; c++) acc[c] = 0.f;
    #pragma unroll 4
    for (int k4 = 0; k4 < 64; k4++) {
        float4 xv = xr[k4];
        float xs[4] = {xv.x, xv.y, xv.z, xv.w};
        #pragma unroll
        for (int j = 0; j < 4; j++) {
            const float4* wr = (const float4*)&Ws[(k4 * 4 + j) * 16];
            #pragma unroll
            for (int q = 0; q < 4; q++) {
                float4 w = wr[q];
                acc[q*4+0] += xs[j] * w.x;
                acc[q*4+1] += xs[j] * w.y;
                acc[q*4+2] += xs[j] * w.z;
                acc[q*4+3] += xs[j] * w.w;
            }
        }
    }
    float4* sp = (float4*)(S + e * 16);
    #pragma unroll
    for (int q = 0; q < 4; q++)
        sp[q] = make_float4(acc[q*4], acc[q*4+1], acc[q*4+2], acc[q*4+3]);
}

// ---------------- fused: w = x @ Wlw, then scatter wY[snd] += w ⊗ Y ----------------
__global__ __launch_bounds__(128) void k_wscatter(const float* __restrict__ X,
                                                  const float* __restrict__ W,
                                                  const float* __restrict__ Y,
                                                  const int* __restrict__ snd,
                                                  float* __restrict__ wY)
{
    __shared__ __align__(16) float Ws[4096];
    int tid = threadIdx.x;
    #pragma unroll
    for (int i = 0; i < 8; i++)
        ((float4*)Ws)[tid + i * 128] = ((const float4*)W)[tid + i * 128];
    __syncthreads();
    size_t e = (size_t)blockIdx.x * 128 + tid;
    const float4* xr = (const float4*)(X + e * 256);
    float acc[16];
    #pragma unroll
    for (int c = 0; c < 16; c++) acc[c] = 0.f;
    #pragma unroll 4
    for (int k4 = 0; k4 < 64; k4++) {
        float4 xv = xr[k4];
        float xs[4] = {xv.x, xv.y, xv.z, xv.w};
        #pragma unroll
        for (int j = 0; j < 4; j++) {
            const float4* wr = (const float4*)&Ws[(k4 * 4 + j) * 16];
            #pragma unroll
            for (int q = 0; q < 4; q++) {
                float4 w = wr[q];
                acc[q*4+0] += xs[j] * w.x;
                acc[q*4+1] += xs[j] * w.y;
                acc[q*4+2] += xs[j] * w.z;
                acc[q*4+3] += xs[j] * w.w;
            }
        }
    }
    float yv[16];
    const float4* Y4 = (const float4*)(Y + e * 16);
    #pragma unroll
    for (int q = 0; q < 4; q++) {
        float4 y = Y4[q];
        yv[q*4+0] = y.x; yv[q*4+1] = y.y; yv[q*4+2] = y.z; yv[q*4+3] = y.w;
    }
    int s = snd[e];
    float* base = wY + (size_t)s * 256;
    #pragma unroll
    for (int m = 0; m < 16; m++) {
        float wv = acc[m];
        #pragma unroll
        for (int i = 0; i < 16; i++)
            atomicAdd(base + m * 16 + i, wv * yv[i]);
    }
}

__global__ void k_zero4(float4* p, int n4)
{
    int i = blockIdx.x * blockDim.x + threadIdx.x;
    if (i < n4) p[i] = make_float4(0.f, 0.f, 0.f, 0.f);
}

// ---------------- layer-0 update: V built on the fly from xv ⊗ Y ----------------
// vv = 0.25 * wY[snd] * (xv * Y); VV0p out; V = vv @ Wlsh (written for layer 1)
__global__ __launch_bounds__(256)
void k_update0(const int* __restrict__ snd, const float* __restrict__ wY,
               const float* __restrict__ s16, const float* __restrict__ Y,
               float* __restrict__ V, float* __restrict__ VV0p,
               const float* __restrict__ Wlsh)
{
    __shared__ float Wsh[256];
    int tid = threadIdx.x;
    Wsh[tid] = Wlsh[tid];
    __syncthreads();
    int idx = blockIdx.x * 256 + tid;
    int e = idx >> 4, m = idx & 15;
    int s = snd[e];
    float xv = s16[idx];
    const float4* wyp = (const float4*)(wY + (size_t)s * 256 + m * 16);
    const float4* yp  = (const float4*)(Y + (size_t)e * 16);
    float vv[16];
    #pragma unroll
    for (int q = 0; q < 4; q++) {
        float4 a = wyp[q];
        float4 y = yp[q];
        vv[q*4+0] = 0.25f * a.x * xv * y.x;
        vv[q*4+1] = 0.25f * a.y * xv * y.y;
        vv[q*4+2] = 0.25f * a.z * xv * y.z;
        vv[q*4+3] = 0.25f * a.w * xv * y.w;
    }
    VV0p[(size_t)e * 32 + m] = tf32r(vv[0]);
    VV0p[(size_t)e * 32 + 16 + m] = 0.f;
    float o[16];
    #pragma unroll
    for (int j = 0; j < 16; j++) o[j] = 0.f;
    #pragma unroll
    for (int i = 0; i < 16; i++) {
        float t = vv[i];
        #pragma unroll
        for (int j = 0; j < 16; j++) o[j] += t * Wsh[i * 16 + j];
    }
    float4* vp = (float4*)(V + (size_t)idx * 16);
    #pragma unroll
    for (int q = 0; q < 4; q++)
        vp[q] = make_float4(o[q*4], o[q*4+1], o[q*4+2], o[q*4+3]);
}

// ---------------- layer-1 update: only VV0 needed (V rotation is dead) -------------
__global__ __launch_bounds__(256)
void k_update1(const int* __restrict__ snd, const float* __restrict__ wY,
               const float* __restrict__ V, float* __restrict__ VV0p)
{
    int idx = blockIdx.x * 256 + threadIdx.x;
    int e = idx >> 4, m = idx & 15;
    int s = snd[e];
    float wy0 = wY[(size_t)s * 256 + m * 16];
    float v0  = V[(size_t)idx * 16];
    VV0p[(size_t)e * 32 + m] = tf32r(0.25f * wy0 * v0);
    VV0p[(size_t)e * 32 + 16 + m] = 0.f;
}

// ---------------- host ----------------
extern "C" void kernel_launch(void* const* d_in, const int* in_sizes, int n_in,
                              void* d_out, int out_size)
{
    const float* attrs = (const float*)d_in[0];
    const float* vec   = (const float*)d_in[1];
    const int*   snd   = (const int*)d_in[2];
    const int*   rcv   = (const int*)d_in[3];
    const float* We0   = (const float*)d_in[4];
    const float* be0   = (const float*)d_in[5];
    const float* We1   = (const float*)d_in[6];
    const float* be1   = (const float*)d_in[7];
    const float* Wv0   = (const float*)d_in[8];
    const float* Wlw   = (const float*)d_in[9];
    const float* Wlsh  = (const float*)d_in[10];
    const float* Wly1  = (const float*)d_in[11];
    const float* bly1  = (const float*)d_in[12];
    const float* Wly2  = (const float*)d_in[13];
    const float* bly2  = (const float*)d_in[14];
    const float* Wout  = (const float*)d_in[15];
    float* out = (float*)d_out;

    float *featp, *uu, *Y, *x, *t, *s16, *V, *VV0p, *wY, *Bt;
    cudaGetSymbolAddress((void**)&featp, g_featp);
    cudaGetSymbolAddress((void**)&uu,    g_u);
    cudaGetSymbolAddress((void**)&Y,     g_Y);
    cudaGetSymbolAddress((void**)&x,     g_x);
    cudaGetSymbolAddress((void**)&t,     g_t);
    cudaGetSymbolAddress((void**)&s16,   g_s16);
    cudaGetSymbolAddress((void**)&V,     g_V);
    cudaGetSymbolAddress((void**)&VV0p,  g_VV0p);
    cudaGetSymbolAddress((void**)&wY,    g_wY);
    cudaGetSymbolAddress((void**)&Bt,    g_Bt);

    // transposed weight regions [256][Kp]
    float* Bt_e0  = Bt + 0;        // Kp=64
    float* Bt_e1  = Bt + 16384;    // Kp=256
    float* Bt_l10 = Bt + 81920;    // Kp=288
    float* Bt_l11 = Bt + 155648;   // Kp=288
    float* Bt_l20 = Bt + 229376;   // Kp=256
    float* Bt_l21 = Bt + 294912;   // Kp=256

    const int SMEM_BYTES = SM_FLOATS * 4;   // 165888
    cudaFuncSetAttribute(mgemm<1>, cudaFuncAttributeMaxDynamicSharedMemorySize, SMEM_BYTES);
    cudaFuncSetAttribute(mgemm<2>, cudaFuncAttributeMaxDynamicSharedMemorySize, SMEM_BYTES);
    cudaFuncSetAttribute(mgemm<3>, cudaFuncAttributeMaxDynamicSharedMemorySize, SMEM_BYTES);
    cudaFuncSetAttribute(mgemm<4>, cudaFuncAttributeMaxDynamicSharedMemorySize, SMEM_BYTES);

    // weight prep (transpose + pad + tf32 round)
    k_wprep<<<64, 256>>>(We0, Bt_e0, 40, 64);
    k_wprep<<<256, 256>>>(We1, Bt_e1, 256, 256);
    k_wprep<<<288, 256>>>(Wly1, Bt_l10, 272, 288);
    k_wprep<<<288, 256>>>(Wly1 + 272 * 256, Bt_l11, 272, 288);
    k_wprep<<<256, 256>>>(Wly2, Bt_l20, 256, 256);
    k_wprep<<<256, 256>>>(Wly2 + 256 * 256, Bt_l21, 256, 256);

    k_geom<<<EE / 256, 256>>>(vec, attrs, snd, rcv, featp, uu, Y);

    const int GB = EE / 128;   // 1024 CTAs
    mgemm<1><<<GB, 256, SMEM_BYTES>>>(featp, 64, 2, nullptr, Bt_e0, 64, 2, be0, nullptr, t,
                                      nullptr, nullptr, nullptr);
    mgemm<2><<<GB, 256, SMEM_BYTES>>>(t, 256, 8, nullptr, Bt_e1, 256, 8, be1, uu, x,
                                      nullptr, nullptr, nullptr);

    gemm_n16<<<EE / 128, 128>>>(x, Wv0, s16);   // xv

    // ---- layer 0 ----
    k_zero4<<<(NN * 256 / 4 + 255) / 256, 256>>>((float4*)wY, NN * 256 / 4);
    k_wscatter<<<EE / 128, 128>>>(x, Wlw, Y, snd, wY);
    k_update0<<<EE * 16 / 256, 256>>>(snd, wY, s16, Y, V, VV0p, Wlsh);
    mgemm<1><<<GB, 256, SMEM_BYTES>>>(x, 256, 8, VV0p, Bt_l10, 288, 9,
                                      bly1, nullptr, t, nullptr, nullptr, nullptr);
    mgemm<3><<<GB, 256, SMEM_BYTES>>>(t, 256, 8, nullptr, Bt_l20, 256, 8,
                                      bly2, uu, x, nullptr, nullptr, nullptr);

    // ---- layer 1 ----
    k_zero4<<<(NN * 256 / 4 + 255) / 256, 256>>>((float4*)wY, NN * 256 / 4);
    k_wscatter<<<EE / 128, 128>>>(x, Wlw + 256 * 16, Y, snd, wY);
    k_update1<<<EE * 16 / 256, 256>>>(snd, wY, V, VV0p);
    mgemm<1><<<GB, 256, SMEM_BYTES>>>(x, 256, 8, VV0p, Bt_l11, 288, 9,
                                      bly1 + 256, nullptr, t, nullptr, nullptr, nullptr);
    k_zero4<<<(NN / 4 + 255) / 256, 256>>>((float4*)out, NN / 4);
    mgemm<4><<<GB, 256, SMEM_BYTES>>>(t, 256, 8, nullptr, Bt_l21, 256, 8,
                                      bly2 + 256, uu, x, Wout, rcv, out);
}

// round 8
// speedup vs baseline: 1.5187x; 1.5187x over previous
#include <cuda_runtime.h>
#include <math.h>
#include <cstdint>

#define NN 8192
#define EE 131072

// ---------------- scratch (device globals; no allocations allowed) ----------------
__device__ __align__(16) float g_featp[EE * 64];   // bessel+attrs, padded K 40->64
__device__ __align__(16) float g_u[EE];
__device__ __align__(16) float g_Y[EE * 16];
__device__ __align__(16) float g_x[EE * 256];
__device__ __align__(16) float g_t[EE * 256];
__device__ __align__(16) float g_s16[EE * 16];     // xv (x @ Wv0), persistent
__device__ __align__(16) float g_w16[EE * 16];     // per-layer w = x @ Wlw[l]
__device__ __align__(16) float g_V[EE * 256];      // V after layer-0 rotation
__device__ __align__(16) float g_VV0p[EE * 32];    // VV[:, :, 0] padded 16->32
__device__ __align__(16) float g_wY[NN * 256];
__device__ __align__(16) float g_Bt[360448];       // transposed [N][Kp] tf32 weights

// ---------------- helpers ----------------
__device__ __forceinline__ float tf32r(float v) {
    uint32_t r;
    asm("cvt.rna.tf32.f32 %0, %1;" : "=r"(r) : "f"(v));
    return __uint_as_float(r);
}
__device__ __forceinline__ uint32_t smem_u32(const void* p) {
    uint32_t a;
    asm("{ .reg .u64 t; cvta.to.shared.u64 t, %1; cvt.u32.u64 %0, t; }" : "=r"(a) : "l"(p));
    return a;
}
__device__ __forceinline__ void cp16(uint32_t dst, const void* src) {
    asm volatile("cp.async.cg.shared.global [%0], [%1], 16;" :: "r"(dst), "l"(src));
}
#define CP_COMMIT() asm volatile("cp.async.commit_group;" ::: "memory")
#define CP_WAIT(n)  asm volatile("cp.async.wait_group %0;" :: "n"(n) : "memory")

__device__ __forceinline__ void mma8(float* d, const uint32_t* a, const uint32_t* b) {
    asm volatile(
        "mma.sync.aligned.m16n8k8.row.col.f32.tf32.tf32.f32 "
        "{%0,%1,%2,%3}, {%4,%5,%6,%7}, {%8,%9}, {%0,%1,%2,%3};"
        : "+f"(d[0]), "+f"(d[1]), "+f"(d[2]), "+f"(d[3])
        : "r"(a[0]), "r"(a[1]), "r"(a[2]), "r"(a[3]), "r"(b[0]), "r"(b[1]));
}

__device__ __forceinline__ float silu_f(float t) { return t / (1.0f + __expf(-t)); }

// smem layout (floats): A[128][36], Bt[256][36] per stage, 3 stages
static constexpr int APAD = 36;
static constexpr int BPADT = 36;
static constexpr int STG_A = 128 * APAD;                  // 4608
static constexpr int STG_B = 256 * BPADT;                 // 9216
static constexpr int STG_FLOATS = STG_A + STG_B;          // 13824
static constexpr int SM_FLOATS = 3 * STG_FLOATS;          // 41472 (165888 B)

// ---------------- mma.sync tf32 GEMM: C[E,256] = A[E,K] @ B[K,256] ----------------
// One CTA computes a full 128x256 tile.  B is pre-transposed [256][Kp].
// EPI: 1 = silu, 2 = u*silu, 3 = C = (C + u*silu)/sqrt(2),
//      4 = like 3 but NO C write; instead out[rcv[row]] += dot(row, Wout)*u*inv
template<int EPI>
__global__ __launch_bounds__(256, 1) void mgemm(
    const float* __restrict__ A1, int sA1, int ntA1,   // main A source, stride, #k-tiles
    const float* __restrict__ A2,                      // stride-32 tail source or null
    const float* __restrict__ Bt, int Kp, int nt,      // transposed weights [256][Kp]
    const float* __restrict__ bias, const float* __restrict__ u,
    float* __restrict__ C,
    const float* __restrict__ Wout, const int* __restrict__ rcv,
    float* __restrict__ out)
{
    extern __shared__ float smf[];
    uint32_t sb = smem_u32(smf);
    int tid = threadIdx.x, lane = tid & 31, wid = tid >> 5;
    int warp_m = wid & 1, warp_n = wid >> 1;     // 2 x 4 warp grid, 64x64 warp tile
    int rowBase = blockIdx.x * 128;

    // ---- async tile loader ----
    auto load_tile = [&](int kt, int buf) {
        uint32_t stBase = sb + buf * STG_FLOATS * 4;
        const float* Ap;
        int stride;
        if (kt < ntA1) { Ap = A1 + (size_t)rowBase * sA1 + kt * 32; stride = sA1; }
        else           { Ap = A2 + (size_t)rowBase * 32;            stride = 32;  }
        #pragma unroll
        for (int i = 0; i < 4; i++) {
            int f = tid + i * 256;
            int r = f >> 3, q = f & 7;
            cp16(stBase + (r * APAD + q * 4) * 4, Ap + (size_t)r * stride + q * 4);
        }
        const float* Bp = Bt + kt * 32;
        uint32_t bBase = stBase + STG_A * 4;
        #pragma unroll
        for (int i = 0; i < 8; i++) {
            int f = tid + i * 256;
            int n = f >> 3, q = f & 7;
            cp16(bBase + (n * BPADT + q * 4) * 4, Bp + (size_t)n * Kp + q * 4);
        }
        CP_COMMIT();
    };

    float acc[4][8][4];
    #pragma unroll
    for (int i = 0; i < 4; i++)
        #pragma unroll
        for (int j = 0; j < 8; j++)
            #pragma unroll
            for (int q = 0; q < 4; q++) acc[i][j][q] = 0.f;

    load_tile(0, 0);
    if (nt > 1) load_tile(1, 1);

    for (int kt = 0; kt < nt; kt++) {
        if (kt + 1 < nt) CP_WAIT(1); else CP_WAIT(0);
        __syncthreads();

        const float* As = smf + (kt % 3) * STG_FLOATS;
        const float* Bs = As + STG_A;
        #pragma unroll
        for (int s = 0; s < 4; s++) {
            uint32_t a[4][4], b[8][2];
            int r1 = lane >> 2, c1 = s * 8 + (lane & 3);
            #pragma unroll
            for (int i = 0; i < 4; i++) {
                int rb = warp_m * 64 + i * 16 + r1;
                a[i][0] = __float_as_uint(As[rb * APAD + c1]);
                a[i][1] = __float_as_uint(As[(rb + 8) * APAD + c1]);
                a[i][2] = __float_as_uint(As[rb * APAD + c1 + 4]);
                a[i][3] = __float_as_uint(As[(rb + 8) * APAD + c1 + 4]);
            }
            int kb = s * 8 + (lane & 3), nq = lane >> 2;
            #pragma unroll
            for (int j = 0; j < 8; j++) {
                int cb = warp_n * 64 + j * 8 + nq;
                b[j][0] = __float_as_uint(Bs[cb * BPADT + kb]);
                b[j][1] = __float_as_uint(Bs[cb * BPADT + kb + 4]);
            }
            #pragma unroll
            for (int i = 0; i < 4; i++)
                #pragma unroll
                for (int j = 0; j < 8; j++)
                    mma8(acc[i][j], a[i], b[j]);
        }
        __syncthreads();
        if (kt + 2 < nt) load_tile(kt + 2, (kt + 2) % 3);
    }

    // ---- fused epilogue ----
    const float RS2 = 0.7071067811865476f;
    float wo0[8], wo1[8];
    if (EPI == 4) {
        #pragma unroll
        for (int j = 0; j < 8; j++) {
            int col = warp_n * 64 + j * 8 + 2 * (lane & 3);
            wo0[j] = __ldg(Wout + col);
            wo1[j] = __ldg(Wout + col + 1);
        }
    }
    #pragma unroll
    for (int i = 0; i < 4; i++) {
        int ra = rowBase + warp_m * 64 + i * 16 + (lane >> 2);
        int rb = ra + 8;
        float ua = 0.f, ub = 0.f;
        if (EPI >= 2) { ua = u[ra]; ub = u[rb]; }
        float pa = 0.f, pb = 0.f;
        #pragma unroll
        for (int j = 0; j < 8; j++) {
            int col = warp_n * 64 + j * 8 + 2 * (lane & 3);
            float b0 = __ldg(bias + col), b1 = __ldg(bias + col + 1);
            float t0 = acc[i][j][0] + b0, t1 = acc[i][j][1] + b1;
            float t2 = acc[i][j][2] + b0, t3 = acc[i][j][3] + b1;
            float o0, o1, o2, o3;
            if (EPI == 1) {
                o0 = silu_f(t0); o1 = silu_f(t1); o2 = silu_f(t2); o3 = silu_f(t3);
            } else {
                o0 = ua * silu_f(t0); o1 = ua * silu_f(t1);
                o2 = ub * silu_f(t2); o3 = ub * silu_f(t3);
            }
            if (EPI <= 2) {
                float* pa_ = C + (size_t)ra * 256 + col;
                float* pb_ = C + (size_t)rb * 256 + col;
                *(float2*)pa_ = make_float2(tf32r(o0), tf32r(o1));
                *(float2*)pb_ = make_float2(tf32r(o2), tf32r(o3));
            } else {
                const float* qa = C + (size_t)ra * 256 + col;
                const float* qb = C + (size_t)rb * 256 + col;
                float2 oa = *(const float2*)qa;
                float2 ob = *(const float2*)qb;
                o0 = (oa.x + o0) * RS2; o1 = (oa.y + o1) * RS2;
                o2 = (ob.x + o2) * RS2; o3 = (ob.y + o3) * RS2;
                if (EPI == 3) {
                    *(float2*)(C + (size_t)ra * 256 + col) = make_float2(tf32r(o0), tf32r(o1));
                    *(float2*)(C + (size_t)rb * 256 + col) = make_float2(tf32r(o2), tf32r(o3));
                } else {
                    pa += o0 * wo0[j] + o1 * wo1[j];
                    pb += o2 * wo0[j] + o3 * wo1[j];
                }
            }
        }
        if (EPI == 4) {
            pa += __shfl_xor_sync(0xffffffffu, pa, 1);
            pa += __shfl_xor_sync(0xffffffffu, pa, 2);
            pb += __shfl_xor_sync(0xffffffffu, pb, 1);
            pb += __shfl_xor_sync(0xffffffffu, pb, 2);
            if ((lane & 3) == 0) {
                atomicAdd(out + __ldg(rcv + ra), pa * ua * 0.25f);
                atomicAdd(out + __ldg(rcv + rb), pb * ub * 0.25f);
            }
        }
    }
}

// ---------------- weight transpose+pad+round: Bt[n, k] = tf32(W[k, n]) ----------------
__global__ void k_wprep(const float* __restrict__ W, float* __restrict__ Bt, int K, int Kp)
{
    int idx = blockIdx.x * 256 + threadIdx.x;     // 256*Kp total
    int n = idx / Kp, k = idx % Kp;
    Bt[idx] = (k < K) ? tf32r(W[(size_t)k * 256 + n]) : 0.f;
}

// ---------------- geometry ----------------
__global__ void k_geom(const float* __restrict__ vec, const float* __restrict__ attrs,
                       const int* __restrict__ snd, const int* __restrict__ rcv,
                       float* __restrict__ feat, float* __restrict__ uo, float* __restrict__ Yo)
{
    int e = blockIdx.x * blockDim.x + threadIdx.x;
    if (e >= EE) return;
    float vx = vec[3*e+0], vy = vec[3*e+1], vz = vec[3*e+2];
    float d2 = vx*vx + vy*vy + vz*vz;
    float d  = sqrtf(d2);
    float d6 = d2 * d2 * d2;
    float env = 1.0f + d6 * (-28.0f + d * (48.0f - 21.0f * d));
    uo[e] = env;
    float invd = 1.0f / d;
    const float S2 = 1.4142135623730951f;
    float* fp = feat + (size_t)e * 64;
    #pragma unroll
    for (int k = 1; k <= 8; k++)
        fp[k-1] = tf32r(S2 * sinpif((float)k * d) * invd);
    int s = snd[e], r = rcv[e];
    #pragma unroll
    for (int i = 0; i < 16; i++) fp[8 + i]  = tf32r(attrs[s*16 + i]);
    #pragma unroll
    for (int i = 0; i < 16; i++) fp[24 + i] = tf32r(attrs[r*16 + i]);
    #pragma unroll
    for (int i = 40; i < 64; i++) fp[i] = 0.f;

    float x = vx*invd, y = vy*invd, z = vz*invd;
    const float s3  = 1.7320508075688772f;
    const float s5  = 2.2360679774997896f;
    const float s15 = 3.8729833462074170f;
    const float s7  = 2.6457513110645907f;
    const float c33 = 2.0916500663351885f;
    const float c32 = 10.246950765959598f;
    const float c31 = 1.6201851746019649f;
    float* Yp = Yo + (size_t)e * 16;
    Yp[0]  = 1.0f;
    Yp[1]  = s3 * x;  Yp[2]  = s3 * y;  Yp[3]  = s3 * z;
    Yp[4]  = s15 * x * y;  Yp[5]  = s15 * y * z;
    Yp[6]  = 0.5f * s5 * (3.0f*z*z - 1.0f);
    Yp[7]  = s15 * x * z;
    Yp[8]  = 0.5f * s15 * (x*x - y*y);
    Yp[9]  = c33 * y * (3.0f*x*x - y*y);
    Yp[10] = c32 * x * y * z;
    Yp[11] = c31 * y * (5.0f*z*z - 1.0f);
    Yp[12] = 0.5f * s7 * (5.0f*z*z*z - 3.0f*z);
    Yp[13] = c31 * x * (5.0f*z*z - 1.0f);
    Yp[14] = 0.5f * c32 * z * (x*x - y*y);
    Yp[15] = c33 * x * (x*x - 3.0f*y*y);
}

// ---------------- (E,256) @ (256,16): thread-per-edge, W broadcast from smem ----------
__global__ __launch_bounds__(128) void gemm_n16(const float* __restrict__ X,
                                                const float* __restrict__ W,
                                                float* __restrict__ S)
{
    __shared__ __align__(16) float Ws[4096];
    int tid = threadIdx.x;
    #pragma unroll
    for (int i = 0; i < 8; i++)
        ((float4*)Ws)[tid + i * 128] = ((const float4*)W)[tid + i * 128];
    __syncthreads();
    size_t e = (size_t)blockIdx.x * 128 + tid;
    const float4* xr = (const float4*)(X + e * 256);
    float acc[16];
    #pragma unroll
    for (int c = 0; c < 16; c++) acc[c] = 0.f;
    #pragma unroll 4
    for (int k4 = 0; k4 < 64; k4++) {
        float4 xv = xr[k4];
        float xs[4] = {xv.x, xv.y, xv.z, xv.w};
        #pragma unroll
        for (int j = 0; j < 4; j++) {
            const float4* wr = (const float4*)&Ws[(k4 * 4 + j) * 16];
            #pragma unroll
            for (int q = 0; q < 4; q++) {
                float4 w = wr[q];
                acc[q*4+0] += xs[j] * w.x;
                acc[q*4+1] += xs[j] * w.y;
                acc[q*4+2] += xs[j] * w.z;
                acc[q*4+3] += xs[j] * w.w;
            }
        }
    }
    float4* sp = (float4*)(S + e * 16);
    #pragma unroll
    for (int q = 0; q < 4; q++)
        sp[q] = make_float4(acc[q*4], acc[q*4+1], acc[q*4+2], acc[q*4+3]);
}

__global__ void k_zero4(float4* p, int n4)
{
    int i = blockIdx.x * blockDim.x + threadIdx.x;
    if (i < n4) p[i] = make_float4(0.f, 0.f, 0.f, 0.f);
}

// ---------------- segment_sum scatter: 16 threads per edge, wide parallelism --------
__global__ void k_scatter(const float* __restrict__ w, const float* __restrict__ Y,
                          const int* __restrict__ snd, float* __restrict__ wY)
{
    int idx = blockIdx.x * blockDim.x + threadIdx.x;   // e*16 + m
    int e = idx >> 4, m = idx & 15;
    float wv = w[idx];
    int s = snd[e];
    float* base = wY + (size_t)s * 256 + m * 16;
    const float4* Y4 = (const float4*)(Y + (size_t)e * 16);
    #pragma unroll
    for (int q = 0; q < 4; q++) {
        float4 y = Y4[q];
        atomicAdd(base + q*4 + 0, wv * y.x);
        atomicAdd(base + q*4 + 1, wv * y.y);
        atomicAdd(base + q*4 + 2, wv * y.z);
        atomicAdd(base + q*4 + 3, wv * y.w);
    }
}

// ---------------- layer-0 update: V built on the fly from xv ⊗ Y ----------------
__global__ __launch_bounds__(256)
void k_update0(const int* __restrict__ snd, const float* __restrict__ wY,
               const float* __restrict__ s16, const float* __restrict__ Y,
               float* __restrict__ V, float* __restrict__ VV0p,
               const float* __restrict__ Wlsh)
{
    __shared__ float Wsh[256];
    int tid = threadIdx.x;
    Wsh[tid] = Wlsh[tid];
    __syncthreads();
    int idx = blockIdx.x * 256 + tid;
    int e = idx >> 4, m = idx & 15;
    int s = snd[e];
    float xv = s16[idx];
    const float4* wyp = (const float4*)(wY + (size_t)s * 256 + m * 16);
    const float4* yp  = (const float4*)(Y + (size_t)e * 16);
    float vv[16];
    #pragma unroll
    for (int q = 0; q < 4; q++) {
        float4 a = wyp[q];
        float4 y = yp[q];
        vv[q*4+0] = 0.25f * a.x * xv * y.x;
        vv[q*4+1] = 0.25f * a.y * xv * y.y;
        vv[q*4+2] = 0.25f * a.z * xv * y.z;
        vv[q*4+3] = 0.25f * a.w * xv * y.w;
    }
    VV0p[(size_t)e * 32 + m] = tf32r(vv[0]);
    VV0p[(size_t)e * 32 + 16 + m] = 0.f;
    float o[16];
    #pragma unroll
    for (int j = 0; j < 16; j++) o[j] = 0.f;
    #pragma unroll
    for (int i = 0; i < 16; i++) {
        float t = vv[i];
        #pragma unroll
        for (int j = 0; j < 16; j++) o[j] += t * Wsh[i * 16 + j];
    }
    float4* vp = (float4*)(V + (size_t)idx * 16);
    #pragma unroll
    for (int q = 0; q < 4; q++)
        vp[q] = make_float4(o[q*4], o[q*4+1], o[q*4+2], o[q*4+3]);
}

// ---------------- layer-1 update: only VV0 needed (V rotation is dead) -------------
__global__ __launch_bounds__(256)
void k_update1(const int* __restrict__ snd, const float* __restrict__ wY,
               const float* __restrict__ V, float* __restrict__ VV0p)
{
    int idx = blockIdx.x * 256 + threadIdx.x;
    int e = idx >> 4, m = idx & 15;
    int s = snd[e];
    float wy0 = wY[(size_t)s * 256 + m * 16];
    float v0  = V[(size_t)idx * 16];
    VV0p[(size_t)e * 32 + m] = tf32r(0.25f * wy0 * v0);
    VV0p[(size_t)e * 32 + 16 + m] = 0.f;
}

// ---------------- host ----------------
extern "C" void kernel_launch(void* const* d_in, const int* in_sizes, int n_in,
                              void* d_out, int out_size)
{
    const float* attrs = (const float*)d_in[0];
    const float* vec   = (const float*)d_in[1];
    const int*   snd   = (const int*)d_in[2];
    const int*   rcv   = (const int*)d_in[3];
    const float* We0   = (const float*)d_in[4];
    const float* be0   = (const float*)d_in[5];
    const float* We1   = (const float*)d_in[6];
    const float* be1   = (const float*)d_in[7];
    const float* Wv0   = (const float*)d_in[8];
    const float* Wlw   = (const float*)d_in[9];
    const float* Wlsh  = (const float*)d_in[10];
    const float* Wly1  = (const float*)d_in[11];
    const float* bly1  = (const float*)d_in[12];
    const float* Wly2  = (const float*)d_in[13];
    const float* bly2  = (const float*)d_in[14];
    const float* Wout  = (const float*)d_in[15];
    float* out = (float*)d_out;

    float *featp, *uu, *Y, *x, *t, *s16, *w16, *V, *VV0p, *wY, *Bt;
    cudaGetSymbolAddress((void**)&featp, g_featp);
    cudaGetSymbolAddress((void**)&uu,    g_u);
    cudaGetSymbolAddress((void**)&Y,     g_Y);
    cudaGetSymbolAddress((void**)&x,     g_x);
    cudaGetSymbolAddress((void**)&t,     g_t);
    cudaGetSymbolAddress((void**)&s16,   g_s16);
    cudaGetSymbolAddress((void**)&w16,   g_w16);
    cudaGetSymbolAddress((void**)&V,     g_V);
    cudaGetSymbolAddress((void**)&VV0p,  g_VV0p);
    cudaGetSymbolAddress((void**)&wY,    g_wY);
    cudaGetSymbolAddress((void**)&Bt,    g_Bt);

    // transposed weight regions [256][Kp]
    float* Bt_e0  = Bt + 0;        // Kp=64
    float* Bt_e1  = Bt + 16384;    // Kp=256
    float* Bt_l10 = Bt + 81920;    // Kp=288
    float* Bt_l11 = Bt + 155648;   // Kp=288
    float* Bt_l20 = Bt + 229376;   // Kp=256
    float* Bt_l21 = Bt + 294912;   // Kp=256

    const int SMEM_BYTES = SM_FLOATS * 4;   // 165888
    cudaFuncSetAttribute(mgemm<1>, cudaFuncAttributeMaxDynamicSharedMemorySize, SMEM_BYTES);
    cudaFuncSetAttribute(mgemm<2>, cudaFuncAttributeMaxDynamicSharedMemorySize, SMEM_BYTES);
    cudaFuncSetAttribute(mgemm<3>, cudaFuncAttributeMaxDynamicSharedMemorySize, SMEM_BYTES);
    cudaFuncSetAttribute(mgemm<4>, cudaFuncAttributeMaxDynamicSharedMemorySize, SMEM_BYTES);

    // weight prep (transpose + pad + tf32 round)
    k_wprep<<<64, 256>>>(We0, Bt_e0, 40, 64);
    k_wprep<<<256, 256>>>(We1, Bt_e1, 256, 256);
    k_wprep<<<288, 256>>>(Wly1, Bt_l10, 272, 288);
    k_wprep<<<288, 256>>>(Wly1 + 272 * 256, Bt_l11, 272, 288);
    k_wprep<<<256, 256>>>(Wly2, Bt_l20, 256, 256);
    k_wprep<<<256, 256>>>(Wly2 + 256 * 256, Bt_l21, 256, 256);

    k_geom<<<EE / 256, 256>>>(vec, attrs, snd, rcv, featp, uu, Y);

    const int GB = EE / 128;   // 1024 CTAs
    mgemm<1><<<GB, 256, SMEM_BYTES>>>(featp, 64, 2, nullptr, Bt_e0, 64, 2, be0, nullptr, t,
                                      nullptr, nullptr, nullptr);
    mgemm<2><<<GB, 256, SMEM_BYTES>>>(t, 256, 8, nullptr, Bt_e1, 256, 8, be1, uu, x,
                                      nullptr, nullptr, nullptr);

    gemm_n16<<<EE / 128, 128>>>(x, Wv0, s16);   // xv, persistent

    // ---- layer 0 ----
    gemm_n16<<<EE / 128, 128>>>(x, Wlw, w16);
    k_zero4<<<(NN * 256 / 4 + 255) / 256, 256>>>((float4*)wY, NN * 256 / 4);
    k_scatter<<<EE * 16 / 256, 256>>>(w16, Y, snd, wY);
    k_update0<<<EE * 16 / 256, 256>>>(snd, wY, s16, Y, V, VV0p, Wlsh);
    mgemm<1><<<GB, 256, SMEM_BYTES>>>(x, 256, 8, VV0p, Bt_l10, 288, 9,
                                      bly1, nullptr, t, nullptr, nullptr, nullptr);
    mgemm<3><<<GB, 256, SMEM_BYTES>>>(t, 256, 8, nullptr, Bt_l20, 256, 8,
                                      bly2, uu, x, nullptr, nullptr, nullptr);

    // ---- layer 1 ----
    gemm_n16<<<EE / 128, 128>>>(x, Wlw + 256 * 16, w16);
    k_zero4<<<(NN * 256 / 4 + 255) / 256, 256>>>((float4*)wY, NN * 256 / 4);
    k_scatter<<<EE * 16 / 256, 256>>>(w16, Y, snd, wY);
    k_update1<<<EE * 16 / 256, 256>>>(snd, wY, V, VV0p);
    mgemm<1><<<GB, 256, SMEM_BYTES>>>(x, 256, 8, VV0p, Bt_l11, 288, 9,
                                      bly1 + 256, nullptr, t, nullptr, nullptr, nullptr);
    k_zero4<<<(NN / 4 + 255) / 256, 256>>>((float4*)out, NN / 4);
    mgemm<4><<<GB, 256, SMEM_BYTES>>>(t, 256, 8, nullptr, Bt_l21, 256, 8,
                                      bly2 + 256, uu, x, Wout, rcv, out);
}

// round 9
// speedup vs baseline: 1.5637x; 1.0296x over previous
#include <cuda_runtime.h>
#include <math.h>
#include <cstdint>

#define NN 8192
#define EE 131072

// ---------------- scratch (device globals; no allocations allowed) ----------------
__device__ __align__(16) float g_featp[EE * 64];   // bessel+attrs, padded K 40->64
__device__ __align__(16) float g_u[EE];
__device__ __align__(16) float g_Y[EE * 16];
__device__ __align__(16) float g_x[EE * 256];
__device__ __align__(16) float g_s16[EE * 16];     // xv (x @ Wv0), persistent
__device__ __align__(16) float g_w16[EE * 16];     // per-layer w = x @ Wlw[l]
__device__ __align__(16) float g_V[EE * 256];      // V after layer-0 rotation
__device__ __align__(16) float g_VV0p[EE * 32];    // VV[:, :, 0] padded 16->32
__device__ __align__(16) float g_wY[NN * 256];
__device__ __align__(16) float g_Bt[360448];       // transposed [N][Kp] tf32 weights

// ---------------- helpers ----------------
__device__ __forceinline__ float tf32r(float v) {
    uint32_t r;
    asm("cvt.rna.tf32.f32 %0, %1;" : "=r"(r) : "f"(v));
    return __uint_as_float(r);
}
__device__ __forceinline__ uint32_t smem_u32(const void* p) {
    uint32_t a;
    asm("{ .reg .u64 t; cvta.to.shared.u64 t, %1; cvt.u32.u64 %0, t; }" : "=r"(a) : "l"(p));
    return a;
}
__device__ __forceinline__ void cp16(uint32_t dst, const void* src) {
    asm volatile("cp.async.cg.shared.global [%0], [%1], 16;" :: "r"(dst), "l"(src));
}
#define CP_COMMIT() asm volatile("cp.async.commit_group;" ::: "memory")
#define CP_WAIT(n)  asm volatile("cp.async.wait_group %0;" :: "n"(n) : "memory")

__device__ __forceinline__ void mma8(float* d, const uint32_t* a, const uint32_t* b) {
    asm volatile(
        "mma.sync.aligned.m16n8k8.row.col.f32.tf32.tf32.f32 "
        "{%0,%1,%2,%3}, {%4,%5,%6,%7}, {%8,%9}, {%0,%1,%2,%3};"
        : "+f"(d[0]), "+f"(d[1]), "+f"(d[2]), "+f"(d[3])
        : "r"(a[0]), "r"(a[1]), "r"(a[2]), "r"(a[3]), "r"(b[0]), "r"(b[1]));
}

__device__ __forceinline__ float silu_f(float t) { return t / (1.0f + __expf(-t)); }

// smem layout (floats):
//   GEMM1 2-stage:  [0, 2*STG_FLOATS)   = [0, 27648)
//   t-tile:         [0, TT_FLOATS)      = [0, 33280)   (aliases GEMM1 stages; used after)
//   B2 2-stage:     [B2_OFF, B2_OFF + 2*STG_B) = [33280, 51712)
static constexpr int APAD = 36;
static constexpr int STG_A = 128 * APAD;                  // 4608
static constexpr int STG_B = 256 * 36;                    // 9216
static constexpr int STG_FLOATS = STG_A + STG_B;          // 13824
static constexpr int TT_STRIDE = 260;                     // conflict-free for frag loads
static constexpr int TT_FLOATS = 128 * TT_STRIDE;         // 33280
static constexpr int B2_OFF = TT_FLOATS;                  // 33280
static constexpr int FSM_FLOATS = B2_OFF + 2 * STG_B;     // 51712 floats = 206848 B

// ---------------- fused GEMM pair ----------------
// GEMM1: T = silu(A[E,K1] @ B1 + bias1)   (T kept in smem, tf32-rounded)
// GEMM2: per EPI on  T @ B2 + bias2  (K=256)
// EPI: 2 = C = u*silu,  3 = C = (C + u*silu)/sqrt(2),
//      4 = no C write; out[rcv[row]] += dot((C+u*silu)/sqrt2, Wout)*u*inv
template<int EPI>
__global__ __launch_bounds__(256, 1) void fgemm(
    const float* __restrict__ A1, int sA1, int ntA1,   // GEMM1 A source, stride, #k-tiles
    const float* __restrict__ A2,                      // stride-32 tail source or null
    const float* __restrict__ B1, int Kp1, int nt1,    // GEMM1 weights [256][Kp1]
    const float* __restrict__ bias1,
    const float* __restrict__ B2,                      // GEMM2 weights [256][256]
    const float* __restrict__ bias2,
    const float* __restrict__ u, float* __restrict__ C,
    const float* __restrict__ Wout, const int* __restrict__ rcv,
    float* __restrict__ out)
{
    extern __shared__ float smf[];
    uint32_t sb = smem_u32(smf);
    int tid = threadIdx.x, lane = tid & 31, wid = tid >> 5;
    int warp_m = wid & 1, warp_n = wid >> 1;     // 2 x 4 warp grid, 64x64 warp tile
    int rowBase = blockIdx.x * 128;

    auto load_tile1 = [&](int kt, int buf) {
        uint32_t stBase = sb + buf * STG_FLOATS * 4;
        const float* Ap;
        int stride;
        if (kt < ntA1) { Ap = A1 + (size_t)rowBase * sA1 + kt * 32; stride = sA1; }
        else           { Ap = A2 + (size_t)rowBase * 32;            stride = 32;  }
        #pragma unroll
        for (int i = 0; i < 4; i++) {
            int f = tid + i * 256;
            int r = f >> 3, q = f & 7;
            cp16(stBase + (r * APAD + q * 4) * 4, Ap + (size_t)r * stride + q * 4);
        }
        const float* Bp = B1 + kt * 32;
        uint32_t bBase = stBase + STG_A * 4;
        #pragma unroll
        for (int i = 0; i < 8; i++) {
            int f = tid + i * 256;
            int n = f >> 3, q = f & 7;
            cp16(bBase + (n * 36 + q * 4) * 4, Bp + (size_t)n * Kp1 + q * 4);
        }
        CP_COMMIT();
    };
    auto load_B2 = [&](int kt, int buf) {
        const float* Bp = B2 + kt * 32;
        uint32_t bBase = sb + (B2_OFF + buf * STG_B) * 4;
        #pragma unroll
        for (int i = 0; i < 8; i++) {
            int f = tid + i * 256;
            int n = f >> 3, q = f & 7;
            cp16(bBase + (n * 36 + q * 4) * 4, Bp + (size_t)n * 256 + q * 4);
        }
        CP_COMMIT();
    };

    float acc[4][8][4];
    auto zero_acc = [&]() {
        #pragma unroll
        for (int i = 0; i < 4; i++)
            #pragma unroll
            for (int j = 0; j < 8; j++)
                #pragma unroll
                for (int q = 0; q < 4; q++) acc[i][j][q] = 0.f;
    };
    // one 32-k slab of MMAs; As has row-stride astride, A cols start at kofs
    auto mma_slab = [&](const float* As, int astride, int kofs, const float* Bs) {
        #pragma unroll
        for (int s = 0; s < 4; s++) {
            uint32_t a[4][4], b[8][2];
            int r1 = lane >> 2, c1 = kofs + s * 8 + (lane & 3);
            #pragma unroll
            for (int i = 0; i < 4; i++) {
                int rb = warp_m * 64 + i * 16 + r1;
                a[i][0] = __float_as_uint(As[rb * astride + c1]);
                a[i][1] = __float_as_uint(As[(rb + 8) * astride + c1]);
                a[i][2] = __float_as_uint(As[rb * astride + c1 + 4]);
                a[i][3] = __float_as_uint(As[(rb + 8) * astride + c1 + 4]);
            }
            int kb = s * 8 + (lane & 3), nq = lane >> 2;
            #pragma unroll
            for (int j = 0; j < 8; j++) {
                int cb = warp_n * 64 + j * 8 + nq;
                b[j][0] = __float_as_uint(Bs[cb * 36 + kb]);
                b[j][1] = __float_as_uint(Bs[cb * 36 + kb + 4]);
            }
            #pragma unroll
            for (int i = 0; i < 4; i++)
                #pragma unroll
                for (int j = 0; j < 8; j++)
                    mma8(acc[i][j], a[i], b[j]);
        }
    };

    // ================= GEMM1 =================
    zero_acc();
    load_tile1(0, 0);
    if (nt1 > 1) load_tile1(1, 1);
    for (int kt = 0; kt < nt1; kt++) {
        if (kt + 1 < nt1) CP_WAIT(1); else CP_WAIT(0);
        __syncthreads();
        const float* As = smf + (kt & 1) * STG_FLOATS;
        mma_slab(As, APAD, 0, As + STG_A);
        __syncthreads();
        if (kt + 2 < nt1) load_tile1(kt + 2, kt & 1);
    }

    // prefetch B2 stages 0,1 (disjoint smem region) while we do the t-tile epilogue
    load_B2(0, 0);
    load_B2(1, 1);

    // GEMM1 epilogue: silu + bias -> t-tile in smem (tf32-rounded)
    #pragma unroll
    for (int i = 0; i < 4; i++) {
        int ra = warp_m * 64 + i * 16 + (lane >> 2);
        int rb = ra + 8;
        #pragma unroll
        for (int j = 0; j < 8; j++) {
            int col = warp_n * 64 + j * 8 + 2 * (lane & 3);
            float b0 = __ldg(bias1 + col), b1 = __ldg(bias1 + col + 1);
            smf[ra * TT_STRIDE + col]     = tf32r(silu_f(acc[i][j][0] + b0));
            smf[ra * TT_STRIDE + col + 1] = tf32r(silu_f(acc[i][j][1] + b1));
            smf[rb * TT_STRIDE + col]     = tf32r(silu_f(acc[i][j][2] + b0));
            smf[rb * TT_STRIDE + col + 1] = tf32r(silu_f(acc[i][j][3] + b1));
        }
    }

    // ================= GEMM2 (K = 256, A = smem t-tile) =================
    zero_acc();
    for (int kt = 0; kt < 8; kt++) {
        if (kt < 7) CP_WAIT(1); else CP_WAIT(0);
        __syncthreads();            // also makes t-tile stores visible at kt=0
        mma_slab(smf, TT_STRIDE, kt * 32, smf + B2_OFF + (kt & 1) * STG_B);
        __syncthreads();
        if (kt + 2 < 8) load_B2(kt + 2, kt & 1);
    }

    // ---- final epilogue ----
    const float RS2 = 0.7071067811865476f;
    float wo0[8], wo1[8];
    if (EPI == 4) {
        #pragma unroll
        for (int j = 0; j < 8; j++) {
            int col = warp_n * 64 + j * 8 + 2 * (lane & 3);
            wo0[j] = __ldg(Wout + col);
            wo1[j] = __ldg(Wout + col + 1);
        }
    }
    #pragma unroll
    for (int i = 0; i < 4; i++) {
        int ra = rowBase + warp_m * 64 + i * 16 + (lane >> 2);
        int rb = ra + 8;
        float ua = u[ra], ub = u[rb];
        float pa = 0.f, pb = 0.f;
        #pragma unroll
        for (int j = 0; j < 8; j++) {
            int col = warp_n * 64 + j * 8 + 2 * (lane & 3);
            float b0 = __ldg(bias2 + col), b1 = __ldg(bias2 + col + 1);
            float o0 = ua * silu_f(acc[i][j][0] + b0);
            float o1 = ua * silu_f(acc[i][j][1] + b1);
            float o2 = ub * silu_f(acc[i][j][2] + b0);
            float o3 = ub * silu_f(acc[i][j][3] + b1);
            if (EPI == 2) {
                *(float2*)(C + (size_t)ra * 256 + col) = make_float2(tf32r(o0), tf32r(o1));
                *(float2*)(C + (size_t)rb * 256 + col) = make_float2(tf32r(o2), tf32r(o3));
            } else {
                float2 oa = *(const float2*)(C + (size_t)ra * 256 + col);
                float2 ob = *(const float2*)(C + (size_t)rb * 256 + col);
                o0 = (oa.x + o0) * RS2; o1 = (oa.y + o1) * RS2;
                o2 = (ob.x + o2) * RS2; o3 = (ob.y + o3) * RS2;
                if (EPI == 3) {
                    *(float2*)(C + (size_t)ra * 256 + col) = make_float2(tf32r(o0), tf32r(o1));
                    *(float2*)(C + (size_t)rb * 256 + col) = make_float2(tf32r(o2), tf32r(o3));
                } else {
                    pa += o0 * wo0[j] + o1 * wo1[j];
                    pb += o2 * wo0[j] + o3 * wo1[j];
                }
            }
        }
        if (EPI == 4) {
            pa += __shfl_xor_sync(0xffffffffu, pa, 1);
            pa += __shfl_xor_sync(0xffffffffu, pa, 2);
            pb += __shfl_xor_sync(0xffffffffu, pb, 1);
            pb += __shfl_xor_sync(0xffffffffu, pb, 2);
            if ((lane & 3) == 0) {
                atomicAdd(out + __ldg(rcv + ra), pa * ua * 0.25f);
                atomicAdd(out + __ldg(rcv + rb), pb * ub * 0.25f);
            }
        }
    }
}

// ---------------- weight transpose+pad+round: Bt[n, k] = tf32(W[k, n]) ----------------
__global__ void k_wprep(const float* __restrict__ W, float* __restrict__ Bt, int K, int Kp)
{
    int idx = blockIdx.x * 256 + threadIdx.x;     // 256*Kp total
    int n = idx / Kp, k = idx % Kp;
    Bt[idx] = (k < K) ? tf32r(W[(size_t)k * 256 + n]) : 0.f;
}

// ---------------- geometry ----------------
__global__ void k_geom(const float* __restrict__ vec, const float* __restrict__ attrs,
                       const int* __restrict__ snd, const int* __restrict__ rcv,
                       float* __restrict__ feat, float* __restrict__ uo, float* __restrict__ Yo)
{
    int e = blockIdx.x * blockDim.x + threadIdx.x;
    if (e >= EE) return;
    float vx = vec[3*e+0], vy = vec[3*e+1], vz = vec[3*e+2];
    float d2 = vx*vx + vy*vy + vz*vz;
    float d  = sqrtf(d2);
    float d6 = d2 * d2 * d2;
    float env = 1.0f + d6 * (-28.0f + d * (48.0f - 21.0f * d));
    uo[e] = env;
    float invd = 1.0f / d;
    const float S2 = 1.4142135623730951f;
    float* fp = feat + (size_t)e * 64;
    #pragma unroll
    for (int k = 1; k <= 8; k++)
        fp[k-1] = tf32r(S2 * sinpif((float)k * d) * invd);
    int s = snd[e], r = rcv[e];
    #pragma unroll
    for (int i = 0; i < 16; i++) fp[8 + i]  = tf32r(attrs[s*16 + i]);
    #pragma unroll
    for (int i = 0; i < 16; i++) fp[24 + i] = tf32r(attrs[r*16 + i]);
    #pragma unroll
    for (int i = 40; i < 64; i++) fp[i] = 0.f;

    float x = vx*invd, y = vy*invd, z = vz*invd;
    const float s3  = 1.7320508075688772f;
    const float s5  = 2.2360679774997896f;
    const float s15 = 3.8729833462074170f;
    const float s7  = 2.6457513110645907f;
    const float c33 = 2.0916500663351885f;
    const float c32 = 10.246950765959598f;
    const float c31 = 1.6201851746019649f;
    float* Yp = Yo + (size_t)e * 16;
    Yp[0]  = 1.0f;
    Yp[1]  = s3 * x;  Yp[2]  = s3 * y;  Yp[3]  = s3 * z;
    Yp[4]  = s15 * x * y;  Yp[5]  = s15 * y * z;
    Yp[6]  = 0.5f * s5 * (3.0f*z*z - 1.0f);
    Yp[7]  = s15 * x * z;
    Yp[8]  = 0.5f * s15 * (x*x - y*y);
    Yp[9]  = c33 * y * (3.0f*x*x - y*y);
    Yp[10] = c32 * x * y * z;
    Yp[11] = c31 * y * (5.0f*z*z - 1.0f);
    Yp[12] = 0.5f * s7 * (5.0f*z*z*z - 3.0f*z);
    Yp[13] = c31 * x * (5.0f*z*z - 1.0f);
    Yp[14] = 0.5f * c32 * z * (x*x - y*y);
    Yp[15] = c33 * x * (x*x - 3.0f*y*y);
}

// ---------------- (E,256) @ (256,16): thread-per-edge, W broadcast from smem ----------
__global__ __launch_bounds__(128) void gemm_n16(const float* __restrict__ X,
                                                const float* __restrict__ W,
                                                float* __restrict__ S)
{
    __shared__ __align__(16) float Ws[4096];
    int tid = threadIdx.x;
    #pragma unroll
    for (int i = 0; i < 8; i++)
        ((float4*)Ws)[tid + i * 128] = ((const float4*)W)[tid + i * 128];
    __syncthreads();
    size_t e = (size_t)blockIdx.x * 128 + tid;
    const float4* xr = (const float4*)(X + e * 256);
    float acc[16];
    #pragma unroll
    for (int c = 0; c < 16; c++) acc[c] = 0.f;
    #pragma unroll 4
    for (int k4 = 0; k4 < 64; k4++) {
        float4 xv = xr[k4];
        float xs[4] = {xv.x, xv.y, xv.z, xv.w};
        #pragma unroll
        for (int j = 0; j < 4; j++) {
            const float4* wr = (const float4*)&Ws[(k4 * 4 + j) * 16];
            #pragma unroll
            for (int q = 0; q < 4; q++) {
                float4 w = wr[q];
                acc[q*4+0] += xs[j] * w.x;
                acc[q*4+1] += xs[j] * w.y;
                acc[q*4+2] += xs[j] * w.z;
                acc[q*4+3] += xs[j] * w.w;
            }
        }
    }
    float4* sp = (float4*)(S + e * 16);
    #pragma unroll
    for (int q = 0; q < 4; q++)
        sp[q] = make_float4(acc[q*4], acc[q*4+1], acc[q*4+2], acc[q*4+3]);
}

__global__ void k_zero4(float4* p, int n4)
{
    int i = blockIdx.x * blockDim.x + threadIdx.x;
    if (i < n4) p[i] = make_float4(0.f, 0.f, 0.f, 0.f);
}

// ---------------- segment_sum scatter: 16 threads per edge, wide parallelism --------
__global__ void k_scatter(const float* __restrict__ w, const float* __restrict__ Y,
                          const int* __restrict__ snd, float* __restrict__ wY)
{
    int idx = blockIdx.x * blockDim.x + threadIdx.x;   // e*16 + m
    int e = idx >> 4, m = idx & 15;
    float wv = w[idx];
    int s = snd[e];
    float* base = wY + (size_t)s * 256 + m * 16;
    const float4* Y4 = (const float4*)(Y + (size_t)e * 16);
    #pragma unroll
    for (int q = 0; q < 4; q++) {
        float4 y = Y4[q];
        atomicAdd(base + q*4 + 0, wv * y.x);
        atomicAdd(base + q*4 + 1, wv * y.y);
        atomicAdd(base + q*4 + 2, wv * y.z);
        atomicAdd(base + q*4 + 3, wv * y.w);
    }
}

// ---------------- layer-0 update: V built on the fly from xv ⊗ Y ----------------
__global__ __launch_bounds__(256)
void k_update0(const int* __restrict__ snd, const float* __restrict__ wY,
               const float* __restrict__ s16, const float* __restrict__ Y,
               float* __restrict__ V, float* __restrict__ VV0p,
               const float* __restrict__ Wlsh)
{
    __shared__ float Wsh[256];
    int tid = threadIdx.x;
    Wsh[tid] = Wlsh[tid];
    __syncthreads();
    int idx = blockIdx.x * 256 + tid;
    int e = idx >> 4, m = idx & 15;
    int s = snd[e];
    float xv = s16[idx];
    const float4* wyp = (const float4*)(wY + (size_t)s * 256 + m * 16);
    const float4* yp  = (const float4*)(Y + (size_t)e * 16);
    float vv[16];
    #pragma unroll
    for (int q = 0; q < 4; q++) {
        float4 a = wyp[q];
        float4 y = yp[q];
        vv[q*4+0] = 0.25f * a.x * xv * y.x;
        vv[q*4+1] = 0.25f * a.y * xv * y.y;
        vv[q*4+2] = 0.25f * a.z * xv * y.z;
        vv[q*4+3] = 0.25f * a.w * xv * y.w;
    }
    VV0p[(size_t)e * 32 + m] = tf32r(vv[0]);
    VV0p[(size_t)e * 32 + 16 + m] = 0.f;
    float o[16];
    #pragma unroll
    for (int j = 0; j < 16; j++) o[j] = 0.f;
    #pragma unroll
    for (int i = 0; i < 16; i++) {
        float t = vv[i];
        #pragma unroll
        for (int j = 0; j < 16; j++) o[j] += t * Wsh[i * 16 + j];
    }
    float4* vp = (float4*)(V + (size_t)idx * 16);
    #pragma unroll
    for (int q = 0; q < 4; q++)
        vp[q] = make_float4(o[q*4], o[q*4+1], o[q*4+2], o[q*4+3]);
}

// ---------------- layer-1 update: only VV0 needed (V rotation is dead) -------------
__global__ __launch_bounds__(256)
void k_update1(const int* __restrict__ snd, const float* __restrict__ wY,
               const float* __restrict__ V, float* __restrict__ VV0p)
{
    int idx = blockIdx.x * 256 + threadIdx.x;
    int e = idx >> 4, m = idx & 15;
    int s = snd[e];
    float wy0 = wY[(size_t)s * 256 + m * 16];
    float v0  = V[(size_t)idx * 16];
    VV0p[(size_t)e * 32 + m] = tf32r(0.25f * wy0 * v0);
    VV0p[(size_t)e * 32 + 16 + m] = 0.f;
}

// ---------------- host ----------------
extern "C" void kernel_launch(void* const* d_in, const int* in_sizes, int n_in,
                              void* d_out, int out_size)
{
    const float* attrs = (const float*)d_in[0];
    const float* vec   = (const float*)d_in[1];
    const int*   snd   = (const int*)d_in[2];
    const int*   rcv   = (const int*)d_in[3];
    const float* We0   = (const float*)d_in[4];
    const float* be0   = (const float*)d_in[5];
    const float* We1   = (const float*)d_in[6];
    const float* be1   = (const float*)d_in[7];
    const float* Wv0   = (const float*)d_in[8];
    const float* Wlw   = (const float*)d_in[9];
    const float* Wlsh  = (const float*)d_in[10];
    const float* Wly1  = (const float*)d_in[11];
    const float* bly1  = (const float*)d_in[12];
    const float* Wly2  = (const float*)d_in[13];
    const float* bly2  = (const float*)d_in[14];
    const float* Wout  = (const float*)d_in[15];
    float* out = (float*)d_out;

    float *featp, *uu, *Y, *x, *s16, *w16, *V, *VV0p, *wY, *Bt;
    cudaGetSymbolAddress((void**)&featp, g_featp);
    cudaGetSymbolAddress((void**)&uu,    g_u);
    cudaGetSymbolAddress((void**)&Y,     g_Y);
    cudaGetSymbolAddress((void**)&x,     g_x);
    cudaGetSymbolAddress((void**)&s16,   g_s16);
    cudaGetSymbolAddress((void**)&w16,   g_w16);
    cudaGetSymbolAddress((void**)&V,     g_V);
    cudaGetSymbolAddress((void**)&VV0p,  g_VV0p);
    cudaGetSymbolAddress((void**)&wY,    g_wY);
    cudaGetSymbolAddress((void**)&Bt,    g_Bt);

    // transposed weight regions [256][Kp]
    float* Bt_e0  = Bt + 0;        // Kp=64
    float* Bt_e1  = Bt + 16384;    // Kp=256
    float* Bt_l10 = Bt + 81920;    // Kp=288
    float* Bt_l11 = Bt + 155648;   // Kp=288
    float* Bt_l20 = Bt + 229376;   // Kp=256
    float* Bt_l21 = Bt + 294912;   // Kp=256

    const int FSM_BYTES = FSM_FLOATS * 4;   // 206848
    cudaFuncSetAttribute(fgemm<2>, cudaFuncAttributeMaxDynamicSharedMemorySize, FSM_BYTES);
    cudaFuncSetAttribute(fgemm<3>, cudaFuncAttributeMaxDynamicSharedMemorySize, FSM_BYTES);
    cudaFuncSetAttribute(fgemm<4>, cudaFuncAttributeMaxDynamicSharedMemorySize, FSM_BYTES);

    // weight prep (transpose + pad + tf32 round)
    k_wprep<<<64, 256>>>(We0, Bt_e0, 40, 64);
    k_wprep<<<256, 256>>>(We1, Bt_e1, 256, 256);
    k_wprep<<<288, 256>>>(Wly1, Bt_l10, 272, 288);
    k_wprep<<<288, 256>>>(Wly1 + 272 * 256, Bt_l11, 272, 288);
    k_wprep<<<256, 256>>>(Wly2, Bt_l20, 256, 256);
    k_wprep<<<256, 256>>>(Wly2 + 256 * 256, Bt_l21, 256, 256);

    k_geom<<<EE / 256, 256>>>(vec, attrs, snd, rcv, featp, uu, Y);

    const int GB = EE / 128;   // 1024 CTAs

    // e0 -> e1 fused:  x = u * silu(silu(feat@We0+be0) @ We1 + be1)
    fgemm<2><<<GB, 256, FSM_BYTES>>>(featp, 64, 2, nullptr,
                                     Bt_e0, 64, 2, be0,
                                     Bt_e1, be1, uu, x,
                                     nullptr, nullptr, nullptr);

    gemm_n16<<<EE / 128, 128>>>(x, Wv0, s16);   // xv, persistent

    // ---- layer 0 ----
    gemm_n16<<<EE / 128, 128>>>(x, Wlw, w16);
    k_zero4<<<(NN * 256 / 4 + 255) / 256, 256>>>((float4*)wY, NN * 256 / 4);
    k_scatter<<<EE * 16 / 256, 256>>>(w16, Y, snd, wY);
    k_update0<<<EE * 16 / 256, 256>>>(snd, wY, s16, Y, V, VV0p, Wlsh);
    fgemm<3><<<GB, 256, FSM_BYTES>>>(x, 256, 8, VV0p,
                                     Bt_l10, 288, 9, bly1,
                                     Bt_l20, bly2, uu, x,
                                     nullptr, nullptr, nullptr);

    // ---- layer 1 ----
    gemm_n16<<<EE / 128, 128>>>(x, Wlw + 256 * 16, w16);
    k_zero4<<<(NN * 256 / 4 + 255) / 256, 256>>>((float4*)wY, NN * 256 / 4);
    k_scatter<<<EE * 16 / 256, 256>>>(w16, Y, snd, wY);
    k_update1<<<EE * 16 / 256, 256>>>(snd, wY, V, VV0p);
    k_zero4<<<(NN / 4 + 255) / 256, 256>>>((float4*)out, NN / 4);
    fgemm<4><<<GB, 256, FSM_BYTES>>>(x, 256, 8, VV0p,
                                     Bt_l11, 288, 9, bly1 + 256,
                                     Bt_l21, bly2 + 256, uu, x,
                                     Wout, rcv, out);
}

// round 10
// speedup vs baseline: 1.6648x; 1.0647x over previous
#include <cuda_runtime.h>
#include <math.h>
#include <cstdint>

#define NN 8192
#define EE 131072

// ---------------- scratch (device globals; no allocations allowed) ----------------
__device__ __align__(16) float g_featp[EE * 64];   // bessel+attrs, padded K 40->64
__device__ __align__(16) float g_u[EE];
__device__ __align__(16) float g_Y[EE * 16];
__device__ __align__(16) float g_x[EE * 256];
__device__ __align__(16) float g_s16[EE * 16];     // xv (x @ Wv0), persistent
__device__ __align__(16) float g_w16[EE * 16];     // per-layer w = x @ Wlw[l]
__device__ __align__(16) float g_V0[EE * 16];      // V[:,:,0] after layer-0 rotation
__device__ __align__(16) float g_VV0p[EE * 32];    // VV[:, :, 0] padded 16->32
__device__ __align__(16) float g_wY[NN * 256];
__device__ __align__(16) float g_Bt[360448];       // transposed [N][Kp] tf32 weights

// ---------------- helpers ----------------
__device__ __forceinline__ float tf32r(float v) {
    uint32_t r;
    asm("cvt.rna.tf32.f32 %0, %1;" : "=r"(r) : "f"(v));
    return __uint_as_float(r);
}
__device__ __forceinline__ uint32_t smem_u32(const void* p) {
    uint32_t a;
    asm("{ .reg .u64 t; cvta.to.shared.u64 t, %1; cvt.u32.u64 %0, t; }" : "=r"(a) : "l"(p));
    return a;
}
__device__ __forceinline__ void cp16(uint32_t dst, const void* src) {
    asm volatile("cp.async.cg.shared.global [%0], [%1], 16;" :: "r"(dst), "l"(src));
}
#define CP_COMMIT() asm volatile("cp.async.commit_group;" ::: "memory")
#define CP_WAIT(n)  asm volatile("cp.async.wait_group %0;" :: "n"(n) : "memory")

__device__ __forceinline__ void mma8(float* d, const uint32_t* a, const uint32_t* b) {
    asm volatile(
        "mma.sync.aligned.m16n8k8.row.col.f32.tf32.tf32.f32 "
        "{%0,%1,%2,%3}, {%4,%5,%6,%7}, {%8,%9}, {%0,%1,%2,%3};"
        : "+f"(d[0]), "+f"(d[1]), "+f"(d[2]), "+f"(d[3])
        : "r"(a[0]), "r"(a[1]), "r"(a[2]), "r"(a[3]), "r"(b[0]), "r"(b[1]));
}

__device__ __forceinline__ float silu_f(float t) { return t / (1.0f + __expf(-t)); }

// smem layout (floats)
static constexpr int APAD = 36;
static constexpr int STG_A = 128 * APAD;                  // 4608
static constexpr int STG_B = 256 * 36;                    // 9216
static constexpr int STG_FLOATS = STG_A + STG_B;          // 13824
static constexpr int TT_STRIDE = 260;
static constexpr int TT_FLOATS = 128 * TT_STRIDE;         // 33280
static constexpr int B2_OFF = TT_FLOATS;
static constexpr int FSM_FLOATS = B2_OFF + 2 * STG_B;     // 51712 floats = 206848 B

// ---------------- fused GEMM pair ----------------
// GEMM1: T = silu(A[E,K1] @ B1 + bias1)   (T kept in smem, tf32-rounded)
// GEMM2: per EPI on  T @ B2 + bias2  (K=256)
// EPI: 2 = C = u*silu,  3 = C = (C + u*silu)/sqrt(2),
//      4 = no C write; out[rcv[row]] += dot((C+u*silu)/sqrt2, Wout)*u*inv
template<int EPI>
__global__ __launch_bounds__(256, 1) void fgemm(
    const float* __restrict__ A1, int sA1, int ntA1,
    const float* __restrict__ A2,
    const float* __restrict__ B1, int Kp1, int nt1,
    const float* __restrict__ bias1,
    const float* __restrict__ B2,
    const float* __restrict__ bias2,
    const float* __restrict__ u, float* __restrict__ C,
    const float* __restrict__ Wout, const int* __restrict__ rcv,
    float* __restrict__ out)
{
    extern __shared__ float smf[];
    uint32_t sb = smem_u32(smf);
    int tid = threadIdx.x, lane = tid & 31, wid = tid >> 5;
    int warp_m = wid & 1, warp_n = wid >> 1;
    int rowBase = blockIdx.x * 128;

    auto load_tile1 = [&](int kt, int buf) {
        uint32_t stBase = sb + buf * STG_FLOATS * 4;
        const float* Ap;
        int stride;
        if (kt < ntA1) { Ap = A1 + (size_t)rowBase * sA1 + kt * 32; stride = sA1; }
        else           { Ap = A2 + (size_t)rowBase * 32;            stride = 32;  }
        #pragma unroll
        for (int i = 0; i < 4; i++) {
            int f = tid + i * 256;
            int r = f >> 3, q = f & 7;
            cp16(stBase + (r * APAD + q * 4) * 4, Ap + (size_t)r * stride + q * 4);
        }
        const float* Bp = B1 + kt * 32;
        uint32_t bBase = stBase + STG_A * 4;
        #pragma unroll
        for (int i = 0; i < 8; i++) {
            int f = tid + i * 256;
            int n = f >> 3, q = f & 7;
            cp16(bBase + (n * 36 + q * 4) * 4, Bp + (size_t)n * Kp1 + q * 4);
        }
        CP_COMMIT();
    };
    auto load_B2 = [&](int kt, int buf) {
        const float* Bp = B2 + kt * 32;
        uint32_t bBase = sb + (B2_OFF + buf * STG_B) * 4;
        #pragma unroll
        for (int i = 0; i < 8; i++) {
            int f = tid + i * 256;
            int n = f >> 3, q = f & 7;
            cp16(bBase + (n * 36 + q * 4) * 4, Bp + (size_t)n * 256 + q * 4);
        }
        CP_COMMIT();
    };

    float acc[4][8][4];
    auto zero_acc = [&]() {
        #pragma unroll
        for (int i = 0; i < 4; i++)
            #pragma unroll
            for (int j = 0; j < 8; j++)
                #pragma unroll
                for (int q = 0; q < 4; q++) acc[i][j][q] = 0.f;
    };
    auto mma_slab = [&](const float* As, int astride, int kofs, const float* Bs) {
        #pragma unroll
        for (int s = 0; s < 4; s++) {
            uint32_t a[4][4], b[8][2];
            int r1 = lane >> 2, c1 = kofs + s * 8 + (lane & 3);
            #pragma unroll
            for (int i = 0; i < 4; i++) {
                int rb = warp_m * 64 + i * 16 + r1;
                a[i][0] = __float_as_uint(As[rb * astride + c1]);
                a[i][1] = __float_as_uint(As[(rb + 8) * astride + c1]);
                a[i][2] = __float_as_uint(As[rb * astride + c1 + 4]);
                a[i][3] = __float_as_uint(As[(rb + 8) * astride + c1 + 4]);
            }
            int kb = s * 8 + (lane & 3), nq = lane >> 2;
            #pragma unroll
            for (int j = 0; j < 8; j++) {
                int cb = warp_n * 64 + j * 8 + nq;
                b[j][0] = __float_as_uint(Bs[cb * 36 + kb]);
                b[j][1] = __float_as_uint(Bs[cb * 36 + kb + 4]);
            }
            #pragma unroll
            for (int i = 0; i < 4; i++)
                #pragma unroll
                for (int j = 0; j < 8; j++)
                    mma8(acc[i][j], a[i], b[j]);
        }
    };

    // ================= GEMM1 =================
    zero_acc();
    load_tile1(0, 0);
    if (nt1 > 1) load_tile1(1, 1);
    for (int kt = 0; kt < nt1; kt++) {
        if (kt + 1 < nt1) CP_WAIT(1); else CP_WAIT(0);
        __syncthreads();
        const float* As = smf + (kt & 1) * STG_FLOATS;
        mma_slab(As, APAD, 0, As + STG_A);
        __syncthreads();
        if (kt + 2 < nt1) load_tile1(kt + 2, kt & 1);
    }

    load_B2(0, 0);
    load_B2(1, 1);

    // GEMM1 epilogue: silu + bias -> t-tile in smem (tf32-rounded)
    #pragma unroll
    for (int i = 0; i < 4; i++) {
        int ra = warp_m * 64 + i * 16 + (lane >> 2);
        int rb = ra + 8;
        #pragma unroll
        for (int j = 0; j < 8; j++) {
            int col = warp_n * 64 + j * 8 + 2 * (lane & 3);
            float b0 = __ldg(bias1 + col), b1 = __ldg(bias1 + col + 1);
            smf[ra * TT_STRIDE + col]     = tf32r(silu_f(acc[i][j][0] + b0));
            smf[ra * TT_STRIDE + col + 1] = tf32r(silu_f(acc[i][j][1] + b1));
            smf[rb * TT_STRIDE + col]     = tf32r(silu_f(acc[i][j][2] + b0));
            smf[rb * TT_STRIDE + col + 1] = tf32r(silu_f(acc[i][j][3] + b1));
        }
    }

    // ================= GEMM2 (K = 256, A = smem t-tile) =================
    zero_acc();
    for (int kt = 0; kt < 8; kt++) {
        if (kt < 7) CP_WAIT(1); else CP_WAIT(0);
        __syncthreads();
        mma_slab(smf, TT_STRIDE, kt * 32, smf + B2_OFF + (kt & 1) * STG_B);
        __syncthreads();
        if (kt + 2 < 8) load_B2(kt + 2, kt & 1);
    }

    // ---- final epilogue ----
    const float RS2 = 0.7071067811865476f;
    float wo0[8], wo1[8];
    if (EPI == 4) {
        #pragma unroll
        for (int j = 0; j < 8; j++) {
            int col = warp_n * 64 + j * 8 + 2 * (lane & 3);
            wo0[j] = __ldg(Wout + col);
            wo1[j] = __ldg(Wout + col + 1);
        }
    }
    #pragma unroll
    for (int i = 0; i < 4; i++) {
        int ra = rowBase + warp_m * 64 + i * 16 + (lane >> 2);
        int rb = ra + 8;
        float ua = u[ra], ub = u[rb];
        float pa = 0.f, pb = 0.f;
        #pragma unroll
        for (int j = 0; j < 8; j++) {
            int col = warp_n * 64 + j * 8 + 2 * (lane & 3);
            float b0 = __ldg(bias2 + col), b1 = __ldg(bias2 + col + 1);
            float o0 = ua * silu_f(acc[i][j][0] + b0);
            float o1 = ua * silu_f(acc[i][j][1] + b1);
            float o2 = ub * silu_f(acc[i][j][2] + b0);
            float o3 = ub * silu_f(acc[i][j][3] + b1);
            if (EPI == 2) {
                *(float2*)(C + (size_t)ra * 256 + col) = make_float2(tf32r(o0), tf32r(o1));
                *(float2*)(C + (size_t)rb * 256 + col) = make_float2(tf32r(o2), tf32r(o3));
            } else {
                float2 oa = *(const float2*)(C + (size_t)ra * 256 + col);
                float2 ob = *(const float2*)(C + (size_t)rb * 256 + col);
                o0 = (oa.x + o0) * RS2; o1 = (oa.y + o1) * RS2;
                o2 = (ob.x + o2) * RS2; o3 = (ob.y + o3) * RS2;
                if (EPI == 3) {
                    *(float2*)(C + (size_t)ra * 256 + col) = make_float2(tf32r(o0), tf32r(o1));
                    *(float2*)(C + (size_t)rb * 256 + col) = make_float2(tf32r(o2), tf32r(o3));
                } else {
                    pa += o0 * wo0[j] + o1 * wo1[j];
                    pb += o2 * wo0[j] + o3 * wo1[j];
                }
            }
        }
        if (EPI == 4) {
            pa += __shfl_xor_sync(0xffffffffu, pa, 1);
            pa += __shfl_xor_sync(0xffffffffu, pa, 2);
            pb += __shfl_xor_sync(0xffffffffu, pb, 1);
            pb += __shfl_xor_sync(0xffffffffu, pb, 2);
            if ((lane & 3) == 0) {
                atomicAdd(out + __ldg(rcv + ra), pa * ua * 0.25f);
                atomicAdd(out + __ldg(rcv + rb), pb * ub * 0.25f);
            }
        }
    }
}

// ---------------- weight transpose+pad+round, merged 3 regions per launch ----------
// regions given by (src, dstOfs, K, Kp) triples encoded in parameters
__global__ void k_wprep3(const float* __restrict__ W0, float* __restrict__ d0, int K0, int Kp0,
                         const float* __restrict__ W1, float* __restrict__ d1, int K1, int Kp1,
                         const float* __restrict__ W2, float* __restrict__ d2, int K2, int Kp2)
{
    int b = blockIdx.x;
    const float* W; float* d; int K, Kp, rb;
    if (b < Kp0)            { W = W0; d = d0; K = K0; Kp = Kp0; rb = b; }
    else if (b < Kp0 + Kp1) { W = W1; d = d1; K = K1; Kp = Kp1; rb = b - Kp0; }
    else                    { W = W2; d = d2; K = K2; Kp = Kp2; rb = b - Kp0 - Kp1; }
    int idx = rb * 256 + threadIdx.x;
    int n = idx / Kp, k = idx % Kp;
    d[idx] = (k < K) ? tf32r(W[(size_t)k * 256 + n]) : 0.f;
}

// ---------------- geometry ----------------
__global__ void k_geom(const float* __restrict__ vec, const float* __restrict__ attrs,
                       const int* __restrict__ snd, const int* __restrict__ rcv,
                       float* __restrict__ feat, float* __restrict__ uo, float* __restrict__ Yo)
{
    int e = blockIdx.x * blockDim.x + threadIdx.x;
    if (e >= EE) return;
    float vx = vec[3*e+0], vy = vec[3*e+1], vz = vec[3*e+2];
    float d2 = vx*vx + vy*vy + vz*vz;
    float d  = sqrtf(d2);
    float d6 = d2 * d2 * d2;
    float env = 1.0f + d6 * (-28.0f + d * (48.0f - 21.0f * d));
    uo[e] = env;
    float invd = 1.0f / d;
    const float S2 = 1.4142135623730951f;
    float* fp = feat + (size_t)e * 64;
    #pragma unroll
    for (int k = 1; k <= 8; k++)
        fp[k-1] = tf32r(S2 * sinpif((float)k * d) * invd);
    int s = snd[e], r = rcv[e];
    #pragma unroll
    for (int i = 0; i < 16; i++) fp[8 + i]  = tf32r(attrs[s*16 + i]);
    #pragma unroll
    for (int i = 0; i < 16; i++) fp[24 + i] = tf32r(attrs[r*16 + i]);
    #pragma unroll
    for (int i = 40; i < 64; i++) fp[i] = 0.f;

    float x = vx*invd, y = vy*invd, z = vz*invd;
    const float s3  = 1.7320508075688772f;
    const float s5  = 2.2360679774997896f;
    const float s15 = 3.8729833462074170f;
    const float s7  = 2.6457513110645907f;
    const float c33 = 2.0916500663351885f;
    const float c32 = 10.246950765959598f;
    const float c31 = 1.6201851746019649f;
    float* Yp = Yo + (size_t)e * 16;
    Yp[0]  = 1.0f;
    Yp[1]  = s3 * x;  Yp[2]  = s3 * y;  Yp[3]  = s3 * z;
    Yp[4]  = s15 * x * y;  Yp[5]  = s15 * y * z;
    Yp[6]  = 0.5f * s5 * (3.0f*z*z - 1.0f);
    Yp[7]  = s15 * x * z;
    Yp[8]  = 0.5f * s15 * (x*x - y*y);
    Yp[9]  = c33 * y * (3.0f*x*x - y*y);
    Yp[10] = c32 * x * y * z;
    Yp[11] = c31 * y * (5.0f*z*z - 1.0f);
    Yp[12] = 0.5f * s7 * (5.0f*z*z*z - 3.0f*z);
    Yp[13] = c31 * x * (5.0f*z*z - 1.0f);
    Yp[14] = 0.5f * c32 * z * (x*x - y*y);
    Yp[15] = c33 * x * (x*x - 3.0f*y*y);
}

// ---------------- (E,256) @ (256,16) x2 sharing one x read ----------
__global__ __launch_bounds__(128) void gemm_n16_dual(const float* __restrict__ X,
                                                     const float* __restrict__ Wa,
                                                     const float* __restrict__ Wb,
                                                     float* __restrict__ Sa,
                                                     float* __restrict__ Sb)
{
    __shared__ __align__(16) float Ws[8192];   // [0:4096) Wa, [4096:8192) Wb
    int tid = threadIdx.x;
    #pragma unroll
    for (int i = 0; i < 8; i++)
        ((float4*)Ws)[tid + i * 128] = ((const float4*)Wa)[tid + i * 128];
    #pragma unroll
    for (int i = 0; i < 8; i++)
        ((float4*)(Ws + 4096))[tid + i * 128] = ((const float4*)Wb)[tid + i * 128];
    __syncthreads();
    size_t e = (size_t)blockIdx.x * 128 + tid;
    const float4* xr = (const float4*)(X + e * 256);
    float acca[16], accb[16];
    #pragma unroll
    for (int c = 0; c < 16; c++) { acca[c] = 0.f; accb[c] = 0.f; }
    #pragma unroll 2
    for (int k4 = 0; k4 < 64; k4++) {
        float4 xv = xr[k4];
        float xs[4] = {xv.x, xv.y, xv.z, xv.w};
        #pragma unroll
        for (int j = 0; j < 4; j++) {
            const float4* wra = (const float4*)&Ws[(k4 * 4 + j) * 16];
            const float4* wrb = (const float4*)&Ws[4096 + (k4 * 4 + j) * 16];
            #pragma unroll
            for (int q = 0; q < 4; q++) {
                float4 wa = wra[q], wb = wrb[q];
                acca[q*4+0] += xs[j] * wa.x;  accb[q*4+0] += xs[j] * wb.x;
                acca[q*4+1] += xs[j] * wa.y;  accb[q*4+1] += xs[j] * wb.y;
                acca[q*4+2] += xs[j] * wa.z;  accb[q*4+2] += xs[j] * wb.z;
                acca[q*4+3] += xs[j] * wa.w;  accb[q*4+3] += xs[j] * wb.w;
            }
        }
    }
    float4* spa = (float4*)(Sa + e * 16);
    float4* spb = (float4*)(Sb + e * 16);
    #pragma unroll
    for (int q = 0; q < 4; q++) {
        spa[q] = make_float4(acca[q*4], acca[q*4+1], acca[q*4+2], acca[q*4+3]);
        spb[q] = make_float4(accb[q*4], accb[q*4+1], accb[q*4+2], accb[q*4+3]);
    }
}

// ---------------- single-output N=16 GEMM (layer-1 w) ----------------
__global__ __launch_bounds__(128) void gemm_n16(const float* __restrict__ X,
                                                const float* __restrict__ W,
                                                float* __restrict__ S)
{
    __shared__ __align__(16) float Ws[4096];
    int tid = threadIdx.x;
    #pragma unroll
    for (int i = 0; i < 8; i++)
        ((float4*)Ws)[tid + i * 128] = ((const float4*)W)[tid + i * 128];
    __syncthreads();
    size_t e = (size_t)blockIdx.x * 128 + tid;
    const float4* xr = (const float4*)(X + e * 256);
    float acc[16];
    #pragma unroll
    for (int c = 0; c < 16; c++) acc[c] = 0.f;
    #pragma unroll 4
    for (int k4 = 0; k4 < 64; k4++) {
        float4 xv = xr[k4];
        float xs[4] = {xv.x, xv.y, xv.z, xv.w};
        #pragma unroll
        for (int j = 0; j < 4; j++) {
            const float4* wr = (const float4*)&Ws[(k4 * 4 + j) * 16];
            #pragma unroll
            for (int q = 0; q < 4; q++) {
                float4 w = wr[q];
                acc[q*4+0] += xs[j] * w.x;
                acc[q*4+1] += xs[j] * w.y;
                acc[q*4+2] += xs[j] * w.z;
                acc[q*4+3] += xs[j] * w.w;
            }
        }
    }
    float4* sp = (float4*)(S + e * 16);
    #pragma unroll
    for (int q = 0; q < 4; q++)
        sp[q] = make_float4(acc[q*4], acc[q*4+1], acc[q*4+2], acc[q*4+3]);
}

__global__ void k_zero4(float4* p, int n4)
{
    int i = blockIdx.x * blockDim.x + threadIdx.x;
    if (i < n4) p[i] = make_float4(0.f, 0.f, 0.f, 0.f);
}

// ---------------- segment_sum scatter: 16 threads per edge, wide parallelism --------
__global__ void k_scatter(const float* __restrict__ w, const float* __restrict__ Y,
                          const int* __restrict__ snd, float* __restrict__ wY)
{
    int idx = blockIdx.x * blockDim.x + threadIdx.x;   // e*16 + m
    int e = idx >> 4, m = idx & 15;
    float wv = w[idx];
    int s = snd[e];
    float* base = wY + (size_t)s * 256 + m * 16;
    const float4* Y4 = (const float4*)(Y + (size_t)e * 16);
    #pragma unroll
    for (int q = 0; q < 4; q++) {
        float4 y = Y4[q];
        atomicAdd(base + q*4 + 0, wv * y.x);
        atomicAdd(base + q*4 + 1, wv * y.y);
        atomicAdd(base + q*4 + 2, wv * y.z);
        atomicAdd(base + q*4 + 3, wv * y.w);
    }
}

// ---------------- layer-0 update: VV0 out + only column 0 of the rotation ----------
__global__ __launch_bounds__(256)
void k_update0(const int* __restrict__ snd, const float* __restrict__ wY,
               const float* __restrict__ s16, const float* __restrict__ Y,
               float* __restrict__ V0, float* __restrict__ VV0p,
               const float* __restrict__ Wlsh)
{
    __shared__ float Wcol0[16];
    int tid = threadIdx.x;
    if (tid < 16) Wcol0[tid] = Wlsh[tid * 16];   // column 0 of W_lsh
    __syncthreads();
    int idx = blockIdx.x * 256 + tid;
    int e = idx >> 4, m = idx & 15;
    int s = snd[e];
    float xv = s16[idx];
    const float4* wyp = (const float4*)(wY + (size_t)s * 256 + m * 16);
    const float4* yp  = (const float4*)(Y + (size_t)e * 16);
    float vv[16];
    #pragma unroll
    for (int q = 0; q < 4; q++) {
        float4 a = wyp[q];
        float4 y = yp[q];
        vv[q*4+0] = 0.25f * a.x * xv * y.x;
        vv[q*4+1] = 0.25f * a.y * xv * y.y;
        vv[q*4+2] = 0.25f * a.z * xv * y.z;
        vv[q*4+3] = 0.25f * a.w * xv * y.w;
    }
    VV0p[(size_t)e * 32 + m] = tf32r(vv[0]);
    VV0p[(size_t)e * 32 + 16 + m] = 0.f;
    float o0 = 0.f;
    #pragma unroll
    for (int i = 0; i < 16; i++) o0 += vv[i] * Wcol0[i];
    V0[idx] = o0;
}

// ---------------- layer-1 update: VV0 only ----------------
__global__ __launch_bounds__(256)
void k_update1(const int* __restrict__ snd, const float* __restrict__ wY,
               const float* __restrict__ V0, float* __restrict__ VV0p)
{
    int idx = blockIdx.x * 256 + threadIdx.x;
    int e = idx >> 4, m = idx & 15;
    int s = snd[e];
    float wy0 = wY[(size_t)s * 256 + m * 16];
    VV0p[(size_t)e * 32 + m] = tf32r(0.25f * wy0 * V0[idx]);
    VV0p[(size_t)e * 32 + 16 + m] = 0.f;
}

// ---------------- host ----------------
extern "C" void kernel_launch(void* const* d_in, const int* in_sizes, int n_in,
                              void* d_out, int out_size)
{
    const float* attrs = (const float*)d_in[0];
    const float* vec   = (const float*)d_in[1];
    const int*   snd   = (const int*)d_in[2];
    const int*   rcv   = (const int*)d_in[3];
    const float* We0   = (const float*)d_in[4];
    const float* be0   = (const float*)d_in[5];
    const float* We1   = (const float*)d_in[6];
    const float* be1   = (const float*)d_in[7];
    const float* Wv0   = (const float*)d_in[8];
    const float* Wlw   = (const float*)d_in[9];
    const float* Wlsh  = (const float*)d_in[10];
    const float* Wly1  = (const float*)d_in[11];
    const float* bly1  = (const float*)d_in[12];
    const float* Wly2  = (const float*)d_in[13];
    const float* bly2  = (const float*)d_in[14];
    const float* Wout  = (const float*)d_in[15];
    float* out = (float*)d_out;

    float *featp, *uu, *Y, *x, *s16, *w16, *V0, *VV0p, *wY, *Bt;
    cudaGetSymbolAddress((void**)&featp, g_featp);
    cudaGetSymbolAddress((void**)&uu,    g_u);
    cudaGetSymbolAddress((void**)&Y,     g_Y);
    cudaGetSymbolAddress((void**)&x,     g_x);
    cudaGetSymbolAddress((void**)&s16,   g_s16);
    cudaGetSymbolAddress((void**)&w16,   g_w16);
    cudaGetSymbolAddress((void**)&V0,    g_V0);
    cudaGetSymbolAddress((void**)&VV0p,  g_VV0p);
    cudaGetSymbolAddress((void**)&wY,    g_wY);
    cudaGetSymbolAddress((void**)&Bt,    g_Bt);

    // transposed weight regions [256][Kp]
    float* Bt_e0  = Bt + 0;        // Kp=64
    float* Bt_e1  = Bt + 16384;    // Kp=256
    float* Bt_l10 = Bt + 81920;    // Kp=288
    float* Bt_l11 = Bt + 155648;   // Kp=288
    float* Bt_l20 = Bt + 229376;   // Kp=256
    float* Bt_l21 = Bt + 294912;   // Kp=256

    const int FSM_BYTES = FSM_FLOATS * 4;   // 206848
    cudaFuncSetAttribute(fgemm<2>, cudaFuncAttributeMaxDynamicSharedMemorySize, FSM_BYTES);
    cudaFuncSetAttribute(fgemm<3>, cudaFuncAttributeMaxDynamicSharedMemorySize, FSM_BYTES);
    cudaFuncSetAttribute(fgemm<4>, cudaFuncAttributeMaxDynamicSharedMemorySize, FSM_BYTES);

    const int GB = EE / 128;   // 1024 CTAs

    // launch order arranged so ncu (-s 5 -c 1) captures fgemm<2> at index 5
    k_geom<<<EE / 256, 256>>>(vec, attrs, snd, rcv, featp, uu, Y);               // 0
    k_wprep3<<<64 + 256 + 288, 256>>>(We0, Bt_e0, 40, 64,                        // 1
                                      We1, Bt_e1, 256, 256,
                                      Wly1, Bt_l10, 272, 288);
    k_wprep3<<<288 + 256 + 256, 256>>>(Wly1 + 272 * 256, Bt_l11, 272, 288,      // 2
                                       Wly2, Bt_l20, 256, 256,
                                       Wly2 + 256 * 256, Bt_l21, 256, 256);
    k_zero4<<<(NN * 256 / 4 + 255) / 256, 256>>>((float4*)wY, NN * 256 / 4);     // 3
    k_zero4<<<(NN / 4 + 255) / 256, 256>>>((float4*)out, NN / 4);                // 4

    // e0 -> e1 fused:  x = u * silu(silu(feat@We0+be0) @ We1 + be1)             // 5
    fgemm<2><<<GB, 256, FSM_BYTES>>>(featp, 64, 2, nullptr,
                                     Bt_e0, 64, 2, be0,
                                     Bt_e1, be1, uu, x,
                                     nullptr, nullptr, nullptr);

    // ---- layer 0 ----
    gemm_n16_dual<<<EE / 128, 128>>>(x, Wv0, Wlw, s16, w16);
    k_scatter<<<EE * 16 / 256, 256>>>(w16, Y, snd, wY);
    k_update0<<<EE * 16 / 256, 256>>>(snd, wY, s16, Y, V0, VV0p, Wlsh);
    fgemm<3><<<GB, 256, FSM_BYTES>>>(x, 256, 8, VV0p,
                                     Bt_l10, 288, 9, bly1,
                                     Bt_l20, bly2, uu, x,
                                     nullptr, nullptr, nullptr);

    // ---- layer 1 ----
    gemm_n16<<<EE / 128, 128>>>(x, Wlw + 256 * 16, w16);
    k_zero4<<<(NN * 256 / 4 + 255) / 256, 256>>>((float4*)wY, NN * 256 / 4);
    k_scatter<<<EE * 16 / 256, 256>>>(w16, Y, snd, wY);
    k_update1<<<EE * 16 / 256, 256>>>(snd, wY, V0, VV0p);
    fgemm<4><<<GB, 256, FSM_BYTES>>>(x, 256, 8, VV0p,
                                     Bt_l11, 288, 9, bly1 + 256,
                                     Bt_l21, bly2 + 256, uu, x,
                                     Wout, rcv, out);
}

// round 11
// speedup vs baseline: 1.8869x; 1.1334x over previous
#include <cuda_runtime.h>
#include <math.h>
#include <cstdint>

#define NN 8192
#define EE 131072

// ---------------- scratch (device globals; no allocations allowed) ----------------
__device__ __align__(16) float g_featp[EE * 64];   // bessel+attrs, padded K 40->64
__device__ __align__(16) float g_u[EE];
__device__ __align__(16) float g_Y[EE * 16];
__device__ __align__(16) float g_x[EE * 256];
__device__ __align__(16) float g_s16[EE * 16];     // xv (x @ Wv0), persistent
__device__ __align__(16) float g_w16[EE * 16];     // per-layer w = x @ Wlw[l]
__device__ __align__(16) float g_V0[EE * 16];      // V[:,:,0] after layer-0 rotation
__device__ __align__(16) float g_VV0p[EE * 32];    // VV[:, :, 0] padded 16->32
__device__ __align__(16) float g_wY[NN * 256];
__device__ __align__(16) float g_Bt[360448];       // transposed [N][Kp] tf32 weights

// ---------------- helpers ----------------
__device__ __forceinline__ float tf32r(float v) {
    uint32_t r;
    asm("cvt.rna.tf32.f32 %0, %1;" : "=r"(r) : "f"(v));
    return __uint_as_float(r);
}
__device__ __forceinline__ uint32_t smem_u32(const void* p) {
    uint32_t a;
    asm("{ .reg .u64 t; cvta.to.shared.u64 t, %1; cvt.u32.u64 %0, t; }" : "=r"(a) : "l"(p));
    return a;
}
__device__ __forceinline__ void cp16(uint32_t dst, const void* src) {
    asm volatile("cp.async.cg.shared.global [%0], [%1], 16;" :: "r"(dst), "l"(src));
}
#define CP_COMMIT() asm volatile("cp.async.commit_group;" ::: "memory")
#define CP_WAIT(n)  asm volatile("cp.async.wait_group %0;" :: "n"(n) : "memory")

__device__ __forceinline__ void mma8(float* d, const uint32_t* a, const uint32_t* b) {
    asm volatile(
        "mma.sync.aligned.m16n8k8.row.col.f32.tf32.tf32.f32 "
        "{%0,%1,%2,%3}, {%4,%5,%6,%7}, {%8,%9}, {%0,%1,%2,%3};"
        : "+f"(d[0]), "+f"(d[1]), "+f"(d[2]), "+f"(d[3])
        : "r"(a[0]), "r"(a[1]), "r"(a[2]), "r"(a[3]), "r"(b[0]), "r"(b[1]));
}

__device__ __forceinline__ float silu_f(float t) { return t / (1.0f + __expf(-t)); }

// smem layout (floats)
static constexpr int APAD = 36;
static constexpr int STG_A = 128 * APAD;                  // 4608
static constexpr int STG_B = 256 * 36;                    // 9216
static constexpr int STG_FLOATS = STG_A + STG_B;          // 13824
static constexpr int TT_STRIDE = 260;
static constexpr int TT_FLOATS = 128 * TT_STRIDE;         // 33280
static constexpr int B2_OFF = TT_FLOATS;
static constexpr int FSM_FLOATS = B2_OFF + 2 * STG_B;     // 51712 floats = 206848 B

// ---------------- fused GEMM pair, 512 threads (16 warps, 2x8 warp grid) ----------
// GEMM1: T = silu(A[E,K1] @ B1 + bias1)   (T kept in smem, tf32-rounded)
// GEMM2: per EPI on  T @ B2 + bias2  (K=256)
// EPI: 2 = C = u*silu,  3 = C = (C + u*silu)/sqrt(2),
//      4 = no C write; out[rcv[row]] += dot((C+u*silu)/sqrt2, Wout)*u*inv
template<int EPI>
__global__ __launch_bounds__(512, 1) void fgemm(
    const float* __restrict__ A1, int sA1, int ntA1,
    const float* __restrict__ A2,
    const float* __restrict__ B1, int Kp1, int nt1,
    const float* __restrict__ bias1,
    const float* __restrict__ B2,
    const float* __restrict__ bias2,
    const float* __restrict__ u, float* __restrict__ C,
    const float* __restrict__ Wout, const int* __restrict__ rcv,
    float* __restrict__ out)
{
    extern __shared__ float smf[];
    uint32_t sb = smem_u32(smf);
    int tid = threadIdx.x, lane = tid & 31, wid = tid >> 5;
    int warp_m = wid & 1, warp_n = wid >> 1;     // 2 x 8 warp grid, 64x32 warp tile
    int rowBase = blockIdx.x * 128;

    auto load_tile1 = [&](int kt, int buf) {
        uint32_t stBase = sb + buf * STG_FLOATS * 4;
        const float* Ap;
        int stride;
        if (kt < ntA1) { Ap = A1 + (size_t)rowBase * sA1 + kt * 32; stride = sA1; }
        else           { Ap = A2 + (size_t)rowBase * 32;            stride = 32;  }
        #pragma unroll
        for (int i = 0; i < 2; i++) {
            int f = tid + i * 512;
            int r = f >> 3, q = f & 7;
            cp16(stBase + (r * APAD + q * 4) * 4, Ap + (size_t)r * stride + q * 4);
        }
        const float* Bp = B1 + kt * 32;
        uint32_t bBase = stBase + STG_A * 4;
        #pragma unroll
        for (int i = 0; i < 4; i++) {
            int f = tid + i * 512;
            int n = f >> 3, q = f & 7;
            cp16(bBase + (n * 36 + q * 4) * 4, Bp + (size_t)n * Kp1 + q * 4);
        }
        CP_COMMIT();
    };
    auto load_B2 = [&](int kt, int buf) {
        const float* Bp = B2 + kt * 32;
        uint32_t bBase = sb + (B2_OFF + buf * STG_B) * 4;
        #pragma unroll
        for (int i = 0; i < 4; i++) {
            int f = tid + i * 512;
            int n = f >> 3, q = f & 7;
            cp16(bBase + (n * 36 + q * 4) * 4, Bp + (size_t)n * 256 + q * 4);
        }
        CP_COMMIT();
    };

    float acc[4][4][4];
    auto zero_acc = [&]() {
        #pragma unroll
        for (int i = 0; i < 4; i++)
            #pragma unroll
            for (int j = 0; j < 4; j++)
                #pragma unroll
                for (int q = 0; q < 4; q++) acc[i][j][q] = 0.f;
    };
    auto mma_slab = [&](const float* As, int astride, int kofs, const float* Bs) {
        #pragma unroll
        for (int s = 0; s < 4; s++) {
            uint32_t a[4][4], b[4][2];
            int r1 = lane >> 2, c1 = kofs + s * 8 + (lane & 3);
            #pragma unroll
            for (int i = 0; i < 4; i++) {
                int rb = warp_m * 64 + i * 16 + r1;
                a[i][0] = __float_as_uint(As[rb * astride + c1]);
                a[i][1] = __float_as_uint(As[(rb + 8) * astride + c1]);
                a[i][2] = __float_as_uint(As[rb * astride + c1 + 4]);
                a[i][3] = __float_as_uint(As[(rb + 8) * astride + c1 + 4]);
            }
            int kb = s * 8 + (lane & 3), nq = lane >> 2;
            #pragma unroll
            for (int j = 0; j < 4; j++) {
                int cb = warp_n * 32 + j * 8 + nq;
                b[j][0] = __float_as_uint(Bs[cb * 36 + kb]);
                b[j][1] = __float_as_uint(Bs[cb * 36 + kb + 4]);
            }
            #pragma unroll
            for (int i = 0; i < 4; i++)
                #pragma unroll
                for (int j = 0; j < 4; j++)
                    mma8(acc[i][j], a[i], b[j]);
        }
    };

    // ================= GEMM1 =================
    zero_acc();
    load_tile1(0, 0);
    if (nt1 > 1) load_tile1(1, 1);
    for (int kt = 0; kt < nt1; kt++) {
        if (kt + 1 < nt1) CP_WAIT(1); else CP_WAIT(0);
        __syncthreads();
        const float* As = smf + (kt & 1) * STG_FLOATS;
        mma_slab(As, APAD, 0, As + STG_A);
        __syncthreads();
        if (kt + 2 < nt1) load_tile1(kt + 2, kt & 1);
    }

    load_B2(0, 0);
    load_B2(1, 1);

    // GEMM1 epilogue: silu + bias -> t-tile in smem (tf32-rounded)
    #pragma unroll
    for (int i = 0; i < 4; i++) {
        int ra = warp_m * 64 + i * 16 + (lane >> 2);
        int rb = ra + 8;
        #pragma unroll
        for (int j = 0; j < 4; j++) {
            int col = warp_n * 32 + j * 8 + 2 * (lane & 3);
            float b0 = __ldg(bias1 + col), b1 = __ldg(bias1 + col + 1);
            smf[ra * TT_STRIDE + col]     = tf32r(silu_f(acc[i][j][0] + b0));
            smf[ra * TT_STRIDE + col + 1] = tf32r(silu_f(acc[i][j][1] + b1));
            smf[rb * TT_STRIDE + col]     = tf32r(silu_f(acc[i][j][2] + b0));
            smf[rb * TT_STRIDE + col + 1] = tf32r(silu_f(acc[i][j][3] + b1));
        }
    }

    // ================= GEMM2 (K = 256, A = smem t-tile) =================
    zero_acc();
    for (int kt = 0; kt < 8; kt++) {
        if (kt < 7) CP_WAIT(1); else CP_WAIT(0);
        __syncthreads();
        mma_slab(smf, TT_STRIDE, kt * 32, smf + B2_OFF + (kt & 1) * STG_B);
        __syncthreads();
        if (kt + 2 < 8) load_B2(kt + 2, kt & 1);
    }

    // ---- final epilogue ----
    const float RS2 = 0.7071067811865476f;
    float wo0[4], wo1[4];
    if (EPI == 4) {
        #pragma unroll
        for (int j = 0; j < 4; j++) {
            int col = warp_n * 32 + j * 8 + 2 * (lane & 3);
            wo0[j] = __ldg(Wout + col);
            wo1[j] = __ldg(Wout + col + 1);
        }
    }
    #pragma unroll
    for (int i = 0; i < 4; i++) {
        int ra = rowBase + warp_m * 64 + i * 16 + (lane >> 2);
        int rb = ra + 8;
        float ua = u[ra], ub = u[rb];
        float pa = 0.f, pb = 0.f;
        #pragma unroll
        for (int j = 0; j < 4; j++) {
            int col = warp_n * 32 + j * 8 + 2 * (lane & 3);
            float b0 = __ldg(bias2 + col), b1 = __ldg(bias2 + col + 1);
            float o0 = ua * silu_f(acc[i][j][0] + b0);
            float o1 = ua * silu_f(acc[i][j][1] + b1);
            float o2 = ub * silu_f(acc[i][j][2] + b0);
            float o3 = ub * silu_f(acc[i][j][3] + b1);
            if (EPI == 2) {
                *(float2*)(C + (size_t)ra * 256 + col) = make_float2(tf32r(o0), tf32r(o1));
                *(float2*)(C + (size_t)rb * 256 + col) = make_float2(tf32r(o2), tf32r(o3));
            } else {
                float2 oa = *(const float2*)(C + (size_t)ra * 256 + col);
                float2 ob = *(const float2*)(C + (size_t)rb * 256 + col);
                o0 = (oa.x + o0) * RS2; o1 = (oa.y + o1) * RS2;
                o2 = (ob.x + o2) * RS2; o3 = (ob.y + o3) * RS2;
                if (EPI == 3) {
                    *(float2*)(C + (size_t)ra * 256 + col) = make_float2(tf32r(o0), tf32r(o1));
                    *(float2*)(C + (size_t)rb * 256 + col) = make_float2(tf32r(o2), tf32r(o3));
                } else {
                    pa += o0 * wo0[j] + o1 * wo1[j];
                    pb += o2 * wo0[j] + o3 * wo1[j];
                }
            }
        }
        if (EPI == 4) {
            pa += __shfl_xor_sync(0xffffffffu, pa, 1);
            pa += __shfl_xor_sync(0xffffffffu, pa, 2);
            pb += __shfl_xor_sync(0xffffffffu, pb, 1);
            pb += __shfl_xor_sync(0xffffffffu, pb, 2);
            if ((lane & 3) == 0) {
                atomicAdd(out + __ldg(rcv + ra), pa * ua * 0.25f);
                atomicAdd(out + __ldg(rcv + rb), pb * ub * 0.25f);
            }
        }
    }
}

// ---------------- weight transpose+pad+round, merged 3 regions per launch ----------
__global__ void k_wprep3(const float* __restrict__ W0, float* __restrict__ d0, int K0, int Kp0,
                         const float* __restrict__ W1, float* __restrict__ d1, int K1, int Kp1,
                         const float* __restrict__ W2, float* __restrict__ d2, int K2, int Kp2)
{
    int b = blockIdx.x;
    const float* W; float* d; int K, Kp, rb;
    if (b < Kp0)            { W = W0; d = d0; K = K0; Kp = Kp0; rb = b; }
    else if (b < Kp0 + Kp1) { W = W1; d = d1; K = K1; Kp = Kp1; rb = b - Kp0; }
    else                    { W = W2; d = d2; K = K2; Kp = Kp2; rb = b - Kp0 - Kp1; }
    int idx = rb * 256 + threadIdx.x;
    int n = idx / Kp, k = idx % Kp;
    d[idx] = (k < K) ? tf32r(W[(size_t)k * 256 + n]) : 0.f;
}

// ---------------- geometry ----------------
__global__ void k_geom(const float* __restrict__ vec, const float* __restrict__ attrs,
                       const int* __restrict__ snd, const int* __restrict__ rcv,
                       float* __restrict__ feat, float* __restrict__ uo, float* __restrict__ Yo)
{
    int e = blockIdx.x * blockDim.x + threadIdx.x;
    if (e >= EE) return;
    float vx = vec[3*e+0], vy = vec[3*e+1], vz = vec[3*e+2];
    float d2 = vx*vx + vy*vy + vz*vz;
    float d  = sqrtf(d2);
    float d6 = d2 * d2 * d2;
    float env = 1.0f + d6 * (-28.0f + d * (48.0f - 21.0f * d));
    uo[e] = env;
    float invd = 1.0f / d;
    const float S2 = 1.4142135623730951f;
    float* fp = feat + (size_t)e * 64;
    #pragma unroll
    for (int k = 1; k <= 8; k++)
        fp[k-1] = tf32r(S2 * sinpif((float)k * d) * invd);
    int s = snd[e], r = rcv[e];
    #pragma unroll
    for (int i = 0; i < 16; i++) fp[8 + i]  = tf32r(attrs[s*16 + i]);
    #pragma unroll
    for (int i = 0; i < 16; i++) fp[24 + i] = tf32r(attrs[r*16 + i]);
    #pragma unroll
    for (int i = 40; i < 64; i++) fp[i] = 0.f;

    float x = vx*invd, y = vy*invd, z = vz*invd;
    const float s3  = 1.7320508075688772f;
    const float s5  = 2.2360679774997896f;
    const float s15 = 3.8729833462074170f;
    const float s7  = 2.6457513110645907f;
    const float c33 = 2.0916500663351885f;
    const float c32 = 10.246950765959598f;
    const float c31 = 1.6201851746019649f;
    float* Yp = Yo + (size_t)e * 16;
    Yp[0]  = 1.0f;
    Yp[1]  = s3 * x;  Yp[2]  = s3 * y;  Yp[3]  = s3 * z;
    Yp[4]  = s15 * x * y;  Yp[5]  = s15 * y * z;
    Yp[6]  = 0.5f * s5 * (3.0f*z*z - 1.0f);
    Yp[7]  = s15 * x * z;
    Yp[8]  = 0.5f * s15 * (x*x - y*y);
    Yp[9]  = c33 * y * (3.0f*x*x - y*y);
    Yp[10] = c32 * x * y * z;
    Yp[11] = c31 * y * (5.0f*z*z - 1.0f);
    Yp[12] = 0.5f * s7 * (5.0f*z*z*z - 3.0f*z);
    Yp[13] = c31 * x * (5.0f*z*z - 1.0f);
    Yp[14] = 0.5f * c32 * z * (x*x - y*y);
    Yp[15] = c33 * x * (x*x - 3.0f*y*y);
}

// ---------------- (E,256) @ (256,16) x2 sharing one x read ----------
__global__ __launch_bounds__(128) void gemm_n16_dual(const float* __restrict__ X,
                                                     const float* __restrict__ Wa,
                                                     const float* __restrict__ Wb,
                                                     float* __restrict__ Sa,
                                                     float* __restrict__ Sb)
{
    __shared__ __align__(16) float Ws[8192];
    int tid = threadIdx.x;
    #pragma unroll
    for (int i = 0; i < 8; i++)
        ((float4*)Ws)[tid + i * 128] = ((const float4*)Wa)[tid + i * 128];
    #pragma unroll
    for (int i = 0; i < 8; i++)
        ((float4*)(Ws + 4096))[tid + i * 128] = ((const float4*)Wb)[tid + i * 128];
    __syncthreads();
    size_t e = (size_t)blockIdx.x * 128 + tid;
    const float4* xr = (const float4*)(X + e * 256);
    float acca[16], accb[16];
    #pragma unroll
    for (int c = 0; c < 16; c++) { acca[c] = 0.f; accb[c] = 0.f; }
    #pragma unroll 2
    for (int k4 = 0; k4 < 64; k4++) {
        float4 xv = xr[k4];
        float xs[4] = {xv.x, xv.y, xv.z, xv.w};
        #pragma unroll
        for (int j = 0; j < 4; j++) {
            const float4* wra = (const float4*)&Ws[(k4 * 4 + j) * 16];
            const float4* wrb = (const float4*)&Ws[4096 + (k4 * 4 + j) * 16];
            #pragma unroll
            for (int q = 0; q < 4; q++) {
                float4 wa = wra[q], wb = wrb[q];
                acca[q*4+0] += xs[j] * wa.x;  accb[q*4+0] += xs[j] * wb.x;
                acca[q*4+1] += xs[j] * wa.y;  accb[q*4+1] += xs[j] * wb.y;
                acca[q*4+2] += xs[j] * wa.z;  accb[q*4+2] += xs[j] * wb.z;
                acca[q*4+3] += xs[j] * wa.w;  accb[q*4+3] += xs[j] * wb.w;
            }
        }
    }
    float4* spa = (float4*)(Sa + e * 16);
    float4* spb = (float4*)(Sb + e * 16);
    #pragma unroll
    for (int q = 0; q < 4; q++) {
        spa[q] = make_float4(acca[q*4], acca[q*4+1], acca[q*4+2], acca[q*4+3]);
        spb[q] = make_float4(accb[q*4], accb[q*4+1], accb[q*4+2], accb[q*4+3]);
    }
}

// ---------------- single-output N=16 GEMM (layer-1 w) ----------------
__global__ __launch_bounds__(128) void gemm_n16(const float* __restrict__ X,
                                                const float* __restrict__ W,
                                                float* __restrict__ S)
{
    __shared__ __align__(16) float Ws[4096];
    int tid = threadIdx.x;
    #pragma unroll
    for (int i = 0; i < 8; i++)
        ((float4*)Ws)[tid + i * 128] = ((const float4*)W)[tid + i * 128];
    __syncthreads();
    size_t e = (size_t)blockIdx.x * 128 + tid;
    const float4* xr = (const float4*)(X + e * 256);
    float acc[16];
    #pragma unroll
    for (int c = 0; c < 16; c++) acc[c] = 0.f;
    #pragma unroll 4
    for (int k4 = 0; k4 < 64; k4++) {
        float4 xv = xr[k4];
        float xs[4] = {xv.x, xv.y, xv.z, xv.w};
        #pragma unroll
        for (int j = 0; j < 4; j++) {
            const float4* wr = (const float4*)&Ws[(k4 * 4 + j) * 16];
            #pragma unroll
            for (int q = 0; q < 4; q++) {
                float4 w = wr[q];
                acc[q*4+0] += xs[j] * w.x;
                acc[q*4+1] += xs[j] * w.y;
                acc[q*4+2] += xs[j] * w.z;
                acc[q*4+3] += xs[j] * w.w;
            }
        }
    }
    float4* sp = (float4*)(S + e * 16);
    #pragma unroll
    for (int q = 0; q < 4; q++)
        sp[q] = make_float4(acc[q*4], acc[q*4+1], acc[q*4+2], acc[q*4+3]);
}

__global__ void k_zero4(float4* p, int n4)
{
    int i = blockIdx.x * blockDim.x + threadIdx.x;
    if (i < n4) p[i] = make_float4(0.f, 0.f, 0.f, 0.f);
}

// ---------------- segment_sum scatter: 16 threads per edge, wide parallelism --------
__global__ void k_scatter(const float* __restrict__ w, const float* __restrict__ Y,
                          const int* __restrict__ snd, float* __restrict__ wY)
{
    int idx = blockIdx.x * blockDim.x + threadIdx.x;   // e*16 + m
    int e = idx >> 4, m = idx & 15;
    float wv = w[idx];
    int s = snd[e];
    float* base = wY + (size_t)s * 256 + m * 16;
    const float4* Y4 = (const float4*)(Y + (size_t)e * 16);
    #pragma unroll
    for (int q = 0; q < 4; q++) {
        float4 y = Y4[q];
        atomicAdd(base + q*4 + 0, wv * y.x);
        atomicAdd(base + q*4 + 1, wv * y.y);
        atomicAdd(base + q*4 + 2, wv * y.z);
        atomicAdd(base + q*4 + 3, wv * y.w);
    }
}

// ---------------- layer-0 update: VV0 out + only column 0 of the rotation ----------
__global__ __launch_bounds__(256)
void k_update0(const int* __restrict__ snd, const float* __restrict__ wY,
               const float* __restrict__ s16, const float* __restrict__ Y,
               float* __restrict__ V0, float* __restrict__ VV0p,
               const float* __restrict__ Wlsh)
{
    __shared__ float Wcol0[16];
    int tid = threadIdx.x;
    if (tid < 16) Wcol0[tid] = Wlsh[tid * 16];   // column 0 of W_lsh
    __syncthreads();
    int idx = blockIdx.x * 256 + tid;
    int e = idx >> 4, m = idx & 15;
    int s = snd[e];
    float xv = s16[idx];
    const float4* wyp = (const float4*)(wY + (size_t)s * 256 + m * 16);
    const float4* yp  = (const float4*)(Y + (size_t)e * 16);
    float vv[16];
    #pragma unroll
    for (int q = 0; q < 4; q++) {
        float4 a = wyp[q];
        float4 y = yp[q];
        vv[q*4+0] = 0.25f * a.x * xv * y.x;
        vv[q*4+1] = 0.25f * a.y * xv * y.y;
        vv[q*4+2] = 0.25f * a.z * xv * y.z;
        vv[q*4+3] = 0.25f * a.w * xv * y.w;
    }
    VV0p[(size_t)e * 32 + m] = tf32r(vv[0]);
    VV0p[(size_t)e * 32 + 16 + m] = 0.f;
    float o0 = 0.f;
    #pragma unroll
    for (int i = 0; i < 16; i++) o0 += vv[i] * Wcol0[i];
    V0[idx] = o0;
}

// ---------------- layer-1 update: VV0 only ----------------
__global__ __launch_bounds__(256)
void k_update1(const int* __restrict__ snd, const float* __restrict__ wY,
               const float* __restrict__ V0, float* __restrict__ VV0p)
{
    int idx = blockIdx.x * 256 + threadIdx.x;
    int e = idx >> 4, m = idx & 15;
    int s = snd[e];
    float wy0 = wY[(size_t)s * 256 + m * 16];
    VV0p[(size_t)e * 32 + m] = tf32r(0.25f * wy0 * V0[idx]);
    VV0p[(size_t)e * 32 + 16 + m] = 0.f;
}

// ---------------- host ----------------
extern "C" void kernel_launch(void* const* d_in, const int* in_sizes, int n_in,
                              void* d_out, int out_size)
{
    const float* attrs = (const float*)d_in[0];
    const float* vec   = (const float*)d_in[1];
    const int*   snd   = (const int*)d_in[2];
    const int*   rcv   = (const int*)d_in[3];
    const float* We0   = (const float*)d_in[4];
    const float* be0   = (const float*)d_in[5];
    const float* We1   = (const float*)d_in[6];
    const float* be1   = (const float*)d_in[7];
    const float* Wv0   = (const float*)d_in[8];
    const float* Wlw   = (const float*)d_in[9];
    const float* Wlsh  = (const float*)d_in[10];
    const float* Wly1  = (const float*)d_in[11];
    const float* bly1  = (const float*)d_in[12];
    const float* Wly2  = (const float*)d_in[13];
    const float* bly2  = (const float*)d_in[14];
    const float* Wout  = (const float*)d_in[15];
    float* out = (float*)d_out;

    float *featp, *uu, *Y, *x, *s16, *w16, *V0, *VV0p, *wY, *Bt;
    cudaGetSymbolAddress((void**)&featp, g_featp);
    cudaGetSymbolAddress((void**)&uu,    g_u);
    cudaGetSymbolAddress((void**)&Y,     g_Y);
    cudaGetSymbolAddress((void**)&x,     g_x);
    cudaGetSymbolAddress((void**)&s16,   g_s16);
    cudaGetSymbolAddress((void**)&w16,   g_w16);
    cudaGetSymbolAddress((void**)&V0,    g_V0);
    cudaGetSymbolAddress((void**)&VV0p,  g_VV0p);
    cudaGetSymbolAddress((void**)&wY,    g_wY);
    cudaGetSymbolAddress((void**)&Bt,    g_Bt);

    // transposed weight regions [256][Kp]
    float* Bt_e0  = Bt + 0;        // Kp=64
    float* Bt_e1  = Bt + 16384;    // Kp=256
    float* Bt_l10 = Bt + 81920;    // Kp=288
    float* Bt_l11 = Bt + 155648;   // Kp=288
    float* Bt_l20 = Bt + 229376;   // Kp=256
    float* Bt_l21 = Bt + 294912;   // Kp=256

    const int FSM_BYTES = FSM_FLOATS * 4;   // 206848
    cudaFuncSetAttribute(fgemm<2>, cudaFuncAttributeMaxDynamicSharedMemorySize, FSM_BYTES);
    cudaFuncSetAttribute(fgemm<3>, cudaFuncAttributeMaxDynamicSharedMemorySize, FSM_BYTES);
    cudaFuncSetAttribute(fgemm<4>, cudaFuncAttributeMaxDynamicSharedMemorySize, FSM_BYTES);

    const int GB = EE / 128;   // 1024 CTAs

    // launch order: fgemm<2> at index 3 (observed ncu capture position)
    k_geom<<<EE / 256, 256>>>(vec, attrs, snd, rcv, featp, uu, Y);               // 0
    k_wprep3<<<64 + 256 + 288, 256>>>(We0, Bt_e0, 40, 64,                        // 1
                                      We1, Bt_e1, 256, 256,
                                      Wly1, Bt_l10, 272, 288);
    k_wprep3<<<288 + 256 + 256, 256>>>(Wly1 + 272 * 256, Bt_l11, 272, 288,      // 2
                                       Wly2, Bt_l20, 256, 256,
                                       Wly2 + 256 * 256, Bt_l21, 256, 256);

    // e0 -> e1 fused:  x = u * silu(silu(feat@We0+be0) @ We1 + be1)             // 3
    fgemm<2><<<GB, 512, FSM_BYTES>>>(featp, 64, 2, nullptr,
                                     Bt_e0, 64, 2, be0,
                                     Bt_e1, be1, uu, x,
                                     nullptr, nullptr, nullptr);

    // ---- layer 0 ----
    k_zero4<<<(NN * 256 / 4 + 255) / 256, 256>>>((float4*)wY, NN * 256 / 4);
    gemm_n16_dual<<<EE / 128, 128>>>(x, Wv0, Wlw, s16, w16);
    k_scatter<<<EE * 16 / 256, 256>>>(w16, Y, snd, wY);
    k_update0<<<EE * 16 / 256, 256>>>(snd, wY, s16, Y, V0, VV0p, Wlsh);
    fgemm<3><<<GB, 512, FSM_BYTES>>>(x, 256, 8, VV0p,
                                     Bt_l10, 288, 9, bly1,
                                     Bt_l20, bly2, uu, x,
                                     nullptr, nullptr, nullptr);

    // ---- layer 1 ----
    gemm_n16<<<EE / 128, 128>>>(x, Wlw + 256 * 16, w16);
    k_zero4<<<(NN * 256 / 4 + 255) / 256, 256>>>((float4*)wY, NN * 256 / 4);
    k_scatter<<<EE * 16 / 256, 256>>>(w16, Y, snd, wY);
    k_update1<<<EE * 16 / 256, 256>>>(snd, wY, V0, VV0p);
    k_zero4<<<(NN / 4 + 255) / 256, 256>>>((float4*)out, NN / 4);
    fgemm<4><<<GB, 512, FSM_BYTES>>>(x, 256, 8, VV0p,
                                     Bt_l11, 288, 9, bly1 + 256,
                                     Bt_l21, bly2 + 256, uu, x,
                                     Wout, rcv, out);
}

// round 12
// speedup vs baseline: 1.9507x; 1.0338x over previous
#include <cuda_runtime.h>
#include <math.h>
#include <cstdint>

#define NN 8192
#define EE 131072

// ---------------- scratch (device globals; no allocations allowed) ----------------
__device__ __align__(16) float g_featp[EE * 64];   // bessel+attrs, padded K 40->64
__device__ __align__(16) float g_u[EE];
__device__ __align__(16) float g_Y[EE * 16];
__device__ __align__(16) float g_x[EE * 256];
__device__ __align__(16) float g_s16[EE * 16];     // xv (x @ Wv0), persistent
__device__ __align__(16) float g_w16[EE * 16];     // per-layer w = x @ Wlw[l]
__device__ __align__(16) float g_V0[EE * 16];      // V[:,:,0] after layer-0 rotation
__device__ __align__(16) float g_VV0p[EE * 32];    // VV[:, :, 0] padded 16->32
__device__ __align__(16) float g_wY[NN * 256];
__device__ __align__(16) float g_Bt[360448];       // pair-permuted tf32 weights

// ---------------- helpers ----------------
__device__ __forceinline__ float tf32r(float v) {
    uint32_t r;
    asm("cvt.rna.tf32.f32 %0, %1;" : "=r"(r) : "f"(v));
    return __uint_as_float(r);
}
__device__ __forceinline__ uint32_t smem_u32(const void* p) {
    uint32_t a;
    asm("{ .reg .u64 t; cvta.to.shared.u64 t, %1; cvt.u32.u64 %0, t; }" : "=r"(a) : "l"(p));
    return a;
}
__device__ __forceinline__ void cp16(uint32_t dst, const void* src) {
    asm volatile("cp.async.cg.shared.global [%0], [%1], 16;" :: "r"(dst), "l"(src));
}
#define CP_COMMIT() asm volatile("cp.async.commit_group;" ::: "memory")
#define CP_WAIT(n)  asm volatile("cp.async.wait_group %0;" :: "n"(n) : "memory")

__device__ __forceinline__ void mma8(float* d, const uint32_t* a, const uint32_t* b) {
    asm volatile(
        "mma.sync.aligned.m16n8k8.row.col.f32.tf32.tf32.f32 "
        "{%0,%1,%2,%3}, {%4,%5,%6,%7}, {%8,%9}, {%0,%1,%2,%3};"
        : "+f"(d[0]), "+f"(d[1]), "+f"(d[2]), "+f"(d[3])
        : "r"(a[0]), "r"(a[1]), "r"(a[2]), "r"(a[3]), "r"(b[0]), "r"(b[1]));
}

__device__ __forceinline__ float silu_f(float t) { return t / (1.0f + __expf(-t)); }

// smem layout (floats)
static constexpr int APAD = 36;                       // GEMM1 A stage row stride
static constexpr int BPX  = 40;                       // B pair-stage row stride (20 float2)
static constexpr int STG1_A = 128 * APAD;             // 4608
static constexpr int STG1_B = 256 * BPX;              // 10240
static constexpr int STG1 = STG1_A + STG1_B;          // 14848 (x2 stages = 29696)
static constexpr int TQS = 66;                        // TQ row stride in float4s
static constexpr int TQ_FLOATS = 128 * TQS * 4;       // 33792 (aliases GEMM1 stages)
static constexpr int B2_OFF = TQ_FLOATS;              // 33792
static constexpr int FSM_FLOATS = B2_OFF + 2 * STG1_B;// 54272 floats = 217088 B

// ---------------- fused GEMM pair, 512 threads (16 warps, 2x8 warp grid) ----------
// GEMM1: T = silu(A[E,K1] @ B1 + bias1)  -> TQ (quad fragment layout, smem)
// GEMM2: per EPI on  T @ B2 + bias2  (K=256)
// EPI: 2 = C = u*silu,  3 = C = (C + u*silu)/sqrt(2),
//      4 = no C write; out[rcv[row]] += dot((C+u*silu)/sqrt2, Wout)*u*inv
template<int EPI>
__global__ __launch_bounds__(512, 1) void fgemm(
    const float* __restrict__ A1, int sA1, int ntA1,
    const float* __restrict__ A2,
    const float* __restrict__ B1, int Kp1, int nt1,    // pair-permuted [256][nt1*32]
    const float* __restrict__ bias1,
    const float* __restrict__ B2,                      // pair-permuted [256][256]
    const float* __restrict__ bias2,
    const float* __restrict__ u, float* __restrict__ C,
    const float* __restrict__ Wout, const int* __restrict__ rcv,
    float* __restrict__ out)
{
    extern __shared__ float smf[];
    uint32_t sb = smem_u32(smf);
    int tid = threadIdx.x, lane = tid & 31, wid = tid >> 5;
    int t3 = lane & 3, r1 = lane >> 2;
    int warp_m = wid & 1, warp_n = wid >> 1;     // 2 x 8 warp grid, 64x32 warp tile
    int rowBase = blockIdx.x * 128;

    auto load_tile1 = [&](int kt, int buf) {
        uint32_t stBase = sb + buf * STG1 * 4;
        const float* Ap;
        int stride;
        if (kt < ntA1) { Ap = A1 + (size_t)rowBase * sA1 + kt * 32; stride = sA1; }
        else           { Ap = A2 + (size_t)rowBase * 32;            stride = 32;  }
        #pragma unroll
        for (int i = 0; i < 2; i++) {
            int f = tid + i * 512;
            int r = f >> 3, q = f & 7;
            cp16(stBase + (r * APAD + q * 4) * 4, Ap + (size_t)r * stride + q * 4);
        }
        const float* Bp = B1 + kt * 32;
        uint32_t bBase = stBase + STG1_A * 4;
        #pragma unroll
        for (int i = 0; i < 4; i++) {
            int f = tid + i * 512;
            int n = f >> 3, g = f & 7;
            cp16(bBase + (n * BPX + g * 4) * 4, Bp + (size_t)n * Kp1 + g * 4);
        }
        CP_COMMIT();
    };
    auto load_B2 = [&](int kt, int buf) {
        const float* Bp = B2 + kt * 32;
        uint32_t bBase = sb + (B2_OFF + buf * STG1_B) * 4;
        #pragma unroll
        for (int i = 0; i < 4; i++) {
            int f = tid + i * 512;
            int n = f >> 3, g = f & 7;
            cp16(bBase + (n * BPX + g * 4) * 4, Bp + (size_t)n * 256 + g * 4);
        }
        CP_COMMIT();
    };

    float acc[4][4][4];
    auto zero_acc = [&]() {
        #pragma unroll
        for (int i = 0; i < 4; i++)
            #pragma unroll
            for (int j = 0; j < 4; j++)
                #pragma unroll
                for (int q = 0; q < 4; q++) acc[i][j][q] = 0.f;
    };

    // GEMM1 slab: scalar A loads (row-major stage), pair-float2 B loads
    auto slab_g1 = [&](const float* As, const float* Bs) {
        #pragma unroll
        for (int s = 0; s < 4; s++) {
            uint32_t a[4][4];
            float2 bq[4];
            int c1 = s * 8 + t3;
            #pragma unroll
            for (int i = 0; i < 4; i++) {
                int rb = warp_m * 64 + i * 16 + r1;
                a[i][0] = __float_as_uint(As[rb * APAD + c1]);
                a[i][1] = __float_as_uint(As[(rb + 8) * APAD + c1]);
                a[i][2] = __float_as_uint(As[rb * APAD + c1 + 4]);
                a[i][3] = __float_as_uint(As[(rb + 8) * APAD + c1 + 4]);
            }
            int pi = s * 4 + t3;
            #pragma unroll
            for (int j = 0; j < 4; j++) {
                int cb = warp_n * 32 + j * 8 + r1;
                bq[j] = *(const float2*)&Bs[cb * BPX + pi * 2];
            }
            #pragma unroll
            for (int i = 0; i < 4; i++)
                #pragma unroll
                for (int j = 0; j < 4; j++)
                    mma8(acc[i][j], a[i], (const uint32_t*)&bq[j]);
        }
    };

    // ================= GEMM1 =================
    zero_acc();
    load_tile1(0, 0);
    if (nt1 > 1) load_tile1(1, 1);
    for (int kt = 0; kt < nt1; kt++) {
        if (kt + 1 < nt1) CP_WAIT(1); else CP_WAIT(0);
        __syncthreads();
        const float* As = smf + (kt & 1) * STG1;
        slab_g1(As, As + STG1_A);
        __syncthreads();
        if (kt + 2 < nt1) load_tile1(kt + 2, kt & 1);
    }

    load_B2(0, 0);
    load_B2(1, 1);

    // GEMM1 epilogue: silu + bias -> TQ quad layout (tf32-rounded)
    {
        int c_sel = (t3 & 1) * 2 + (t3 >> 1);
        #pragma unroll
        for (int i = 0; i < 4; i++) {
            int p = (warp_m * 4 + i) * 8 + r1;
            #pragma unroll
            for (int j = 0; j < 4; j++) {
                int col = warp_n * 32 + j * 8 + 2 * t3;
                float b0 = __ldg(bias1 + col), b1 = __ldg(bias1 + col + 1);
                float o0 = tf32r(silu_f(acc[i][j][0] + b0));
                float o1 = tf32r(silu_f(acc[i][j][1] + b1));
                float o2 = tf32r(silu_f(acc[i][j][2] + b0));
                float o3 = tf32r(silu_f(acc[i][j][3] + b1));
                float q0 = __shfl_xor_sync(0xffffffffu, o0, 2);
                float q1 = __shfl_xor_sync(0xffffffffu, o1, 2);
                float q2 = __shfl_xor_sync(0xffffffffu, o2, 2);
                float q3 = __shfl_xor_sync(0xffffffffu, o3, 2);
                int kq = (warp_n * 4 + j) * 4 + c_sel;
                float4 v = (t3 < 2) ? make_float4(o0, o2, q0, q2)
                                    : make_float4(q1, q3, o1, o3);
                *(float4*)&smf[(kq * TQS + p) * 4] = v;
            }
        }
    }

    // ================= GEMM2 (K = 256, A = TQ quads) =================
    zero_acc();
    for (int kt = 0; kt < 8; kt++) {
        if (kt < 7) CP_WAIT(1); else CP_WAIT(0);
        __syncthreads();            // TQ writes visible at kt=0; B2 stage ready
        const float* Bs = smf + B2_OFF + (kt & 1) * STG1_B;
        #pragma unroll
        for (int s = 0; s < 4; s++) {
            float4 aq[4];
            float2 bq[4];
            int kq = kt * 16 + s * 4 + t3;
            #pragma unroll
            for (int i = 0; i < 4; i++) {
                int p = (warp_m * 4 + i) * 8 + r1;
                aq[i] = *(const float4*)&smf[(kq * TQS + p) * 4];
            }
            int pi = s * 4 + t3;
            #pragma unroll
            for (int j = 0; j < 4; j++) {
                int cb = warp_n * 32 + j * 8 + r1;
                bq[j] = *(const float2*)&Bs[cb * BPX + pi * 2];
            }
            #pragma unroll
            for (int i = 0; i < 4; i++)
                #pragma unroll
                for (int j = 0; j < 4; j++)
                    mma8(acc[i][j], (const uint32_t*)&aq[i], (const uint32_t*)&bq[j]);
        }
        __syncthreads();
        if (kt + 2 < 8) load_B2(kt + 2, kt & 1);
    }

    // ---- final epilogue ----
    const float RS2 = 0.7071067811865476f;
    float wo0[4], wo1[4];
    if (EPI == 4) {
        #pragma unroll
        for (int j = 0; j < 4; j++) {
            int col = warp_n * 32 + j * 8 + 2 * t3;
            wo0[j] = __ldg(Wout + col);
            wo1[j] = __ldg(Wout + col + 1);
        }
    }
    #pragma unroll
    for (int i = 0; i < 4; i++) {
        int ra = rowBase + warp_m * 64 + i * 16 + r1;
        int rb = ra + 8;
        float ua = u[ra], ub = u[rb];
        float pa = 0.f, pb = 0.f;
        #pragma unroll
        for (int j = 0; j < 4; j++) {
            int col = warp_n * 32 + j * 8 + 2 * t3;
            float b0 = __ldg(bias2 + col), b1 = __ldg(bias2 + col + 1);
            float o0 = ua * silu_f(acc[i][j][0] + b0);
            float o1 = ua * silu_f(acc[i][j][1] + b1);
            float o2 = ub * silu_f(acc[i][j][2] + b0);
            float o3 = ub * silu_f(acc[i][j][3] + b1);
            if (EPI == 2) {
                *(float2*)(C + (size_t)ra * 256 + col) = make_float2(tf32r(o0), tf32r(o1));
                *(float2*)(C + (size_t)rb * 256 + col) = make_float2(tf32r(o2), tf32r(o3));
            } else {
                float2 oa = *(const float2*)(C + (size_t)ra * 256 + col);
                float2 ob = *(const float2*)(C + (size_t)rb * 256 + col);
                o0 = (oa.x + o0) * RS2; o1 = (oa.y + o1) * RS2;
                o2 = (ob.x + o2) * RS2; o3 = (ob.y + o3) * RS2;
                if (EPI == 3) {
                    *(float2*)(C + (size_t)ra * 256 + col) = make_float2(tf32r(o0), tf32r(o1));
                    *(float2*)(C + (size_t)rb * 256 + col) = make_float2(tf32r(o2), tf32r(o3));
                } else {
                    pa += o0 * wo0[j] + o1 * wo1[j];
                    pb += o2 * wo0[j] + o3 * wo1[j];
                }
            }
        }
        if (EPI == 4) {
            pa += __shfl_xor_sync(0xffffffffu, pa, 1);
            pa += __shfl_xor_sync(0xffffffffu, pa, 2);
            pb += __shfl_xor_sync(0xffffffffu, pb, 1);
            pb += __shfl_xor_sync(0xffffffffu, pb, 2);
            if (t3 == 0) {
                atomicAdd(out + __ldg(rcv + ra), pa * ua * 0.25f);
                atomicAdd(out + __ldg(rcv + rb), pb * ub * 0.25f);
            }
        }
    }
}

// ---------------- weight prep: transpose + tf32 + PAIR permutation ----------------
// Output layout: Btp[n][kt][32]: float index f in tile -> pi = f>>1, h = f&1,
//   k = kt*32 + (pi>>2)*8 + (pi&3) + 4*h
__global__ void k_wprep3(const float* __restrict__ W0, float* __restrict__ d0, int K0, int Kp0,
                         const float* __restrict__ W1, float* __restrict__ d1, int K1, int Kp1,
                         const float* __restrict__ W2, float* __restrict__ d2, int K2, int Kp2)
{
    int b = blockIdx.x;
    const float* W; float* d; int K, Kp, rb;
    if (b < Kp0)            { W = W0; d = d0; K = K0; Kp = Kp0; rb = b; }
    else if (b < Kp0 + Kp1) { W = W1; d = d1; K = K1; Kp = Kp1; rb = b - Kp0; }
    else                    { W = W2; d = d2; K = K2; Kp = Kp2; rb = b - Kp0 - Kp1; }
    int idx = rb * 256 + threadIdx.x;      // over 256*Kp
    int n = idx / Kp, rem = idx % Kp;
    int kt = rem >> 5, f = rem & 31;
    int pi = f >> 1, h = f & 1;
    int k = kt * 32 + (pi >> 2) * 8 + (pi & 3) + 4 * h;
    d[idx] = (k < K) ? tf32r(W[(size_t)k * 256 + n]) : 0.f;
}

// ---------------- geometry ----------------
__global__ void k_geom(const float* __restrict__ vec, const float* __restrict__ attrs,
                       const int* __restrict__ snd, const int* __restrict__ rcv,
                       float* __restrict__ feat, float* __restrict__ uo, float* __restrict__ Yo)
{
    int e = blockIdx.x * blockDim.x + threadIdx.x;
    if (e >= EE) return;
    float vx = vec[3*e+0], vy = vec[3*e+1], vz = vec[3*e+2];
    float d2 = vx*vx + vy*vy + vz*vz;
    float d  = sqrtf(d2);
    float d6 = d2 * d2 * d2;
    float env = 1.0f + d6 * (-28.0f + d * (48.0f - 21.0f * d));
    uo[e] = env;
    float invd = 1.0f / d;
    const float S2 = 1.4142135623730951f;
    float* fp = feat + (size_t)e * 64;
    #pragma unroll
    for (int k = 1; k <= 8; k++)
        fp[k-1] = tf32r(S2 * sinpif((float)k * d) * invd);
    int s = snd[e], r = rcv[e];
    #pragma unroll
    for (int i = 0; i < 16; i++) fp[8 + i]  = tf32r(attrs[s*16 + i]);
    #pragma unroll
    for (int i = 0; i < 16; i++) fp[24 + i] = tf32r(attrs[r*16 + i]);
    #pragma unroll
    for (int i = 40; i < 64; i++) fp[i] = 0.f;

    float x = vx*invd, y = vy*invd, z = vz*invd;
    const float s3  = 1.7320508075688772f;
    const float s5  = 2.2360679774997896f;
    const float s15 = 3.8729833462074170f;
    const float s7  = 2.6457513110645907f;
    const float c33 = 2.0916500663351885f;
    const float c32 = 10.246950765959598f;
    const float c31 = 1.6201851746019649f;
    float* Yp = Yo + (size_t)e * 16;
    Yp[0]  = 1.0f;
    Yp[1]  = s3 * x;  Yp[2]  = s3 * y;  Yp[3]  = s3 * z;
    Yp[4]  = s15 * x * y;  Yp[5]  = s15 * y * z;
    Yp[6]  = 0.5f * s5 * (3.0f*z*z - 1.0f);
    Yp[7]  = s15 * x * z;
    Yp[8]  = 0.5f * s15 * (x*x - y*y);
    Yp[9]  = c33 * y * (3.0f*x*x - y*y);
    Yp[10] = c32 * x * y * z;
    Yp[11] = c31 * y * (5.0f*z*z - 1.0f);
    Yp[12] = 0.5f * s7 * (5.0f*z*z*z - 3.0f*z);
    Yp[13] = c31 * x * (5.0f*z*z - 1.0f);
    Yp[14] = 0.5f * c32 * z * (x*x - y*y);
    Yp[15] = c33 * x * (x*x - 3.0f*y*y);
}

// ---------------- (E,256) @ (256,16) x2 sharing one x read ----------
__global__ __launch_bounds__(128) void gemm_n16_dual(const float* __restrict__ X,
                                                     const float* __restrict__ Wa,
                                                     const float* __restrict__ Wb,
                                                     float* __restrict__ Sa,
                                                     float* __restrict__ Sb)
{
    __shared__ __align__(16) float Ws[8192];
    int tid = threadIdx.x;
    #pragma unroll
    for (int i = 0; i < 8; i++)
        ((float4*)Ws)[tid + i * 128] = ((const float4*)Wa)[tid + i * 128];
    #pragma unroll
    for (int i = 0; i < 8; i++)
        ((float4*)(Ws + 4096))[tid + i * 128] = ((const float4*)Wb)[tid + i * 128];
    __syncthreads();
    size_t e = (size_t)blockIdx.x * 128 + tid;
    const float4* xr = (const float4*)(X + e * 256);
    float acca[16], accb[16];
    #pragma unroll
    for (int c = 0; c < 16; c++) { acca[c] = 0.f; accb[c] = 0.f; }
    #pragma unroll 2
    for (int k4 = 0; k4 < 64; k4++) {
        float4 xv = xr[k4];
        float xs[4] = {xv.x, xv.y, xv.z, xv.w};
        #pragma unroll
        for (int j = 0; j < 4; j++) {
            const float4* wra = (const float4*)&Ws[(k4 * 4 + j) * 16];
            const float4* wrb = (const float4*)&Ws[4096 + (k4 * 4 + j) * 16];
            #pragma unroll
            for (int q = 0; q < 4; q++) {
                float4 wa = wra[q], wb = wrb[q];
                acca[q*4+0] += xs[j] * wa.x;  accb[q*4+0] += xs[j] * wb.x;
                acca[q*4+1] += xs[j] * wa.y;  accb[q*4+1] += xs[j] * wb.y;
                acca[q*4+2] += xs[j] * wa.z;  accb[q*4+2] += xs[j] * wb.z;
                acca[q*4+3] += xs[j] * wa.w;  accb[q*4+3] += xs[j] * wb.w;
            }
        }
    }
    float4* spa = (float4*)(Sa + e * 16);
    float4* spb = (float4*)(Sb + e * 16);
    #pragma unroll
    for (int q = 0; q < 4; q++) {
        spa[q] = make_float4(acca[q*4], acca[q*4+1], acca[q*4+2], acca[q*4+3]);
        spb[q] = make_float4(accb[q*4], accb[q*4+1], accb[q*4+2], accb[q*4+3]);
    }
}

// ---------------- single-output N=16 GEMM (layer-1 w) ----------------
__global__ __launch_bounds__(128) void gemm_n16(const float* __restrict__ X,
                                                const float* __restrict__ W,
                                                float* __restrict__ S)
{
    __shared__ __align__(16) float Ws[4096];
    int tid = threadIdx.x;
    #pragma unroll
    for (int i = 0; i < 8; i++)
        ((float4*)Ws)[tid + i * 128] = ((const float4*)W)[tid + i * 128];
    __syncthreads();
    size_t e = (size_t)blockIdx.x * 128 + tid;
    const float4* xr = (const float4*)(X + e * 256);
    float acc[16];
    #pragma unroll
    for (int c = 0; c < 16; c++) acc[c] = 0.f;
    #pragma unroll 4
    for (int k4 = 0; k4 < 64; k4++) {
        float4 xv = xr[k4];
        float xs[4] = {xv.x, xv.y, xv.z, xv.w};
        #pragma unroll
        for (int j = 0; j < 4; j++) {
            const float4* wr = (const float4*)&Ws[(k4 * 4 + j) * 16];
            #pragma unroll
            for (int q = 0; q < 4; q++) {
                float4 w = wr[q];
                acc[q*4+0] += xs[j] * w.x;
                acc[q*4+1] += xs[j] * w.y;
                acc[q*4+2] += xs[j] * w.z;
                acc[q*4+3] += xs[j] * w.w;
            }
        }
    }
    float4* sp = (float4*)(S + e * 16);
    #pragma unroll
    for (int q = 0; q < 4; q++)
        sp[q] = make_float4(acc[q*4], acc[q*4+1], acc[q*4+2], acc[q*4+3]);
}

__global__ void k_zero4(float4* p, int n4)
{
    int i = blockIdx.x * blockDim.x + threadIdx.x;
    if (i < n4) p[i] = make_float4(0.f, 0.f, 0.f, 0.f);
}

// ---------------- segment_sum scatter: 16 threads per edge ----------
__global__ void k_scatter(const float* __restrict__ w, const float* __restrict__ Y,
                          const int* __restrict__ snd, float* __restrict__ wY)
{
    int idx = blockIdx.x * blockDim.x + threadIdx.x;   // e*16 + m
    int e = idx >> 4, m = idx & 15;
    float wv = w[idx];
    int s = snd[e];
    float* base = wY + (size_t)s * 256 + m * 16;
    const float4* Y4 = (const float4*)(Y + (size_t)e * 16);
    #pragma unroll
    for (int q = 0; q < 4; q++) {
        float4 y = Y4[q];
        atomicAdd(base + q*4 + 0, wv * y.x);
        atomicAdd(base + q*4 + 1, wv * y.y);
        atomicAdd(base + q*4 + 2, wv * y.z);
        atomicAdd(base + q*4 + 3, wv * y.w);
    }
}

// ---------------- layer-0 update ----------------
__global__ __launch_bounds__(256)
void k_update0(const int* __restrict__ snd, const float* __restrict__ wY,
               const float* __restrict__ s16, const float* __restrict__ Y,
               float* __restrict__ V0, float* __restrict__ VV0p,
               const float* __restrict__ Wlsh)
{
    __shared__ float Wcol0[16];
    int tid = threadIdx.x;
    if (tid < 16) Wcol0[tid] = Wlsh[tid * 16];
    __syncthreads();
    int idx = blockIdx.x * 256 + tid;
    int e = idx >> 4, m = idx & 15;
    int s = snd[e];
    float xv = s16[idx];
    const float4* wyp = (const float4*)(wY + (size_t)s * 256 + m * 16);
    const float4* yp  = (const float4*)(Y + (size_t)e * 16);
    float vv[16];
    #pragma unroll
    for (int q = 0; q < 4; q++) {
        float4 a = wyp[q];
        float4 y = yp[q];
        vv[q*4+0] = 0.25f * a.x * xv * y.x;
        vv[q*4+1] = 0.25f * a.y * xv * y.y;
        vv[q*4+2] = 0.25f * a.z * xv * y.z;
        vv[q*4+3] = 0.25f * a.w * xv * y.w;
    }
    VV0p[(size_t)e * 32 + m] = tf32r(vv[0]);
    VV0p[(size_t)e * 32 + 16 + m] = 0.f;
    float o0 = 0.f;
    #pragma unroll
    for (int i = 0; i < 16; i++) o0 += vv[i] * Wcol0[i];
    V0[idx] = o0;
}

// ---------------- layer-1 update ----------------
__global__ __launch_bounds__(256)
void k_update1(const int* __restrict__ snd, const float* __restrict__ wY,
               const float* __restrict__ V0, float* __restrict__ VV0p)
{
    int idx = blockIdx.x * 256 + threadIdx.x;
    int e = idx >> 4, m = idx & 15;
    int s = snd[e];
    float wy0 = wY[(size_t)s * 256 + m * 16];
    VV0p[(size_t)e * 32 + m] = tf32r(0.25f * wy0 * V0[idx]);
    VV0p[(size_t)e * 32 + 16 + m] = 0.f;
}

// ---------------- host ----------------
extern "C" void kernel_launch(void* const* d_in, const int* in_sizes, int n_in,
                              void* d_out, int out_size)
{
    const float* attrs = (const float*)d_in[0];
    const float* vec   = (const float*)d_in[1];
    const int*   snd   = (const int*)d_in[2];
    const int*   rcv   = (const int*)d_in[3];
    const float* We0   = (const float*)d_in[4];
    const float* be0   = (const float*)d_in[5];
    const float* We1   = (const float*)d_in[6];
    const float* be1   = (const float*)d_in[7];
    const float* Wv0   = (const float*)d_in[8];
    const float* Wlw   = (const float*)d_in[9];
    const float* Wlsh  = (const float*)d_in[10];
    const float* Wly1  = (const float*)d_in[11];
    const float* bly1  = (const float*)d_in[12];
    const float* Wly2  = (const float*)d_in[13];
    const float* bly2  = (const float*)d_in[14];
    const float* Wout  = (const float*)d_in[15];
    float* out = (float*)d_out;

    float *featp, *uu, *Y, *x, *s16, *w16, *V0, *VV0p, *wY, *Bt;
    cudaGetSymbolAddress((void**)&featp, g_featp);
    cudaGetSymbolAddress((void**)&uu,    g_u);
    cudaGetSymbolAddress((void**)&Y,     g_Y);
    cudaGetSymbolAddress((void**)&x,     g_x);
    cudaGetSymbolAddress((void**)&s16,   g_s16);
    cudaGetSymbolAddress((void**)&w16,   g_w16);
    cudaGetSymbolAddress((void**)&V0,    g_V0);
    cudaGetSymbolAddress((void**)&VV0p,  g_VV0p);
    cudaGetSymbolAddress((void**)&wY,    g_wY);
    cudaGetSymbolAddress((void**)&Bt,    g_Bt);

    // pair-permuted weight regions [256][Kp]
    float* Bt_e0  = Bt + 0;        // Kp=64
    float* Bt_e1  = Bt + 16384;    // Kp=256
    float* Bt_l10 = Bt + 81920;    // Kp=288
    float* Bt_l11 = Bt + 155648;   // Kp=288
    float* Bt_l20 = Bt + 229376;   // Kp=256
    float* Bt_l21 = Bt + 294912;   // Kp=256

    const int FSM_BYTES = FSM_FLOATS * 4;   // 217088
    cudaFuncSetAttribute(fgemm<2>, cudaFuncAttributeMaxDynamicSharedMemorySize, FSM_BYTES);
    cudaFuncSetAttribute(fgemm<3>, cudaFuncAttributeMaxDynamicSharedMemorySize, FSM_BYTES);
    cudaFuncSetAttribute(fgemm<4>, cudaFuncAttributeMaxDynamicSharedMemorySize, FSM_BYTES);

    const int GB = EE / 128;   // 1024 CTAs

    k_geom<<<EE / 256, 256>>>(vec, attrs, snd, rcv, featp, uu, Y);               // 0
    k_wprep3<<<64 + 256 + 288, 256>>>(We0, Bt_e0, 40, 64,                        // 1
                                      We1, Bt_e1, 256, 256,
                                      Wly1, Bt_l10, 272, 288);
    k_wprep3<<<288 + 256 + 256, 256>>>(Wly1 + 272 * 256, Bt_l11, 272, 288,      // 2
                                       Wly2, Bt_l20, 256, 256,
                                       Wly2 + 256 * 256, Bt_l21, 256, 256);

    // e0 -> e1 fused                                                            // 3
    fgemm<2><<<GB, 512, FSM_BYTES>>>(featp, 64, 2, nullptr,
                                     Bt_e0, 64, 2, be0,
                                     Bt_e1, be1, uu, x,
                                     nullptr, nullptr, nullptr);

    // ---- layer 0 ----
    k_zero4<<<(NN * 256 / 4 + 255) / 256, 256>>>((float4*)wY, NN * 256 / 4);
    gemm_n16_dual<<<EE / 128, 128>>>(x, Wv0, Wlw, s16, w16);
    k_scatter<<<EE * 16 / 256, 256>>>(w16, Y, snd, wY);
    k_update0<<<EE * 16 / 256, 256>>>(snd, wY, s16, Y, V0, VV0p, Wlsh);
    fgemm<3><<<GB, 512, FSM_BYTES>>>(x, 256, 8, VV0p,
                                     Bt_l10, 288, 9, bly1,
                                     Bt_l20, bly2, uu, x,
                                     nullptr, nullptr, nullptr);

    // ---- layer 1 ----
    gemm_n16<<<EE / 128, 128>>>(x, Wlw + 256 * 16, w16);
    k_zero4<<<(NN * 256 / 4 + 255) / 256, 256>>>((float4*)wY, NN * 256 / 4);
    k_scatter<<<EE * 16 / 256, 256>>>(w16, Y, snd, wY);
    k_update1<<<EE * 16 / 256, 256>>>(snd, wY, V0, VV0p);
    k_zero4<<<(NN / 4 + 255) / 256, 256>>>((float4*)out, NN / 4);
    fgemm<4><<<GB, 512, FSM_BYTES>>>(x, 256, 8, VV0p,
                                     Bt_l11, 288, 9, bly1 + 256,
                                     Bt_l21, bly2 + 256, uu, x,
                                     Wout, rcv, out);
}

// round 13
// speedup vs baseline: 2.1069x; 1.0801x over previous
#include <cuda_runtime.h>
#include <math.h>
#include <cstdint>

#define NN 8192
#define EE 131072

// ---------------- scratch (device globals; no allocations allowed) ----------------
__device__ __align__(16) float g_featp[EE * 64];   // bessel+attrs, padded K 40->64
__device__ __align__(16) float g_u[EE];
__device__ __align__(16) float g_Y[EE * 16];
__device__ __align__(16) float g_x[EE * 256];
__device__ __align__(16) float g_s16[EE * 16];     // xv (x @ Wv0), persistent
__device__ __align__(16) float g_w16[EE * 16];     // per-layer w = x @ Wlw[l]
__device__ __align__(16) float g_V0[EE * 16];      // V[:,:,0] after layer-0 rotation
__device__ __align__(16) float g_VV0p[EE * 32];    // VV[:, :, 0] padded 16->32
__device__ __align__(16) float g_wY[NN * 256];
__device__ __align__(16) float g_Bt[360448];       // warp-coalesced tf32 weights

// ---------------- helpers ----------------
__device__ __forceinline__ float tf32r(float v) {
    uint32_t r;
    asm("cvt.rna.tf32.f32 %0, %1;" : "=r"(r) : "f"(v));
    return __uint_as_float(r);
}
__device__ __forceinline__ uint32_t smem_u32(const void* p) {
    uint32_t a;
    asm("{ .reg .u64 t; cvta.to.shared.u64 t, %1; cvt.u32.u64 %0, t; }" : "=r"(a) : "l"(p));
    return a;
}
__device__ __forceinline__ void cp16(uint32_t dst, const void* src) {
    asm volatile("cp.async.cg.shared.global [%0], [%1], 16;" :: "r"(dst), "l"(src));
}
#define CP_COMMIT() asm volatile("cp.async.commit_group;" ::: "memory")
#define CP_WAIT(n)  asm volatile("cp.async.wait_group %0;" :: "n"(n) : "memory")

__device__ __forceinline__ void mma8(float* d, const uint32_t* a, const uint32_t* b) {
    asm volatile(
        "mma.sync.aligned.m16n8k8.row.col.f32.tf32.tf32.f32 "
        "{%0,%1,%2,%3}, {%4,%5,%6,%7}, {%8,%9}, {%0,%1,%2,%3};"
        : "+f"(d[0]), "+f"(d[1]), "+f"(d[2]), "+f"(d[3])
        : "r"(a[0]), "r"(a[1]), "r"(a[2]), "r"(a[3]), "r"(b[0]), "r"(b[1]));
}

__device__ __forceinline__ float silu_f(float t) { return t / (1.0f + __expf(-t)); }

// smem layout (floats): 3-stage A ring aliases low part of TQ region
static constexpr int APAD = 36;
static constexpr int STGA = 64 * APAD;            // 2304 floats per A stage (3 stages = 6912)
static constexpr int TQS  = 34;                   // TQ row stride in float4s
static constexpr int FSM_FLOATS = 128 * TQS * 4;  // 17408 floats = 69632 B

// ---------------- fused GEMM pair: M-tile 64, 256 threads, 2 CTAs/SM ----------------
// GEMM1: T = silu(A[E,K1] @ B1 + bias1)  -> TQ (quad layout, smem)
// GEMM2: per EPI on  T @ B2 + bias2  (K=256); B via coalesced LDG (L2), sync-free
// EPI: 2 = C = u*silu,  3 = C = (C + u*silu)/sqrt(2),
//      4 = no C write; out[rcv[row]] += dot((C+u*silu)/sqrt2, Wout)*u*inv
template<int EPI>
__global__ __launch_bounds__(256, 2) void fgemm(
    const float* __restrict__ A1, int sA1, int ntA1,
    const float* __restrict__ A2,
    const float* __restrict__ B1, int nt1,             // warp-coalesced [Kp1/8][8][4][32]x2
    const float* __restrict__ bias1,
    const float* __restrict__ B2,                      // warp-coalesced, Kp=256
    const float* __restrict__ bias2,
    const float* __restrict__ u, float* __restrict__ C,
    const float* __restrict__ Wout, const int* __restrict__ rcv,
    float* __restrict__ out)
{
    extern __shared__ float smf[];
    uint32_t sb = smem_u32(smf);
    int tid = threadIdx.x, lane = tid & 31, wid = tid >> 5;
    int t3 = lane & 3, r1 = lane >> 2;
    int warp_n = wid;                 // 1 x 8 warp grid, 64x32 warp tile
    int rowBase = blockIdx.x * 64;

    auto load_A = [&](int kt, int buf) {
        uint32_t stBase = sb + buf * STGA * 4;
        const float* Ap;
        int stride;
        if (kt < ntA1) { Ap = A1 + (size_t)rowBase * sA1 + kt * 32; stride = sA1; }
        else           { Ap = A2 + (size_t)rowBase * 32;            stride = 32;  }
        #pragma unroll
        for (int i = 0; i < 2; i++) {
            int f = tid + i * 256;
            int r = f >> 3, q = f & 7;
            cp16(stBase + (r * APAD + q * 4) * 4, Ap + (size_t)r * stride + q * 4);
        }
        CP_COMMIT();
    };

    float acc[4][4][4];
    auto zero_acc = [&]() {
        #pragma unroll
        for (int i = 0; i < 4; i++)
            #pragma unroll
            for (int j = 0; j < 4; j++)
                #pragma unroll
                for (int q = 0; q < 4; q++) acc[i][j][q] = 0.f;
    };

    // ================= GEMM1 (A staged, B coalesced LDG) =================
    zero_acc();
    load_A(0, 0);
    if (nt1 > 1) load_A(1, 1);
    const float2* B1p = (const float2*)B1;
    for (int kt = 0; kt < nt1; kt++) {
        if (kt + 1 < nt1) CP_WAIT(1); else CP_WAIT(0);
        __syncthreads();
        if (kt + 2 < nt1) load_A(kt + 2, (kt + 2) % 3);
        const float* As = smf + (kt % 3) * STGA;
        #pragma unroll
        for (int s = 0; s < 4; s++) {
            uint32_t a[4][4];
            float2 bq[4];
            int b2base = ((kt * 4 + s) * 8 + warp_n) * 128 + lane;
            #pragma unroll
            for (int j = 0; j < 4; j++) bq[j] = __ldg(&B1p[b2base + j * 32]);
            int c1 = s * 8 + t3;
            #pragma unroll
            for (int i = 0; i < 4; i++) {
                int rb = i * 16 + r1;
                a[i][0] = __float_as_uint(As[rb * APAD + c1]);
                a[i][1] = __float_as_uint(As[(rb + 8) * APAD + c1]);
                a[i][2] = __float_as_uint(As[rb * APAD + c1 + 4]);
                a[i][3] = __float_as_uint(As[(rb + 8) * APAD + c1 + 4]);
            }
            #pragma unroll
            for (int i = 0; i < 4; i++)
                #pragma unroll
                for (int j = 0; j < 4; j++)
                    mma8(acc[i][j], a[i], (const uint32_t*)&bq[j]);
        }
    }

    __syncthreads();   // all warps done reading A stages (TQ aliases them)

    // GEMM1 epilogue: silu + bias -> TQ quad layout (tf32-rounded)
    {
        int c_sel = (t3 & 1) * 2 + (t3 >> 1);
        #pragma unroll
        for (int i = 0; i < 4; i++) {
            int p = i * 8 + r1;
            #pragma unroll
            for (int j = 0; j < 4; j++) {
                int col = warp_n * 32 + j * 8 + 2 * t3;
                float b0 = __ldg(bias1 + col), b1 = __ldg(bias1 + col + 1);
                float o0 = tf32r(silu_f(acc[i][j][0] + b0));
                float o1 = tf32r(silu_f(acc[i][j][1] + b1));
                float o2 = tf32r(silu_f(acc[i][j][2] + b0));
                float o3 = tf32r(silu_f(acc[i][j][3] + b1));
                float q0 = __shfl_xor_sync(0xffffffffu, o0, 2);
                float q1 = __shfl_xor_sync(0xffffffffu, o1, 2);
                float q2 = __shfl_xor_sync(0xffffffffu, o2, 2);
                float q3 = __shfl_xor_sync(0xffffffffu, o3, 2);
                int kq = (warp_n * 4 + j) * 4 + c_sel;
                float4 v = (t3 < 2) ? make_float4(o0, o2, q0, q2)
                                    : make_float4(q1, q3, o1, o3);
                *(float4*)&smf[(kq * TQS + p) * 4] = v;
            }
        }
    }
    __syncthreads();

    // ================= GEMM2 (A = TQ smem, B = coalesced LDG, sync-free) ==========
    zero_acc();
    const float2* B2p = (const float2*)B2;
    #pragma unroll 2
    for (int kt = 0; kt < 8; kt++) {
        #pragma unroll
        for (int s = 0; s < 4; s++) {
            float4 aq[4];
            float2 bq[4];
            int b2base = ((kt * 4 + s) * 8 + warp_n) * 128 + lane;
            #pragma unroll
            for (int j = 0; j < 4; j++) bq[j] = __ldg(&B2p[b2base + j * 32]);
            int kq = kt * 16 + s * 4 + t3;
            #pragma unroll
            for (int i = 0; i < 4; i++)
                aq[i] = *(const float4*)&smf[(kq * TQS + i * 8 + r1) * 4];
            #pragma unroll
            for (int i = 0; i < 4; i++)
                #pragma unroll
                for (int j = 0; j < 4; j++)
                    mma8(acc[i][j], (const uint32_t*)&aq[i], (const uint32_t*)&bq[j]);
        }
    }

    // ---- final epilogue ----
    const float RS2 = 0.7071067811865476f;
    float wo0[4], wo1[4];
    if (EPI == 4) {
        #pragma unroll
        for (int j = 0; j < 4; j++) {
            int col = warp_n * 32 + j * 8 + 2 * t3;
            wo0[j] = __ldg(Wout + col);
            wo1[j] = __ldg(Wout + col + 1);
        }
    }
    #pragma unroll
    for (int i = 0; i < 4; i++) {
        int ra = rowBase + i * 16 + r1;
        int rb = ra + 8;
        float ua = u[ra], ub = u[rb];
        float pa = 0.f, pb = 0.f;
        #pragma unroll
        for (int j = 0; j < 4; j++) {
            int col = warp_n * 32 + j * 8 + 2 * t3;
            float b0 = __ldg(bias2 + col), b1 = __ldg(bias2 + col + 1);
            float o0 = ua * silu_f(acc[i][j][0] + b0);
            float o1 = ua * silu_f(acc[i][j][1] + b1);
            float o2 = ub * silu_f(acc[i][j][2] + b0);
            float o3 = ub * silu_f(acc[i][j][3] + b1);
            if (EPI == 2) {
                *(float2*)(C + (size_t)ra * 256 + col) = make_float2(tf32r(o0), tf32r(o1));
                *(float2*)(C + (size_t)rb * 256 + col) = make_float2(tf32r(o2), tf32r(o3));
            } else {
                float2 oa = *(const float2*)(C + (size_t)ra * 256 + col);
                float2 ob = *(const float2*)(C + (size_t)rb * 256 + col);
                o0 = (oa.x + o0) * RS2; o1 = (oa.y + o1) * RS2;
                o2 = (ob.x + o2) * RS2; o3 = (ob.y + o3) * RS2;
                if (EPI == 3) {
                    *(float2*)(C + (size_t)ra * 256 + col) = make_float2(tf32r(o0), tf32r(o1));
                    *(float2*)(C + (size_t)rb * 256 + col) = make_float2(tf32r(o2), tf32r(o3));
                } else {
                    pa += o0 * wo0[j] + o1 * wo1[j];
                    pb += o2 * wo0[j] + o3 * wo1[j];
                }
            }
        }
        if (EPI == 4) {
            pa += __shfl_xor_sync(0xffffffffu, pa, 1);
            pa += __shfl_xor_sync(0xffffffffu, pa, 2);
            pb += __shfl_xor_sync(0xffffffffu, pb, 1);
            pb += __shfl_xor_sync(0xffffffffu, pb, 2);
            if (t3 == 0) {
                atomicAdd(out + __ldg(rcv + ra), pa * ua * 0.25f);
                atomicAdd(out + __ldg(rcv + rb), pb * ub * 0.25f);
            }
        }
    }
}

// ---------------- weight prep: transpose + tf32 + warp-coalesced permutation --------
// float idx f: F2=f>>1, h=f&1, lane=F2&31, j=(F2>>5)&3, nb=(F2>>7)&7, ks=F2>>10
//   n = nb*32 + j*8 + (lane>>2),  k = ks*8 + (lane&3) + 4*h
__global__ void k_wprep3(const float* __restrict__ W0, float* __restrict__ d0, int K0, int Kp0,
                         const float* __restrict__ W1, float* __restrict__ d1, int K1, int Kp1,
                         const float* __restrict__ W2, float* __restrict__ d2, int K2, int Kp2)
{
    int b = blockIdx.x;
    const float* W; float* d; int K, Kp, rb;
    if (b < Kp0)            { W = W0; d = d0; K = K0; Kp = Kp0; rb = b; }
    else if (b < Kp0 + Kp1) { W = W1; d = d1; K = K1; Kp = Kp1; rb = b - Kp0; }
    else                    { W = W2; d = d2; K = K2; Kp = Kp2; rb = b - Kp0 - Kp1; }
    int idx = rb * 256 + threadIdx.x;      // over 256*Kp
    int F2 = idx >> 1, h = idx & 1;
    int ln = F2 & 31, jj = (F2 >> 5) & 3, nb = (F2 >> 7) & 7, ks = F2 >> 10;
    int n = nb * 32 + jj * 8 + (ln >> 2);
    int k = ks * 8 + (ln & 3) + 4 * h;
    d[idx] = (k < K) ? tf32r(W[(size_t)k * 256 + n]) : 0.f;
}

// ---------------- geometry ----------------
__global__ void k_geom(const float* __restrict__ vec, const float* __restrict__ attrs,
                       const int* __restrict__ snd, const int* __restrict__ rcv,
                       float* __restrict__ feat, float* __restrict__ uo, float* __restrict__ Yo)
{
    int e = blockIdx.x * blockDim.x + threadIdx.x;
    if (e >= EE) return;
    float vx = vec[3*e+0], vy = vec[3*e+1], vz = vec[3*e+2];
    float d2 = vx*vx + vy*vy + vz*vz;
    float d  = sqrtf(d2);
    float d6 = d2 * d2 * d2;
    float env = 1.0f + d6 * (-28.0f + d * (48.0f - 21.0f * d));
    uo[e] = env;
    float invd = 1.0f / d;
    const float S2 = 1.4142135623730951f;
    float* fp = feat + (size_t)e * 64;
    #pragma unroll
    for (int k = 1; k <= 8; k++)
        fp[k-1] = tf32r(S2 * sinpif((float)k * d) * invd);
    int s = snd[e], r = rcv[e];
    #pragma unroll
    for (int i = 0; i < 16; i++) fp[8 + i]  = tf32r(attrs[s*16 + i]);
    #pragma unroll
    for (int i = 0; i < 16; i++) fp[24 + i] = tf32r(attrs[r*16 + i]);
    #pragma unroll
    for (int i = 40; i < 64; i++) fp[i] = 0.f;

    float x = vx*invd, y = vy*invd, z = vz*invd;
    const float s3  = 1.7320508075688772f;
    const float s5  = 2.2360679774997896f;
    const float s15 = 3.8729833462074170f;
    const float s7  = 2.6457513110645907f;
    const float c33 = 2.0916500663351885f;
    const float c32 = 10.246950765959598f;
    const float c31 = 1.6201851746019649f;
    float* Yp = Yo + (size_t)e * 16;
    Yp[0]  = 1.0f;
    Yp[1]  = s3 * x;  Yp[2]  = s3 * y;  Yp[3]  = s3 * z;
    Yp[4]  = s15 * x * y;  Yp[5]  = s15 * y * z;
    Yp[6]  = 0.5f * s5 * (3.0f*z*z - 1.0f);
    Yp[7]  = s15 * x * z;
    Yp[8]  = 0.5f * s15 * (x*x - y*y);
    Yp[9]  = c33 * y * (3.0f*x*x - y*y);
    Yp[10] = c32 * x * y * z;
    Yp[11] = c31 * y * (5.0f*z*z - 1.0f);
    Yp[12] = 0.5f * s7 * (5.0f*z*z*z - 3.0f*z);
    Yp[13] = c31 * x * (5.0f*z*z - 1.0f);
    Yp[14] = 0.5f * c32 * z * (x*x - y*y);
    Yp[15] = c33 * x * (x*x - 3.0f*y*y);
}

// ---------------- (E,256) @ (256,16) x2 sharing one x read ----------
__global__ __launch_bounds__(128) void gemm_n16_dual(const float* __restrict__ X,
                                                     const float* __restrict__ Wa,
                                                     const float* __restrict__ Wb,
                                                     float* __restrict__ Sa,
                                                     float* __restrict__ Sb)
{
    __shared__ __align__(16) float Ws[8192];
    int tid = threadIdx.x;
    #pragma unroll
    for (int i = 0; i < 8; i++)
        ((float4*)Ws)[tid + i * 128] = ((const float4*)Wa)[tid + i * 128];
    #pragma unroll
    for (int i = 0; i < 8; i++)
        ((float4*)(Ws + 4096))[tid + i * 128] = ((const float4*)Wb)[tid + i * 128];
    __syncthreads();
    size_t e = (size_t)blockIdx.x * 128 + tid;
    const float4* xr = (const float4*)(X + e * 256);
    float acca[16], accb[16];
    #pragma unroll
    for (int c = 0; c < 16; c++) { acca[c] = 0.f; accb[c] = 0.f; }
    #pragma unroll 2
    for (int k4 = 0; k4 < 64; k4++) {
        float4 xv = xr[k4];
        float xs[4] = {xv.x, xv.y, xv.z, xv.w};
        #pragma unroll
        for (int j = 0; j < 4; j++) {
            const float4* wra = (const float4*)&Ws[(k4 * 4 + j) * 16];
            const float4* wrb = (const float4*)&Ws[4096 + (k4 * 4 + j) * 16];
            #pragma unroll
            for (int q = 0; q < 4; q++) {
                float4 wa = wra[q], wb = wrb[q];
                acca[q*4+0] += xs[j] * wa.x;  accb[q*4+0] += xs[j] * wb.x;
                acca[q*4+1] += xs[j] * wa.y;  accb[q*4+1] += xs[j] * wb.y;
                acca[q*4+2] += xs[j] * wa.z;  accb[q*4+2] += xs[j] * wb.z;
                acca[q*4+3] += xs[j] * wa.w;  accb[q*4+3] += xs[j] * wb.w;
            }
        }
    }
    float4* spa = (float4*)(Sa + e * 16);
    float4* spb = (float4*)(Sb + e * 16);
    #pragma unroll
    for (int q = 0; q < 4; q++) {
        spa[q] = make_float4(acca[q*4], acca[q*4+1], acca[q*4+2], acca[q*4+3]);
        spb[q] = make_float4(accb[q*4], accb[q*4+1], accb[q*4+2], accb[q*4+3]);
    }
}

// ---------------- single-output N=16 GEMM (layer-1 w) ----------------
__global__ __launch_bounds__(128) void gemm_n16(const float* __restrict__ X,
                                                const float* __restrict__ W,
                                                float* __restrict__ S)
{
    __shared__ __align__(16) float Ws[4096];
    int tid = threadIdx.x;
    #pragma unroll
    for (int i = 0; i < 8; i++)
        ((float4*)Ws)[tid + i * 128] = ((const float4*)W)[tid + i * 128];
    __syncthreads();
    size_t e = (size_t)blockIdx.x * 128 + tid;
    const float4* xr = (const float4*)(X + e * 256);
    float acc[16];
    #pragma unroll
    for (int c = 0; c < 16; c++) acc[c] = 0.f;
    #pragma unroll 4
    for (int k4 = 0; k4 < 64; k4++) {
        float4 xv = xr[k4];
        float xs[4] = {xv.x, xv.y, xv.z, xv.w};
        #pragma unroll
        for (int j = 0; j < 4; j++) {
            const float4* wr = (const float4*)&Ws[(k4 * 4 + j) * 16];
            #pragma unroll
            for (int q = 0; q < 4; q++) {
                float4 w = wr[q];
                acc[q*4+0] += xs[j] * w.x;
                acc[q*4+1] += xs[j] * w.y;
                acc[q*4+2] += xs[j] * w.z;
                acc[q*4+3] += xs[j] * w.w;
            }
        }
    }
    float4* sp = (float4*)(S + e * 16);
    #pragma unroll
    for (int q = 0; q < 4; q++)
        sp[q] = make_float4(acc[q*4], acc[q*4+1], acc[q*4+2], acc[q*4+3]);
}

__global__ void k_zero4(float4* p, int n4)
{
    int i = blockIdx.x * blockDim.x + threadIdx.x;
    if (i < n4) p[i] = make_float4(0.f, 0.f, 0.f, 0.f);
}

// ---------------- segment_sum scatter: 16 threads per edge ----------
__global__ void k_scatter(const float* __restrict__ w, const float* __restrict__ Y,
                          const int* __restrict__ snd, float* __restrict__ wY)
{
    int idx = blockIdx.x * blockDim.x + threadIdx.x;   // e*16 + m
    int e = idx >> 4, m = idx & 15;
    float wv = w[idx];
    int s = snd[e];
    float* base = wY + (size_t)s * 256 + m * 16;
    const float4* Y4 = (const float4*)(Y + (size_t)e * 16);
    #pragma unroll
    for (int q = 0; q < 4; q++) {
        float4 y = Y4[q];
        atomicAdd(base + q*4 + 0, wv * y.x);
        atomicAdd(base + q*4 + 1, wv * y.y);
        atomicAdd(base + q*4 + 2, wv * y.z);
        atomicAdd(base + q*4 + 3, wv * y.w);
    }
}

// ---------------- layer-0 update ----------------
__global__ __launch_bounds__(256)
void k_update0(const int* __restrict__ snd, const float* __restrict__ wY,
               const float* __restrict__ s16, const float* __restrict__ Y,
               float* __restrict__ V0, float* __restrict__ VV0p,
               const float* __restrict__ Wlsh)
{
    __shared__ float Wcol0[16];
    int tid = threadIdx.x;
    if (tid < 16) Wcol0[tid] = Wlsh[tid * 16];
    __syncthreads();
    int idx = blockIdx.x * 256 + tid;
    int e = idx >> 4, m = idx & 15;
    int s = snd[e];
    float xv = s16[idx];
    const float4* wyp = (const float4*)(wY + (size_t)s * 256 + m * 16);
    const float4* yp  = (const float4*)(Y + (size_t)e * 16);
    float vv[16];
    #pragma unroll
    for (int q = 0; q < 4; q++) {
        float4 a = wyp[q];
        float4 y = yp[q];
        vv[q*4+0] = 0.25f * a.x * xv * y.x;
        vv[q*4+1] = 0.25f * a.y * xv * y.y;
        vv[q*4+2] = 0.25f * a.z * xv * y.z;
        vv[q*4+3] = 0.25f * a.w * xv * y.w;
    }
    VV0p[(size_t)e * 32 + m] = tf32r(vv[0]);
    VV0p[(size_t)e * 32 + 16 + m] = 0.f;
    float o0 = 0.f;
    #pragma unroll
    for (int i = 0; i < 16; i++) o0 += vv[i] * Wcol0[i];
    V0[idx] = o0;
}

// ---------------- layer-1 update ----------------
__global__ __launch_bounds__(256)
void k_update1(const int* __restrict__ snd, const float* __restrict__ wY,
               const float* __restrict__ V0, float* __restrict__ VV0p)
{
    int idx = blockIdx.x * 256 + threadIdx.x;
    int e = idx >> 4, m = idx & 15;
    int s = snd[e];
    float wy0 = wY[(size_t)s * 256 + m * 16];
    VV0p[(size_t)e * 32 + m] = tf32r(0.25f * wy0 * V0[idx]);
    VV0p[(size_t)e * 32 + 16 + m] = 0.f;
}

// ---------------- host ----------------
extern "C" void kernel_launch(void* const* d_in, const int* in_sizes, int n_in,
                              void* d_out, int out_size)
{
    const float* attrs = (const float*)d_in[0];
    const float* vec   = (const float*)d_in[1];
    const int*   snd   = (const int*)d_in[2];
    const int*   rcv   = (const int*)d_in[3];
    const float* We0   = (const float*)d_in[4];
    const float* be0   = (const float*)d_in[5];
    const float* We1   = (const float*)d_in[6];
    const float* be1   = (const float*)d_in[7];
    const float* Wv0   = (const float*)d_in[8];
    const float* Wlw   = (const float*)d_in[9];
    const float* Wlsh  = (const float*)d_in[10];
    const float* Wly1  = (const float*)d_in[11];
    const float* bly1  = (const float*)d_in[12];
    const float* Wly2  = (const float*)d_in[13];
    const float* bly2  = (const float*)d_in[14];
    const float* Wout  = (const float*)d_in[15];
    float* out = (float*)d_out;

    float *featp, *uu, *Y, *x, *s16, *w16, *V0, *VV0p, *wY, *Bt;
    cudaGetSymbolAddress((void**)&featp, g_featp);
    cudaGetSymbolAddress((void**)&uu,    g_u);
    cudaGetSymbolAddress((void**)&Y,     g_Y);
    cudaGetSymbolAddress((void**)&x,     g_x);
    cudaGetSymbolAddress((void**)&s16,   g_s16);
    cudaGetSymbolAddress((void**)&w16,   g_w16);
    cudaGetSymbolAddress((void**)&V0,    g_V0);
    cudaGetSymbolAddress((void**)&VV0p,  g_VV0p);
    cudaGetSymbolAddress((void**)&wY,    g_wY);
    cudaGetSymbolAddress((void**)&Bt,    g_Bt);

    // warp-coalesced weight regions, sizes 256*Kp floats
    float* Bt_e0  = Bt + 0;        // Kp=64
    float* Bt_e1  = Bt + 16384;    // Kp=256
    float* Bt_l10 = Bt + 81920;    // Kp=288
    float* Bt_l11 = Bt + 155648;   // Kp=288
    float* Bt_l20 = Bt + 229376;   // Kp=256
    float* Bt_l21 = Bt + 294912;   // Kp=256

    const int FSM_BYTES = FSM_FLOATS * 4;   // 69632
    cudaFuncSetAttribute(fgemm<2>, cudaFuncAttributeMaxDynamicSharedMemorySize, FSM_BYTES);
    cudaFuncSetAttribute(fgemm<3>, cudaFuncAttributeMaxDynamicSharedMemorySize, FSM_BYTES);
    cudaFuncSetAttribute(fgemm<4>, cudaFuncAttributeMaxDynamicSharedMemorySize, FSM_BYTES);

    const int GB = EE / 64;   // 2048 CTAs

    k_geom<<<EE / 256, 256>>>(vec, attrs, snd, rcv, featp, uu, Y);               // 0
    k_wprep3<<<64 + 256 + 288, 256>>>(We0, Bt_e0, 40, 64,                        // 1
                                      We1, Bt_e1, 256, 256,
                                      Wly1, Bt_l10, 272, 288);
    k_wprep3<<<288 + 256 + 256, 256>>>(Wly1 + 272 * 256, Bt_l11, 272, 288,      // 2
                                       Wly2, Bt_l20, 256, 256,
                                       Wly2 + 256 * 256, Bt_l21, 256, 256);

    // e0 -> e1 fused                                                            // 3
    fgemm<2><<<GB, 256, FSM_BYTES>>>(featp, 64, 2, nullptr,
                                     Bt_e0, 2, be0,
                                     Bt_e1, be1, uu, x,
                                     nullptr, nullptr, nullptr);

    // ---- layer 0 ----
    k_zero4<<<(NN * 256 / 4 + 255) / 256, 256>>>((float4*)wY, NN * 256 / 4);
    gemm_n16_dual<<<EE / 128, 128>>>(x, Wv0, Wlw, s16, w16);
    k_scatter<<<EE * 16 / 256, 256>>>(w16, Y, snd, wY);
    k_update0<<<EE * 16 / 256, 256>>>(snd, wY, s16, Y, V0, VV0p, Wlsh);
    fgemm<3><<<GB, 256, FSM_BYTES>>>(x, 256, 8, VV0p,
                                     Bt_l10, 9, bly1,
                                     Bt_l20, bly2, uu, x,
                                     nullptr, nullptr, nullptr);

    // ---- layer 1 ----
    gemm_n16<<<EE / 128, 128>>>(x, Wlw + 256 * 16, w16);
    k_zero4<<<(NN * 256 / 4 + 255) / 256, 256>>>((float4*)wY, NN * 256 / 4);
    k_scatter<<<EE * 16 / 256, 256>>>(w16, Y, snd, wY);
    k_update1<<<EE * 16 / 256, 256>>>(snd, wY, V0, VV0p);
    k_zero4<<<(NN / 4 + 255) / 256, 256>>>((float4*)out, NN / 4);
    fgemm<4><<<GB, 256, FSM_BYTES>>>(x, 256, 8, VV0p,
                                     Bt_l11, 9, bly1 + 256,
                                     Bt_l21, bly2 + 256, uu, x,
                                     Wout, rcv, out);
}

// round 14
// speedup vs baseline: 2.6121x; 1.2398x over previous
#include <cuda_runtime.h>
#include <math.h>
#include <cstdint>

#define NN 8192
#define EE 131072

// ---------------- scratch (device globals; no allocations allowed) ----------------
__device__ __align__(16) float g_featp[EE * 64];   // bessel+attrs, padded K 40->64
__device__ __align__(16) float g_u[EE];
__device__ __align__(16) float g_Y[EE * 16];
__device__ __align__(16) float g_x[EE * 256];
__device__ __align__(16) float g_s16[EE * 16];     // xv (x @ Wv0), persistent
__device__ __align__(16) float g_w16[EE * 16];     // per-layer w = x @ Wlw[l]
__device__ __align__(16) float g_V0[EE * 16];      // V[:,:,0] after layer-0 rotation
__device__ __align__(16) float g_VV0p[EE * 32];    // VV[:, :, 0] padded 16->32
__device__ __align__(16) float g_wY[NN * 256];
__device__ __align__(16) float g_Bt[360448];       // warp-coalesced tf32 weights

// ---------------- helpers ----------------
__device__ __forceinline__ float tf32r(float v) {
    uint32_t r;
    asm("cvt.rna.tf32.f32 %0, %1;" : "=r"(r) : "f"(v));
    return __uint_as_float(r);
}
__device__ __forceinline__ uint32_t smem_u32(const void* p) {
    uint32_t a;
    asm("{ .reg .u64 t; cvta.to.shared.u64 t, %1; cvt.u32.u64 %0, t; }" : "=r"(a) : "l"(p));
    return a;
}
__device__ __forceinline__ void cp16(uint32_t dst, const void* src) {
    asm volatile("cp.async.cg.shared.global [%0], [%1], 16;" :: "r"(dst), "l"(src));
}
#define CP_COMMIT() asm volatile("cp.async.commit_group;" ::: "memory")
#define CP_WAIT(n)  asm volatile("cp.async.wait_group %0;" :: "n"(n) : "memory")

__device__ __forceinline__ void mma8(float* d, const uint32_t* a, const uint32_t* b) {
    asm volatile(
        "mma.sync.aligned.m16n8k8.row.col.f32.tf32.tf32.f32 "
        "{%0,%1,%2,%3}, {%4,%5,%6,%7}, {%8,%9}, {%0,%1,%2,%3};"
        : "+f"(d[0]), "+f"(d[1]), "+f"(d[2]), "+f"(d[3])
        : "r"(a[0]), "r"(a[1]), "r"(a[2]), "r"(a[3]), "r"(b[0]), "r"(b[1]));
}

__device__ __forceinline__ void red4(float* p, float a, float b, float c, float d) {
    asm volatile("red.global.add.v4.f32 [%0], {%1, %2, %3, %4};"
                 :: "l"(p), "f"(a), "f"(b), "f"(c), "f"(d) : "memory");
}

__device__ __forceinline__ float silu_f(float t) { return t / (1.0f + __expf(-t)); }

// smem layout (floats): 3-stage A ring aliases low part of TQ region
static constexpr int APAD = 36;
static constexpr int STGA = 64 * APAD;            // 2304 floats per A stage (3 stages = 6912)
static constexpr int TQS  = 34;                   // TQ row stride in float4s
static constexpr int FSM_FLOATS = 128 * TQS * 4;  // 17408 floats = 69632 B

// ---------------- fused GEMM pair: M-tile 64, 256 threads, 2 CTAs/SM ----------------
// GEMM1: T = silu(A[E,K1] @ B1 + bias1)  -> TQ (quad layout, smem)
// GEMM2: per EPI on  T @ B2 + bias2  (K=256); B via coalesced LDG (L2), sync-free
// EPI: 2 = C = u*silu,  3 = C = (C + u*silu)/sqrt(2),
//      4 = no C write; out[rcv[row]] += dot((C+u*silu)/sqrt2, Wout)*u*inv
template<int EPI>
__global__ __launch_bounds__(256, 2) void fgemm(
    const float* __restrict__ A1, int sA1, int ntA1,
    const float* __restrict__ A2,
    const float* __restrict__ B1, int nt1,             // warp-coalesced [Kp1/8][8][4][32]x2
    const float* __restrict__ bias1,
    const float* __restrict__ B2,                      // warp-coalesced, Kp=256
    const float* __restrict__ bias2,
    const float* __restrict__ u, float* __restrict__ C,
    const float* __restrict__ Wout, const int* __restrict__ rcv,
    float* __restrict__ out)
{
    extern __shared__ float smf[];
    uint32_t sb = smem_u32(smf);
    int tid = threadIdx.x, lane = tid & 31, wid = tid >> 5;
    int t3 = lane & 3, r1 = lane >> 2;
    int warp_n = wid;                 // 1 x 8 warp grid, 64x32 warp tile
    int rowBase = blockIdx.x * 64;

    auto load_A = [&](int kt, int buf) {
        uint32_t stBase = sb + buf * STGA * 4;
        const float* Ap;
        int stride;
        if (kt < ntA1) { Ap = A1 + (size_t)rowBase * sA1 + kt * 32; stride = sA1; }
        else           { Ap = A2 + (size_t)rowBase * 32;            stride = 32;  }
        #pragma unroll
        for (int i = 0; i < 2; i++) {
            int f = tid + i * 256;
            int r = f >> 3, q = f & 7;
            cp16(stBase + (r * APAD + q * 4) * 4, Ap + (size_t)r * stride + q * 4);
        }
        CP_COMMIT();
    };

    float acc[4][4][4];
    auto zero_acc = [&]() {
        #pragma unroll
        for (int i = 0; i < 4; i++)
            #pragma unroll
            for (int j = 0; j < 4; j++)
                #pragma unroll
                for (int q = 0; q < 4; q++) acc[i][j][q] = 0.f;
    };

    // ================= GEMM1 (A staged, B coalesced LDG) =================
    zero_acc();
    load_A(0, 0);
    if (nt1 > 1) load_A(1, 1);
    const float2* B1p = (const float2*)B1;
    for (int kt = 0; kt < nt1; kt++) {
        if (kt + 1 < nt1) CP_WAIT(1); else CP_WAIT(0);
        __syncthreads();
        if (kt + 2 < nt1) load_A(kt + 2, (kt + 2) % 3);
        const float* As = smf + (kt % 3) * STGA;
        #pragma unroll
        for (int s = 0; s < 4; s++) {
            uint32_t a[4][4];
            float2 bq[4];
            int b2base = ((kt * 4 + s) * 8 + warp_n) * 128 + lane;
            #pragma unroll
            for (int j = 0; j < 4; j++) bq[j] = __ldg(&B1p[b2base + j * 32]);
            int c1 = s * 8 + t3;
            #pragma unroll
            for (int i = 0; i < 4; i++) {
                int rb = i * 16 + r1;
                a[i][0] = __float_as_uint(As[rb * APAD + c1]);
                a[i][1] = __float_as_uint(As[(rb + 8) * APAD + c1]);
                a[i][2] = __float_as_uint(As[rb * APAD + c1 + 4]);
                a[i][3] = __float_as_uint(As[(rb + 8) * APAD + c1 + 4]);
            }
            #pragma unroll
            for (int i = 0; i < 4; i++)
                #pragma unroll
                for (int j = 0; j < 4; j++)
                    mma8(acc[i][j], a[i], (const uint32_t*)&bq[j]);
        }
    }

    __syncthreads();   // all warps done reading A stages (TQ aliases them)

    // GEMM1 epilogue: silu + bias -> TQ quad layout (tf32-rounded)
    {
        int c_sel = (t3 & 1) * 2 + (t3 >> 1);
        #pragma unroll
        for (int i = 0; i < 4; i++) {
            int p = i * 8 + r1;
            #pragma unroll
            for (int j = 0; j < 4; j++) {
                int col = warp_n * 32 + j * 8 + 2 * t3;
                float b0 = __ldg(bias1 + col), b1 = __ldg(bias1 + col + 1);
                float o0 = tf32r(silu_f(acc[i][j][0] + b0));
                float o1 = tf32r(silu_f(acc[i][j][1] + b1));
                float o2 = tf32r(silu_f(acc[i][j][2] + b0));
                float o3 = tf32r(silu_f(acc[i][j][3] + b1));
                float q0 = __shfl_xor_sync(0xffffffffu, o0, 2);
                float q1 = __shfl_xor_sync(0xffffffffu, o1, 2);
                float q2 = __shfl_xor_sync(0xffffffffu, o2, 2);
                float q3 = __shfl_xor_sync(0xffffffffu, o3, 2);
                int kq = (warp_n * 4 + j) * 4 + c_sel;
                float4 v = (t3 < 2) ? make_float4(o0, o2, q0, q2)
                                    : make_float4(q1, q3, o1, o3);
                *(float4*)&smf[(kq * TQS + p) * 4] = v;
            }
        }
    }
    __syncthreads();

    // ================= GEMM2 (A = TQ smem, B prefetch-pipelined LDG) ==========
    zero_acc();
    const float2* B2p = (const float2*)B2;
    {
        float2 bq[4], bqn[4];
        int base0 = warp_n * 128 + lane;
        #pragma unroll
        for (int j = 0; j < 4; j++) bq[j] = __ldg(&B2p[base0 + j * 32]);
        for (int ss = 0; ss < 32; ss++) {
            if (ss + 1 < 32) {
                int bn = ((ss + 1) * 8 + warp_n) * 128 + lane;
                #pragma unroll
                for (int j = 0; j < 4; j++) bqn[j] = __ldg(&B2p[bn + j * 32]);
            }
            float4 aq[4];
            int kq = ss * 4 + t3;
            #pragma unroll
            for (int i = 0; i < 4; i++)
                aq[i] = *(const float4*)&smf[(kq * TQS + i * 8 + r1) * 4];
            #pragma unroll
            for (int i = 0; i < 4; i++)
                #pragma unroll
                for (int j = 0; j < 4; j++)
                    mma8(acc[i][j], (const uint32_t*)&aq[i], (const uint32_t*)&bq[j]);
            #pragma unroll
            for (int j = 0; j < 4; j++) bq[j] = bqn[j];
        }
    }

    // ---- final epilogue ----
    const float RS2 = 0.7071067811865476f;
    float wo0[4], wo1[4];
    if (EPI == 4) {
        #pragma unroll
        for (int j = 0; j < 4; j++) {
            int col = warp_n * 32 + j * 8 + 2 * t3;
            wo0[j] = __ldg(Wout + col);
            wo1[j] = __ldg(Wout + col + 1);
        }
    }
    #pragma unroll
    for (int i = 0; i < 4; i++) {
        int ra = rowBase + i * 16 + r1;
        int rb = ra + 8;
        float ua = u[ra], ub = u[rb];
        float pa = 0.f, pb = 0.f;
        #pragma unroll
        for (int j = 0; j < 4; j++) {
            int col = warp_n * 32 + j * 8 + 2 * t3;
            float b0 = __ldg(bias2 + col), b1 = __ldg(bias2 + col + 1);
            float o0 = ua * silu_f(acc[i][j][0] + b0);
            float o1 = ua * silu_f(acc[i][j][1] + b1);
            float o2 = ub * silu_f(acc[i][j][2] + b0);
            float o3 = ub * silu_f(acc[i][j][3] + b1);
            if (EPI == 2) {
                *(float2*)(C + (size_t)ra * 256 + col) = make_float2(tf32r(o0), tf32r(o1));
                *(float2*)(C + (size_t)rb * 256 + col) = make_float2(tf32r(o2), tf32r(o3));
            } else {
                float2 oa = *(const float2*)(C + (size_t)ra * 256 + col);
                float2 ob = *(const float2*)(C + (size_t)rb * 256 + col);
                o0 = (oa.x + o0) * RS2; o1 = (oa.y + o1) * RS2;
                o2 = (ob.x + o2) * RS2; o3 = (ob.y + o3) * RS2;
                if (EPI == 3) {
                    *(float2*)(C + (size_t)ra * 256 + col) = make_float2(tf32r(o0), tf32r(o1));
                    *(float2*)(C + (size_t)rb * 256 + col) = make_float2(tf32r(o2), tf32r(o3));
                } else {
                    pa += o0 * wo0[j] + o1 * wo1[j];
                    pb += o2 * wo0[j] + o3 * wo1[j];
                }
            }
        }
        if (EPI == 4) {
            pa += __shfl_xor_sync(0xffffffffu, pa, 1);
            pa += __shfl_xor_sync(0xffffffffu, pa, 2);
            pb += __shfl_xor_sync(0xffffffffu, pb, 1);
            pb += __shfl_xor_sync(0xffffffffu, pb, 2);
            if (t3 == 0) {
                atomicAdd(out + __ldg(rcv + ra), pa * ua * 0.25f);
                atomicAdd(out + __ldg(rcv + rb), pb * ub * 0.25f);
            }
        }
    }
}

// ---------------- weight prep: transpose + tf32 + warp-coalesced permutation --------
// float idx f: F2=f>>1, h=f&1, lane=F2&31, j=(F2>>5)&3, nb=(F2>>7)&7, ks=F2>>10
//   n = nb*32 + j*8 + (lane>>2),  k = ks*8 + (lane&3) + 4*h
__global__ void k_wprep3(const float* __restrict__ W0, float* __restrict__ d0, int K0, int Kp0,
                         const float* __restrict__ W1, float* __restrict__ d1, int K1, int Kp1,
                         const float* __restrict__ W2, float* __restrict__ d2, int K2, int Kp2)
{
    int b = blockIdx.x;
    const float* W; float* d; int K, Kp, rb;
    if (b < Kp0)            { W = W0; d = d0; K = K0; Kp = Kp0; rb = b; }
    else if (b < Kp0 + Kp1) { W = W1; d = d1; K = K1; Kp = Kp1; rb = b - Kp0; }
    else                    { W = W2; d = d2; K = K2; Kp = Kp2; rb = b - Kp0 - Kp1; }
    int idx = rb * 256 + threadIdx.x;      // over 256*Kp
    int F2 = idx >> 1, h = idx & 1;
    int ln = F2 & 31, jj = (F2 >> 5) & 3, nb = (F2 >> 7) & 7, ks = F2 >> 10;
    int n = nb * 32 + jj * 8 + (ln >> 2);
    int k = ks * 8 + (ln & 3) + 4 * h;
    d[idx] = (k < K) ? tf32r(W[(size_t)k * 256 + n]) : 0.f;
}

// ---------------- geometry ----------------
__global__ void k_geom(const float* __restrict__ vec, const float* __restrict__ attrs,
                       const int* __restrict__ snd, const int* __restrict__ rcv,
                       float* __restrict__ feat, float* __restrict__ uo, float* __restrict__ Yo)
{
    int e = blockIdx.x * blockDim.x + threadIdx.x;
    if (e >= EE) return;
    float vx = vec[3*e+0], vy = vec[3*e+1], vz = vec[3*e+2];
    float d2 = vx*vx + vy*vy + vz*vz;
    float d  = sqrtf(d2);
    float d6 = d2 * d2 * d2;
    float env = 1.0f + d6 * (-28.0f + d * (48.0f - 21.0f * d));
    uo[e] = env;
    float invd = 1.0f / d;
    const float S2 = 1.4142135623730951f;
    float* fp = feat + (size_t)e * 64;
    #pragma unroll
    for (int k = 1; k <= 8; k++)
        fp[k-1] = tf32r(S2 * sinpif((float)k * d) * invd);
    int s = snd[e], r = rcv[e];
    #pragma unroll
    for (int i = 0; i < 16; i++) fp[8 + i]  = tf32r(attrs[s*16 + i]);
    #pragma unroll
    for (int i = 0; i < 16; i++) fp[24 + i] = tf32r(attrs[r*16 + i]);
    #pragma unroll
    for (int i = 40; i < 64; i++) fp[i] = 0.f;

    float x = vx*invd, y = vy*invd, z = vz*invd;
    const float s3  = 1.7320508075688772f;
    const float s5  = 2.2360679774997896f;
    const float s15 = 3.8729833462074170f;
    const float s7  = 2.6457513110645907f;
    const float c33 = 2.0916500663351885f;
    const float c32 = 10.246950765959598f;
    const float c31 = 1.6201851746019649f;
    float* Yp = Yo + (size_t)e * 16;
    Yp[0]  = 1.0f;
    Yp[1]  = s3 * x;  Yp[2]  = s3 * y;  Yp[3]  = s3 * z;
    Yp[4]  = s15 * x * y;  Yp[5]  = s15 * y * z;
    Yp[6]  = 0.5f * s5 * (3.0f*z*z - 1.0f);
    Yp[7]  = s15 * x * z;
    Yp[8]  = 0.5f * s15 * (x*x - y*y);
    Yp[9]  = c33 * y * (3.0f*x*x - y*y);
    Yp[10] = c32 * x * y * z;
    Yp[11] = c31 * y * (5.0f*z*z - 1.0f);
    Yp[12] = 0.5f * s7 * (5.0f*z*z*z - 3.0f*z);
    Yp[13] = c31 * x * (5.0f*z*z - 1.0f);
    Yp[14] = 0.5f * c32 * z * (x*x - y*y);
    Yp[15] = c33 * x * (x*x - 3.0f*y*y);
}

// ---------------- (E,256) @ (256,16) x2 sharing one x read ----------
__global__ __launch_bounds__(128) void gemm_n16_dual(const float* __restrict__ X,
                                                     const float* __restrict__ Wa,
                                                     const float* __restrict__ Wb,
                                                     float* __restrict__ Sa,
                                                     float* __restrict__ Sb)
{
    __shared__ __align__(16) float Ws[8192];
    int tid = threadIdx.x;
    #pragma unroll
    for (int i = 0; i < 8; i++)
        ((float4*)Ws)[tid + i * 128] = ((const float4*)Wa)[tid + i * 128];
    #pragma unroll
    for (int i = 0; i < 8; i++)
        ((float4*)(Ws + 4096))[tid + i * 128] = ((const float4*)Wb)[tid + i * 128];
    __syncthreads();
    size_t e = (size_t)blockIdx.x * 128 + tid;
    const float4* xr = (const float4*)(X + e * 256);
    float acca[16], accb[16];
    #pragma unroll
    for (int c = 0; c < 16; c++) { acca[c] = 0.f; accb[c] = 0.f; }
    #pragma unroll 2
    for (int k4 = 0; k4 < 64; k4++) {
        float4 xv = xr[k4];
        float xs[4] = {xv.x, xv.y, xv.z, xv.w};
        #pragma unroll
        for (int j = 0; j < 4; j++) {
            const float4* wra = (const float4*)&Ws[(k4 * 4 + j) * 16];
            const float4* wrb = (const float4*)&Ws[4096 + (k4 * 4 + j) * 16];
            #pragma unroll
            for (int q = 0; q < 4; q++) {
                float4 wa = wra[q], wb = wrb[q];
                acca[q*4+0] += xs[j] * wa.x;  accb[q*4+0] += xs[j] * wb.x;
                acca[q*4+1] += xs[j] * wa.y;  accb[q*4+1] += xs[j] * wb.y;
                acca[q*4+2] += xs[j] * wa.z;  accb[q*4+2] += xs[j] * wb.z;
                acca[q*4+3] += xs[j] * wa.w;  accb[q*4+3] += xs[j] * wb.w;
            }
        }
    }
    float4* spa = (float4*)(Sa + e * 16);
    float4* spb = (float4*)(Sb + e * 16);
    #pragma unroll
    for (int q = 0; q < 4; q++) {
        spa[q] = make_float4(acca[q*4], acca[q*4+1], acca[q*4+2], acca[q*4+3]);
        spb[q] = make_float4(accb[q*4], accb[q*4+1], accb[q*4+2], accb[q*4+3]);
    }
}

// ---------------- single-output N=16 GEMM (layer-1 w) ----------------
__global__ __launch_bounds__(128) void gemm_n16(const float* __restrict__ X,
                                                const float* __restrict__ W,
                                                float* __restrict__ S)
{
    __shared__ __align__(16) float Ws[4096];
    int tid = threadIdx.x;
    #pragma unroll
    for (int i = 0; i < 8; i++)
        ((float4*)Ws)[tid + i * 128] = ((const float4*)W)[tid + i * 128];
    __syncthreads();
    size_t e = (size_t)blockIdx.x * 128 + tid;
    const float4* xr = (const float4*)(X + e * 256);
    float acc[16];
    #pragma unroll
    for (int c = 0; c < 16; c++) acc[c] = 0.f;
    #pragma unroll 4
    for (int k4 = 0; k4 < 64; k4++) {
        float4 xv = xr[k4];
        float xs[4] = {xv.x, xv.y, xv.z, xv.w};
        #pragma unroll
        for (int j = 0; j < 4; j++) {
            const float4* wr = (const float4*)&Ws[(k4 * 4 + j) * 16];
            #pragma unroll
            for (int q = 0; q < 4; q++) {
                float4 w = wr[q];
                acc[q*4+0] += xs[j] * w.x;
                acc[q*4+1] += xs[j] * w.y;
                acc[q*4+2] += xs[j] * w.z;
                acc[q*4+3] += xs[j] * w.w;
            }
        }
    }
    float4* sp = (float4*)(S + e * 16);
    #pragma unroll
    for (int q = 0; q < 4; q++)
        sp[q] = make_float4(acc[q*4], acc[q*4+1], acc[q*4+2], acc[q*4+3]);
}

__global__ void k_zero4(float4* p, int n4)
{
    int i = blockIdx.x * blockDim.x + threadIdx.x;
    if (i < n4) p[i] = make_float4(0.f, 0.f, 0.f, 0.f);
}

// ---------------- segment_sum scatter: 16 threads per edge, vector reds ----------
__global__ void k_scatter(const float* __restrict__ w, const float* __restrict__ Y,
                          const int* __restrict__ snd, float* __restrict__ wY)
{
    int idx = blockIdx.x * blockDim.x + threadIdx.x;   // e*16 + m
    int e = idx >> 4, m = idx & 15;
    float wv = w[idx];
    int s = snd[e];
    float* base = wY + (size_t)s * 256 + m * 16;
    const float4* Y4 = (const float4*)(Y + (size_t)e * 16);
    #pragma unroll
    for (int q = 0; q < 4; q++) {
        float4 y = Y4[q];
        red4(base + q * 4, wv * y.x, wv * y.y, wv * y.z, wv * y.w);
    }
}

// ---------------- layer-0 update ----------------
__global__ __launch_bounds__(256)
void k_update0(const int* __restrict__ snd, const float* __restrict__ wY,
               const float* __restrict__ s16, const float* __restrict__ Y,
               float* __restrict__ V0, float* __restrict__ VV0p,
               const float* __restrict__ Wlsh)
{
    __shared__ float Wcol0[16];
    int tid = threadIdx.x;
    if (tid < 16) Wcol0[tid] = Wlsh[tid * 16];
    __syncthreads();
    int idx = blockIdx.x * 256 + tid;
    int e = idx >> 4, m = idx & 15;
    int s = snd[e];
    float xv = s16[idx];
    const float4* wyp = (const float4*)(wY + (size_t)s * 256 + m * 16);
    const float4* yp  = (const float4*)(Y + (size_t)e * 16);
    float vv[16];
    #pragma unroll
    for (int q = 0; q < 4; q++) {
        float4 a = wyp[q];
        float4 y = yp[q];
        vv[q*4+0] = 0.25f * a.x * xv * y.x;
        vv[q*4+1] = 0.25f * a.y * xv * y.y;
        vv[q*4+2] = 0.25f * a.z * xv * y.z;
        vv[q*4+3] = 0.25f * a.w * xv * y.w;
    }
    VV0p[(size_t)e * 32 + m] = tf32r(vv[0]);
    VV0p[(size_t)e * 32 + 16 + m] = 0.f;
    float o0 = 0.f;
    #pragma unroll
    for (int i = 0; i < 16; i++) o0 += vv[i] * Wcol0[i];
    V0[idx] = o0;
}

// ---------------- layer-1 update ----------------
__global__ __launch_bounds__(256)
void k_update1(const int* __restrict__ snd, const float* __restrict__ wY,
               const float* __restrict__ V0, float* __restrict__ VV0p)
{
    int idx = blockIdx.x * 256 + threadIdx.x;
    int e = idx >> 4, m = idx & 15;
    int s = snd[e];
    float wy0 = wY[(size_t)s * 256 + m * 16];
    VV0p[(size_t)e * 32 + m] = tf32r(0.25f * wy0 * V0[idx]);
    VV0p[(size_t)e * 32 + 16 + m] = 0.f;
}

// ---------------- host ----------------
extern "C" void kernel_launch(void* const* d_in, const int* in_sizes, int n_in,
                              void* d_out, int out_size)
{
    const float* attrs = (const float*)d_in[0];
    const float* vec   = (const float*)d_in[1];
    const int*   snd   = (const int*)d_in[2];
    const int*   rcv   = (const int*)d_in[3];
    const float* We0   = (const float*)d_in[4];
    const float* be0   = (const float*)d_in[5];
    const float* We1   = (const float*)d_in[6];
    const float* be1   = (const float*)d_in[7];
    const float* Wv0   = (const float*)d_in[8];
    const float* Wlw   = (const float*)d_in[9];
    const float* Wlsh  = (const float*)d_in[10];
    const float* Wly1  = (const float*)d_in[11];
    const float* bly1  = (const float*)d_in[12];
    const float* Wly2  = (const float*)d_in[13];
    const float* bly2  = (const float*)d_in[14];
    const float* Wout  = (const float*)d_in[15];
    float* out = (float*)d_out;

    float *featp, *uu, *Y, *x, *s16, *w16, *V0, *VV0p, *wY, *Bt;
    cudaGetSymbolAddress((void**)&featp, g_featp);
    cudaGetSymbolAddress((void**)&uu,    g_u);
    cudaGetSymbolAddress((void**)&Y,     g_Y);
    cudaGetSymbolAddress((void**)&x,     g_x);
    cudaGetSymbolAddress((void**)&s16,   g_s16);
    cudaGetSymbolAddress((void**)&w16,   g_w16);
    cudaGetSymbolAddress((void**)&V0,    g_V0);
    cudaGetSymbolAddress((void**)&VV0p,  g_VV0p);
    cudaGetSymbolAddress((void**)&wY,    g_wY);
    cudaGetSymbolAddress((void**)&Bt,    g_Bt);

    // warp-coalesced weight regions, sizes 256*Kp floats
    float* Bt_e0  = Bt + 0;        // Kp=64
    float* Bt_e1  = Bt + 16384;    // Kp=256
    float* Bt_l10 = Bt + 81920;    // Kp=288
    float* Bt_l11 = Bt + 155648;   // Kp=288
    float* Bt_l20 = Bt + 229376;   // Kp=256
    float* Bt_l21 = Bt + 294912;   // Kp=256

    const int FSM_BYTES = FSM_FLOATS * 4;   // 69632
    cudaFuncSetAttribute(fgemm<2>, cudaFuncAttributeMaxDynamicSharedMemorySize, FSM_BYTES);
    cudaFuncSetAttribute(fgemm<3>, cudaFuncAttributeMaxDynamicSharedMemorySize, FSM_BYTES);
    cudaFuncSetAttribute(fgemm<4>, cudaFuncAttributeMaxDynamicSharedMemorySize, FSM_BYTES);

    const int GB = EE / 64;   // 2048 CTAs

    k_geom<<<EE / 256, 256>>>(vec, attrs, snd, rcv, featp, uu, Y);               // 0
    k_wprep3<<<64 + 256 + 288, 256>>>(We0, Bt_e0, 40, 64,                        // 1
                                      We1, Bt_e1, 256, 256,
                                      Wly1, Bt_l10, 272, 288);
    k_wprep3<<<288 + 256 + 256, 256>>>(Wly1 + 272 * 256, Bt_l11, 272, 288,      // 2
                                       Wly2, Bt_l20, 256, 256,
                                       Wly2 + 256 * 256, Bt_l21, 256, 256);

    // e0 -> e1 fused                                                            // 3
    fgemm<2><<<GB, 256, FSM_BYTES>>>(featp, 64, 2, nullptr,
                                     Bt_e0, 2, be0,
                                     Bt_e1, be1, uu, x,
                                     nullptr, nullptr, nullptr);

    // ---- layer 0 ----
    k_zero4<<<(NN * 256 / 4 + 255) / 256, 256>>>((float4*)wY, NN * 256 / 4);
    gemm_n16_dual<<<EE / 128, 128>>>(x, Wv0, Wlw, s16, w16);
    k_scatter<<<EE * 16 / 256, 256>>>(w16, Y, snd, wY);
    k_update0<<<EE * 16 / 256, 256>>>(snd, wY, s16, Y, V0, VV0p, Wlsh);
    fgemm<3><<<GB, 256, FSM_BYTES>>>(x, 256, 8, VV0p,
                                     Bt_l10, 9, bly1,
                                     Bt_l20, bly2, uu, x,
                                     nullptr, nullptr, nullptr);

    // ---- layer 1 ----
    gemm_n16<<<EE / 128, 128>>>(x, Wlw + 256 * 16, w16);
    k_zero4<<<(NN * 256 / 4 + 255) / 256, 256>>>((float4*)wY, NN * 256 / 4);
    k_scatter<<<EE * 16 / 256, 256>>>(w16, Y, snd, wY);
    k_update1<<<EE * 16 / 256, 256>>>(snd, wY, V0, VV0p);
    k_zero4<<<(NN / 4 + 255) / 256, 256>>>((float4*)out, NN / 4);
    fgemm<4><<<GB, 256, FSM_BYTES>>>(x, 256, 8, VV0p,
                                     Bt_l11, 9, bly1 + 256,
                                     Bt_l21, bly2 + 256, uu, x,
                                     Wout, rcv, out);
}

// round 15
// speedup vs baseline: 3.2218x; 1.2334x over previous
#include <cuda_runtime.h>
#include <cuda_fp16.h>
#include <math.h>
#include <cstdint>

#define NN 8192
#define EE 131072

// ---------------- scratch (device globals; no allocations allowed) ----------------
__device__ __align__(16) __half g_feath[EE * 64];  // fp16 bessel+attrs, K 40->64
__device__ __align__(16) float  g_u[EE];
__device__ __align__(16) float  g_Y[EE * 16];
__device__ __align__(16) float  g_x[EE * 256];     // fp32 x (residual + n16 gemms)
__device__ __align__(16) __half g_xh[EE * 256];    // fp16 shadow of x (MMA operand)
__device__ __align__(16) float  g_s16[EE * 16];
__device__ __align__(16) float  g_w16[EE * 16];
__device__ __align__(16) float  g_V0[EE * 16];
__device__ __align__(16) __half g_VV0ph[EE * 32];  // fp16 VV0, padded 16->32
__device__ __align__(16) float  g_wY[NN * 256];
__device__ __align__(16) __half g_Bt[360448];      // lane-major packed fp16 weights

// ---------------- helpers ----------------
__device__ __forceinline__ uint32_t smem_u32(const void* p) {
    uint32_t a;
    asm("{ .reg .u64 t; cvta.to.shared.u64 t, %1; cvt.u32.u64 %0, t; }" : "=r"(a) : "l"(p));
    return a;
}
__device__ __forceinline__ void cp16(uint32_t dst, const void* src) {
    asm volatile("cp.async.cg.shared.global [%0], [%1], 16;" :: "r"(dst), "l"(src));
}
#define CP_COMMIT() asm volatile("cp.async.commit_group;" ::: "memory")
#define CP_WAIT(n)  asm volatile("cp.async.wait_group %0;" :: "n"(n) : "memory")

__device__ __forceinline__ void mma16(float* d, const uint32_t* a, const uint32_t* b) {
    asm volatile(
        "mma.sync.aligned.m16n8k16.row.col.f32.f16.f16.f32 "
        "{%0,%1,%2,%3}, {%4,%5,%6,%7}, {%8,%9}, {%0,%1,%2,%3};"
        : "+f"(d[0]), "+f"(d[1]), "+f"(d[2]), "+f"(d[3])
        : "r"(a[0]), "r"(a[1]), "r"(a[2]), "r"(a[3]), "r"(b[0]), "r"(b[1]));
}

__device__ __forceinline__ void red4(float* p, float a, float b, float c, float d) {
    asm volatile("red.global.add.v4.f32 [%0], {%1, %2, %3, %4};"
                 :: "l"(p), "f"(a), "f"(b), "f"(c), "f"(d) : "memory");
}

__device__ __forceinline__ uint32_t packh2(float a, float b) {
    __half2 h = __floats2half2_rn(a, b);
    return *(uint32_t*)&h;
}

__device__ __forceinline__ float silu_f(float t) { return t / (1.0f + __expf(-t)); }

// smem layout (32-bit words):
//   A stages: 3 x 64 rows x 20 words (row = 32 halfs data + pad)   [0, 3840)
//   TQ: 64 kq x 34 quads x 4 words                                  [3840, 12544)
static constexpr int AW = 20;                      // A stage row stride (words)
static constexpr int STGA_W = 64 * AW;             // 1280
static constexpr int TQ_W = 3 * STGA_W;            // 3840
static constexpr int TQP = 34;                     // quads per kq row
static constexpr int FSM_BYTES = (TQ_W + 64 * TQP * 4) * 4;   // 50176

// ---------------- fused GEMM pair, fp16 MMA, M-tile 64, 256 thr, 2 CTAs/SM ---------
// GEMM1: T = silu(A[E,K1] @ B1 + bias1)  -> TQ (fp16 quad layout, smem)
// GEMM2: per EPI on  T @ B2 + bias2  (K=256); B via coalesced LDG.64 (L2)
// EPI: 2 = C/Ch = u*silu,  3 = C/Ch = (C + u*silu)/sqrt(2),
//      4 = no write; out[rcv[row]] += dot((C+u*silu)/sqrt2, Wout)*u*inv
template<int EPI>
__global__ __launch_bounds__(256, 2) void fgemm(
    const __half* __restrict__ A1, int sA1, int ntA1,
    const __half* __restrict__ A2,
    const uint2* __restrict__ B1, int nt1,
    const float* __restrict__ bias1,
    const uint2* __restrict__ B2,
    const float* __restrict__ bias2,
    const float* __restrict__ u, float* __restrict__ C, __half* __restrict__ Ch,
    const float* __restrict__ Wout, const int* __restrict__ rcv,
    float* __restrict__ out)
{
    extern __shared__ uint32_t smw[];
    uint32_t sb = smem_u32(smw);
    int tid = threadIdx.x, lane = tid & 31, wid = tid >> 5;
    int t3 = lane & 3, r1 = lane >> 2;
    int warp_n = wid;                 // 1 x 8 warp grid, 64x32 warp tile
    int rowBase = blockIdx.x * 64;

    auto load_A = [&](int kt, int buf) {
        uint32_t stBase = sb + buf * STGA_W * 4;
        const __half* Ap;
        int strideH;
        if (kt < ntA1) { Ap = A1 + (size_t)rowBase * sA1 + kt * 32; strideH = sA1; }
        else           { Ap = A2 + (size_t)rowBase * 32;            strideH = 32;  }
        int r = tid >> 2, q = tid & 3;
        cp16(stBase + (r * AW + q * 4) * 4, Ap + (size_t)r * strideH + q * 8);
        CP_COMMIT();
    };

    float acc[4][4][4];
    auto zero_acc = [&]() {
        #pragma unroll
        for (int i = 0; i < 4; i++)
            #pragma unroll
            for (int j = 0; j < 4; j++)
                #pragma unroll
                for (int q = 0; q < 4; q++) acc[i][j][q] = 0.f;
    };

    // ================= GEMM1 (A staged fp16, B coalesced LDG.64) =================
    zero_acc();
    load_A(0, 0);
    if (nt1 > 1) load_A(1, 1);
    for (int kt = 0; kt < nt1; kt++) {
        if (kt + 1 < nt1) CP_WAIT(1); else CP_WAIT(0);
        __syncthreads();
        if (kt + 2 < nt1) load_A(kt + 2, (kt + 2) % 3);
        const uint32_t* As = smw + (kt % 3) * STGA_W;
        #pragma unroll
        for (int s = 0; s < 2; s++) {
            uint32_t a[4][4];
            uint2 bq[4];
            int bidx = ((kt * 2 + s) * 8 + warp_n) * 128 + lane;
            #pragma unroll
            for (int j = 0; j < 4; j++) bq[j] = __ldg(&B1[bidx + j * 32]);
            int cw = s * 8 + t3;
            #pragma unroll
            for (int i = 0; i < 4; i++) {
                int rb = i * 16 + r1;
                a[i][0] = As[rb * AW + cw];
                a[i][1] = As[(rb + 8) * AW + cw];
                a[i][2] = As[rb * AW + cw + 4];
                a[i][3] = As[(rb + 8) * AW + cw + 4];
            }
            #pragma unroll
            for (int i = 0; i < 4; i++)
                #pragma unroll
                for (int j = 0; j < 4; j++)
                    mma16(acc[i][j], a[i], (const uint32_t*)&bq[j]);
        }
    }

    // GEMM1 epilogue: silu+bias -> TQ fp16 quads (thread-local pack, no shuffles)
    #pragma unroll
    for (int i = 0; i < 4; i++) {
        int p = i * 8 + r1;
        #pragma unroll
        for (int jp = 0; jp < 2; jp++) {
            int j0 = 2 * jp;
            int col0 = warp_n * 32 + j0 * 8 + 2 * t3;       // low-k fragment
            int col1 = col0 + 8;                            // high-k fragment
            float b00 = __ldg(bias1 + col0), b01 = __ldg(bias1 + col0 + 1);
            float b10 = __ldg(bias1 + col1), b11 = __ldg(bias1 + col1 + 1);
            uint4 v;
            v.x = packh2(silu_f(acc[i][j0][0] + b00),  silu_f(acc[i][j0][1] + b01));
            v.y = packh2(silu_f(acc[i][j0][2] + b00),  silu_f(acc[i][j0][3] + b01));
            v.z = packh2(silu_f(acc[i][j0+1][0] + b10), silu_f(acc[i][j0+1][1] + b11));
            v.w = packh2(silu_f(acc[i][j0+1][2] + b10), silu_f(acc[i][j0+1][3] + b11));
            int kq = (warp_n * 2 + jp) * 4 + t3;
            *(uint4*)&smw[TQ_W + (kq * TQP + p) * 4] = v;
        }
    }
    __syncthreads();

    // ================= GEMM2 (A = TQ quads LDS.128, B prefetch LDG.64) ==========
    zero_acc();
    {
        uint2 bq[4], bqn[4];
        int bi0 = warp_n * 128 + lane;
        #pragma unroll
        for (int j = 0; j < 4; j++) bq[j] = __ldg(&B2[bi0 + j * 32]);
        for (int ss = 0; ss < 16; ss++) {
            if (ss + 1 < 16) {
                int bn = ((ss + 1) * 8 + warp_n) * 128 + lane;
                #pragma unroll
                for (int j = 0; j < 4; j++) bqn[j] = __ldg(&B2[bn + j * 32]);
            }
            uint4 aq[4];
            int kq = ss * 4 + t3;
            #pragma unroll
            for (int i = 0; i < 4; i++)
                aq[i] = *(const uint4*)&smw[TQ_W + (kq * TQP + i * 8 + r1) * 4];
            #pragma unroll
            for (int i = 0; i < 4; i++)
                #pragma unroll
                for (int j = 0; j < 4; j++)
                    mma16(acc[i][j], (const uint32_t*)&aq[i], (const uint32_t*)&bq[j]);
            #pragma unroll
            for (int j = 0; j < 4; j++) bq[j] = bqn[j];
        }
    }

    // ---- final epilogue ----
    const float RS2 = 0.7071067811865476f;
    float wo0[4], wo1[4];
    if (EPI == 4) {
        #pragma unroll
        for (int j = 0; j < 4; j++) {
            int col = warp_n * 32 + j * 8 + 2 * t3;
            wo0[j] = __ldg(Wout + col);
            wo1[j] = __ldg(Wout + col + 1);
        }
    }
    #pragma unroll
    for (int i = 0; i < 4; i++) {
        int ra = rowBase + i * 16 + r1;
        int rb = ra + 8;
        float ua = u[ra], ub = u[rb];
        float pa = 0.f, pb = 0.f;
        #pragma unroll
        for (int j = 0; j < 4; j++) {
            int col = warp_n * 32 + j * 8 + 2 * t3;
            float b0 = __ldg(bias2 + col), b1 = __ldg(bias2 + col + 1);
            float o0 = ua * silu_f(acc[i][j][0] + b0);
            float o1 = ua * silu_f(acc[i][j][1] + b1);
            float o2 = ub * silu_f(acc[i][j][2] + b0);
            float o3 = ub * silu_f(acc[i][j][3] + b1);
            if (EPI == 2) {
                *(float2*)(C + (size_t)ra * 256 + col) = make_float2(o0, o1);
                *(float2*)(C + (size_t)rb * 256 + col) = make_float2(o2, o3);
                *(uint32_t*)(Ch + (size_t)ra * 256 + col) = packh2(o0, o1);
                *(uint32_t*)(Ch + (size_t)rb * 256 + col) = packh2(o2, o3);
            } else {
                float2 oa = *(const float2*)(C + (size_t)ra * 256 + col);
                float2 ob = *(const float2*)(C + (size_t)rb * 256 + col);
                o0 = (oa.x + o0) * RS2; o1 = (oa.y + o1) * RS2;
                o2 = (ob.x + o2) * RS2; o3 = (ob.y + o3) * RS2;
                if (EPI == 3) {
                    *(float2*)(C + (size_t)ra * 256 + col) = make_float2(o0, o1);
                    *(float2*)(C + (size_t)rb * 256 + col) = make_float2(o2, o3);
                    *(uint32_t*)(Ch + (size_t)ra * 256 + col) = packh2(o0, o1);
                    *(uint32_t*)(Ch + (size_t)rb * 256 + col) = packh2(o2, o3);
                } else {
                    pa += o0 * wo0[j] + o1 * wo1[j];
                    pb += o2 * wo0[j] + o3 * wo1[j];
                }
            }
        }
        if (EPI == 4) {
            pa += __shfl_xor_sync(0xffffffffu, pa, 1);
            pa += __shfl_xor_sync(0xffffffffu, pa, 2);
            pb += __shfl_xor_sync(0xffffffffu, pb, 1);
            pb += __shfl_xor_sync(0xffffffffu, pb, 2);
            if (t3 == 0) {
                atomicAdd(out + __ldg(rcv + ra), pa * ua * 0.25f);
                atomicAdd(out + __ldg(rcv + rb), pb * ub * 0.25f);
            }
        }
    }
}

// ---------------- weight prep: transpose + fp16 + lane-major uint2 packing ----------
// half index f: u2 = f>>2, q = f&3; lane = u2&31, j = (u2>>5)&3, nb = (u2>>7)&7,
// ks = u2>>10;  n = nb*32 + j*8 + (lane>>2);  k = ks*16 + 2*(lane&3) + (q&1) + 8*(q>>1)
__global__ void k_wprep3(const float* __restrict__ W0, __half* __restrict__ d0, int K0, int Kp0,
                         const float* __restrict__ W1, __half* __restrict__ d1, int K1, int Kp1,
                         const float* __restrict__ W2, __half* __restrict__ d2, int K2, int Kp2)
{
    int b = blockIdx.x;
    const float* W; __half* d; int K, Kp, rb;
    if (b < Kp0)            { W = W0; d = d0; K = K0; Kp = Kp0; rb = b; }
    else if (b < Kp0 + Kp1) { W = W1; d = d1; K = K1; Kp = Kp1; rb = b - Kp0; }
    else                    { W = W2; d = d2; K = K2; Kp = Kp2; rb = b - Kp0 - Kp1; }
    int f = rb * 256 + threadIdx.x;        // over 256*Kp halfs
    int u2 = f >> 2, q = f & 3;
    int ln = u2 & 31, jj = (u2 >> 5) & 3, nb = (u2 >> 7) & 7, ks = u2 >> 10;
    int n = nb * 32 + jj * 8 + (ln >> 2);
    int k = ks * 16 + 2 * (ln & 3) + (q & 1) + 8 * (q >> 1);
    d[f] = __float2half((k < K) ? W[(size_t)k * 256 + n] : 0.f);
}

// ---------------- geometry (writes fp16 features) ----------------
__global__ void k_geom(const float* __restrict__ vec, const float* __restrict__ attrs,
                       const int* __restrict__ snd, const int* __restrict__ rcv,
                       __half* __restrict__ feat, float* __restrict__ uo, float* __restrict__ Yo)
{
    int e = blockIdx.x * blockDim.x + threadIdx.x;
    if (e >= EE) return;
    float vx = vec[3*e+0], vy = vec[3*e+1], vz = vec[3*e+2];
    float d2 = vx*vx + vy*vy + vz*vz;
    float d  = sqrtf(d2);
    float d6 = d2 * d2 * d2;
    float env = 1.0f + d6 * (-28.0f + d * (48.0f - 21.0f * d));
    uo[e] = env;
    float invd = 1.0f / d;
    const float S2 = 1.4142135623730951f;
    __half2* hp = (__half2*)(feat + (size_t)e * 64);
    float bs[8];
    #pragma unroll
    for (int k = 1; k <= 8; k++)
        bs[k-1] = S2 * sinpif((float)k * d) * invd;
    #pragma unroll
    for (int q = 0; q < 4; q++)
        hp[q] = __floats2half2_rn(bs[2*q], bs[2*q+1]);
    int s = snd[e], r = rcv[e];
    #pragma unroll
    for (int i = 0; i < 8; i++)
        hp[4 + i] = __floats2half2_rn(attrs[s*16 + 2*i], attrs[s*16 + 2*i + 1]);
    #pragma unroll
    for (int i = 0; i < 8; i++)
        hp[12 + i] = __floats2half2_rn(attrs[r*16 + 2*i], attrs[r*16 + 2*i + 1]);
    #pragma unroll
    for (int i = 20; i < 32; i++) hp[i] = __floats2half2_rn(0.f, 0.f);

    float x = vx*invd, y = vy*invd, z = vz*invd;
    const float s3  = 1.7320508075688772f;
    const float s5  = 2.2360679774997896f;
    const float s15 = 3.8729833462074170f;
    const float s7  = 2.6457513110645907f;
    const float c33 = 2.0916500663351885f;
    const float c32 = 10.246950765959598f;
    const float c31 = 1.6201851746019649f;
    float* Yp = Yo + (size_t)e * 16;
    Yp[0]  = 1.0f;
    Yp[1]  = s3 * x;  Yp[2]  = s3 * y;  Yp[3]  = s3 * z;
    Yp[4]  = s15 * x * y;  Yp[5]  = s15 * y * z;
    Yp[6]  = 0.5f * s5 * (3.0f*z*z - 1.0f);
    Yp[7]  = s15 * x * z;
    Yp[8]  = 0.5f * s15 * (x*x - y*y);
    Yp[9]  = c33 * y * (3.0f*x*x - y*y);
    Yp[10] = c32 * x * y * z;
    Yp[11] = c31 * y * (5.0f*z*z - 1.0f);
    Yp[12] = 0.5f * s7 * (5.0f*z*z*z - 3.0f*z);
    Yp[13] = c31 * x * (5.0f*z*z - 1.0f);
    Yp[14] = 0.5f * c32 * z * (x*x - y*y);
    Yp[15] = c33 * x * (x*x - 3.0f*y*y);
}

// ---------------- (E,256) @ (256,16) x2 sharing one x read ----------
__global__ __launch_bounds__(128) void gemm_n16_dual(const float* __restrict__ X,
                                                     const float* __restrict__ Wa,
                                                     const float* __restrict__ Wb,
                                                     float* __restrict__ Sa,
                                                     float* __restrict__ Sb)
{
    __shared__ __align__(16) float Ws[8192];
    int tid = threadIdx.x;
    #pragma unroll
    for (int i = 0; i < 8; i++)
        ((float4*)Ws)[tid + i * 128] = ((const float4*)Wa)[tid + i * 128];
    #pragma unroll
    for (int i = 0; i < 8; i++)
        ((float4*)(Ws + 4096))[tid + i * 128] = ((const float4*)Wb)[tid + i * 128];
    __syncthreads();
    size_t e = (size_t)blockIdx.x * 128 + tid;
    const float4* xr = (const float4*)(X + e * 256);
    float acca[16], accb[16];
    #pragma unroll
    for (int c = 0; c < 16; c++) { acca[c] = 0.f; accb[c] = 0.f; }
    #pragma unroll 2
    for (int k4 = 0; k4 < 64; k4++) {
        float4 xv = xr[k4];
        float xs[4] = {xv.x, xv.y, xv.z, xv.w};
        #pragma unroll
        for (int j = 0; j < 4; j++) {
            const float4* wra = (const float4*)&Ws[(k4 * 4 + j) * 16];
            const float4* wrb = (const float4*)&Ws[4096 + (k4 * 4 + j) * 16];
            #pragma unroll
            for (int q = 0; q < 4; q++) {
                float4 wa = wra[q], wb = wrb[q];
                acca[q*4+0] += xs[j] * wa.x;  accb[q*4+0] += xs[j] * wb.x;
                acca[q*4+1] += xs[j] * wa.y;  accb[q*4+1] += xs[j] * wb.y;
                acca[q*4+2] += xs[j] * wa.z;  accb[q*4+2] += xs[j] * wb.z;
                acca[q*4+3] += xs[j] * wa.w;  accb[q*4+3] += xs[j] * wb.w;
            }
        }
    }
    float4* spa = (float4*)(Sa + e * 16);
    float4* spb = (float4*)(Sb + e * 16);
    #pragma unroll
    for (int q = 0; q < 4; q++) {
        spa[q] = make_float4(acca[q*4], acca[q*4+1], acca[q*4+2], acca[q*4+3]);
        spb[q] = make_float4(accb[q*4], accb[q*4+1], accb[q*4+2], accb[q*4+3]);
    }
}

// ---------------- single-output N=16 GEMM (layer-1 w) ----------------
__global__ __launch_bounds__(128) void gemm_n16(const float* __restrict__ X,
                                                const float* __restrict__ W,
                                                float* __restrict__ S)
{
    __shared__ __align__(16) float Ws[4096];
    int tid = threadIdx.x;
    #pragma unroll
    for (int i = 0; i < 8; i++)
        ((float4*)Ws)[tid + i * 128] = ((const float4*)W)[tid + i * 128];
    __syncthreads();
    size_t e = (size_t)blockIdx.x * 128 + tid;
    const float4* xr = (const float4*)(X + e * 256);
    float acc[16];
    #pragma unroll
    for (int c = 0; c < 16; c++) acc[c] = 0.f;
    #pragma unroll 4
    for (int k4 = 0; k4 < 64; k4++) {
        float4 xv = xr[k4];
        float xs[4] = {xv.x, xv.y, xv.z, xv.w};
        #pragma unroll
        for (int j = 0; j < 4; j++) {
            const float4* wr = (const float4*)&Ws[(k4 * 4 + j) * 16];
            #pragma unroll
            for (int q = 0; q < 4; q++) {
                float4 w = wr[q];
                acc[q*4+0] += xs[j] * w.x;
                acc[q*4+1] += xs[j] * w.y;
                acc[q*4+2] += xs[j] * w.z;
                acc[q*4+3] += xs[j] * w.w;
            }
        }
    }
    float4* sp = (float4*)(S + e * 16);
    #pragma unroll
    for (int q = 0; q < 4; q++)
        sp[q] = make_float4(acc[q*4], acc[q*4+1], acc[q*4+2], acc[q*4+3]);
}

__global__ void k_zero4(float4* p, int n4)
{
    int i = blockIdx.x * blockDim.x + threadIdx.x;
    if (i < n4) p[i] = make_float4(0.f, 0.f, 0.f, 0.f);
}

// ---------------- segment_sum scatter: vector reds ----------
__global__ void k_scatter(const float* __restrict__ w, const float* __restrict__ Y,
                          const int* __restrict__ snd, float* __restrict__ wY)
{
    int idx = blockIdx.x * blockDim.x + threadIdx.x;   // e*16 + m
    int e = idx >> 4, m = idx & 15;
    float wv = w[idx];
    int s = snd[e];
    float* base = wY + (size_t)s * 256 + m * 16;
    const float4* Y4 = (const float4*)(Y + (size_t)e * 16);
    #pragma unroll
    for (int q = 0; q < 4; q++) {
        float4 y = Y4[q];
        red4(base + q * 4, wv * y.x, wv * y.y, wv * y.z, wv * y.w);
    }
}

// ---------------- layer-0 update (fp16 VV0 out) ----------------
__global__ __launch_bounds__(256)
void k_update0(const int* __restrict__ snd, const float* __restrict__ wY,
               const float* __restrict__ s16, const float* __restrict__ Y,
               float* __restrict__ V0, __half* __restrict__ VV0ph,
               const float* __restrict__ Wlsh)
{
    __shared__ float Wcol0[16];
    int tid = threadIdx.x;
    if (tid < 16) Wcol0[tid] = Wlsh[tid * 16];
    __syncthreads();
    int idx = blockIdx.x * 256 + tid;
    int e = idx >> 4, m = idx & 15;
    int s = snd[e];
    float xv = s16[idx];
    const float4* wyp = (const float4*)(wY + (size_t)s * 256 + m * 16);
    const float4* yp  = (const float4*)(Y + (size_t)e * 16);
    float vv[16];
    #pragma unroll
    for (int q = 0; q < 4; q++) {
        float4 a = wyp[q];
        float4 y = yp[q];
        vv[q*4+0] = 0.25f * a.x * xv * y.x;
        vv[q*4+1] = 0.25f * a.y * xv * y.y;
        vv[q*4+2] = 0.25f * a.z * xv * y.z;
        vv[q*4+3] = 0.25f * a.w * xv * y.w;
    }
    VV0ph[(size_t)e * 32 + m] = __float2half(vv[0]);
    VV0ph[(size_t)e * 32 + 16 + m] = __float2half(0.f);
    float o0 = 0.f;
    #pragma unroll
    for (int i = 0; i < 16; i++) o0 += vv[i] * Wcol0[i];
    V0[idx] = o0;
}

// ---------------- layer-1 update ----------------
__global__ __launch_bounds__(256)
void k_update1(const int* __restrict__ snd, const float* __restrict__ wY,
               const float* __restrict__ V0, __half* __restrict__ VV0ph)
{
    int idx = blockIdx.x * 256 + threadIdx.x;
    int e = idx >> 4, m = idx & 15;
    int s = snd[e];
    float wy0 = wY[(size_t)s * 256 + m * 16];
    VV0ph[(size_t)e * 32 + m] = __float2half(0.25f * wy0 * V0[idx]);
    VV0ph[(size_t)e * 32 + 16 + m] = __float2half(0.f);
}

// ---------------- host ----------------
extern "C" void kernel_launch(void* const* d_in, const int* in_sizes, int n_in,
                              void* d_out, int out_size)
{
    const float* attrs = (const float*)d_in[0];
    const float* vec   = (const float*)d_in[1];
    const int*   snd   = (const int*)d_in[2];
    const int*   rcv   = (const int*)d_in[3];
    const float* We0   = (const float*)d_in[4];
    const float* be0   = (const float*)d_in[5];
    const float* We1   = (const float*)d_in[6];
    const float* be1   = (const float*)d_in[7];
    const float* Wv0   = (const float*)d_in[8];
    const float* Wlw   = (const float*)d_in[9];
    const float* Wlsh  = (const float*)d_in[10];
    const float* Wly1  = (const float*)d_in[11];
    const float* bly1  = (const float*)d_in[12];
    const float* Wly2  = (const float*)d_in[13];
    const float* bly2  = (const float*)d_in[14];
    const float* Wout  = (const float*)d_in[15];
    float* out = (float*)d_out;

    __half *feath, *xh, *VV0ph, *Bt;
    float *uu, *Y, *x, *s16, *w16, *V0, *wY;
    cudaGetSymbolAddress((void**)&feath, g_feath);
    cudaGetSymbolAddress((void**)&uu,    g_u);
    cudaGetSymbolAddress((void**)&Y,     g_Y);
    cudaGetSymbolAddress((void**)&x,     g_x);
    cudaGetSymbolAddress((void**)&xh,    g_xh);
    cudaGetSymbolAddress((void**)&s16,   g_s16);
    cudaGetSymbolAddress((void**)&w16,   g_w16);
    cudaGetSymbolAddress((void**)&V0,    g_V0);
    cudaGetSymbolAddress((void**)&VV0ph, g_VV0ph);
    cudaGetSymbolAddress((void**)&wY,    g_wY);
    cudaGetSymbolAddress((void**)&Bt,    g_Bt);

    // packed fp16 weight regions, sizes 256*Kp halfs
    __half* Bt_e0  = Bt + 0;        // Kp=64
    __half* Bt_e1  = Bt + 16384;    // Kp=256
    __half* Bt_l10 = Bt + 81920;    // Kp=288
    __half* Bt_l11 = Bt + 155648;   // Kp=288
    __half* Bt_l20 = Bt + 229376;   // Kp=256
    __half* Bt_l21 = Bt + 294912;   // Kp=256

    cudaFuncSetAttribute(fgemm<2>, cudaFuncAttributeMaxDynamicSharedMemorySize, FSM_BYTES);
    cudaFuncSetAttribute(fgemm<3>, cudaFuncAttributeMaxDynamicSharedMemorySize, FSM_BYTES);
    cudaFuncSetAttribute(fgemm<4>, cudaFuncAttributeMaxDynamicSharedMemorySize, FSM_BYTES);

    const int GB = EE / 64;   // 2048 CTAs

    k_geom<<<EE / 256, 256>>>(vec, attrs, snd, rcv, feath, uu, Y);               // 0
    k_wprep3<<<64 + 256 + 288, 256>>>(We0, Bt_e0, 40, 64,                        // 1
                                      We1, Bt_e1, 256, 256,
                                      Wly1, Bt_l10, 272, 288);
    k_wprep3<<<288 + 256 + 256, 256>>>(Wly1 + 272 * 256, Bt_l11, 272, 288,      // 2
                                       Wly2, Bt_l20, 256, 256,
                                       Wly2 + 256 * 256, Bt_l21, 256, 256);

    // e0 -> e1 fused                                                            // 3
    fgemm<2><<<GB, 256, FSM_BYTES>>>(feath, 64, 2, nullptr,
                                     (const uint2*)Bt_e0, 2, be0,
                                     (const uint2*)Bt_e1, be1, uu, x, xh,
                                     nullptr, nullptr, nullptr);

    // ---- layer 0 ----
    k_zero4<<<(NN * 256 / 4 + 255) / 256, 256>>>((float4*)wY, NN * 256 / 4);
    gemm_n16_dual<<<EE / 128, 128>>>(x, Wv0, Wlw, s16, w16);
    k_scatter<<<EE * 16 / 256, 256>>>(w16, Y, snd, wY);
    k_update0<<<EE * 16 / 256, 256>>>(snd, wY, s16, Y, V0, VV0ph, Wlsh);
    fgemm<3><<<GB, 256, FSM_BYTES>>>(xh, 256, 8, VV0ph,
                                     (const uint2*)Bt_l10, 9, bly1,
                                     (const uint2*)Bt_l20, bly2, uu, x, xh,
                                     nullptr, nullptr, nullptr);

    // ---- layer 1 ----
    gemm_n16<<<EE / 128, 128>>>(x, Wlw + 256 * 16, w16);
    k_zero4<<<(NN * 256 / 4 + 255) / 256, 256>>>((float4*)wY, NN * 256 / 4);
    k_scatter<<<EE * 16 / 256, 256>>>(w16, Y, snd, wY);
    k_update1<<<EE * 16 / 256, 256>>>(snd, wY, V0, VV0ph);
    k_zero4<<<(NN / 4 + 255) / 256, 256>>>((float4*)out, NN / 4);
    fgemm<4><<<GB, 256, FSM_BYTES>>>(xh, 256, 8, VV0ph,
                                     (const uint2*)Bt_l11, 9, bly1 + 256,
                                     (const uint2*)Bt_l21, bly2 + 256, uu, x, nullptr,
                                     Wout, rcv, out);
}

// round 17
// speedup vs baseline: 3.3961x; 1.0541x over previous
#include <cuda_runtime.h>
#include <cuda_fp16.h>
#include <math.h>
#include <cstdint>

#define NN 8192
#define EE 131072

// ---------------- scratch (device globals; no allocations allowed) ----------------
__device__ __align__(16) __half g_feath[EE * 64];  // fp16 bessel+attrs, K 40->64
__device__ __align__(16) float  g_u[EE];
__device__ __align__(16) float  g_Y[EE * 16];
__device__ __align__(16) __half g_xh[EE * 256];    // fp16 x (sole representation)
__device__ __align__(16) float  g_s16[EE * 16];
__device__ __align__(16) float  g_w16[EE * 16];
__device__ __align__(16) float  g_V0[EE * 16];
__device__ __align__(16) __half g_VV0ph[EE * 32];  // fp16 VV0, padded 16->32
__device__ __align__(16) float  g_wY[NN * 256];
__device__ __align__(16) __half g_Bt[360448];      // lane-major packed fp16 weights

// ---------------- helpers ----------------
__device__ __forceinline__ uint32_t smem_u32(const void* p) {
    uint32_t a;
    asm("{ .reg .u64 t; cvta.to.shared.u64 t, %1; cvt.u32.u64 %0, t; }" : "=r"(a) : "l"(p));
    return a;
}
__device__ __forceinline__ void cp16(uint32_t dst, const void* src) {
    asm volatile("cp.async.cg.shared.global [%0], [%1], 16;" :: "r"(dst), "l"(src));
}
#define CP_COMMIT() asm volatile("cp.async.commit_group;" ::: "memory")
#define CP_WAIT(n)  asm volatile("cp.async.wait_group %0;" :: "n"(n) : "memory")

__device__ __forceinline__ void mma16(float* d, const uint32_t* a, const uint32_t* b) {
    asm volatile(
        "mma.sync.aligned.m16n8k16.row.col.f32.f16.f16.f32 "
        "{%0,%1,%2,%3}, {%4,%5,%6,%7}, {%8,%9}, {%0,%1,%2,%3};"
        : "+f"(d[0]), "+f"(d[1]), "+f"(d[2]), "+f"(d[3])
        : "r"(a[0]), "r"(a[1]), "r"(a[2]), "r"(a[3]), "r"(b[0]), "r"(b[1]));
}

__device__ __forceinline__ void red4(float* p, float a, float b, float c, float d) {
    asm volatile("red.global.add.v4.f32 [%0], {%1, %2, %3, %4};"
                 :: "l"(p), "f"(a), "f"(b), "f"(c), "f"(d) : "memory");
}

__device__ __forceinline__ uint32_t packh2(float a, float b) {
    __half2 h = __floats2half2_rn(a, b);
    return *(uint32_t*)&h;
}
__device__ __forceinline__ float2 unpackh2(uint32_t v) {
    return __half22float2(*(__half2*)&v);
}

__device__ __forceinline__ float silu_f(float t) { return t / (1.0f + __expf(-t)); }

// smem layout (32-bit words):
//   A stages: 3 x 64 rows x 20 words    [0, 3840)
//   TQ: 64 kq x 34 quads x 4 words      [3840, 12544)
static constexpr int AW = 20;
static constexpr int STGA_W = 64 * AW;             // 1280
static constexpr int TQ_W = 3 * STGA_W;            // 3840
static constexpr int TQP = 34;
static constexpr int FSM_BYTES = (TQ_W + 64 * TQP * 4) * 4;   // 50176

// ---------------- fused GEMM pair, fp16 MMA, M-tile 64, 256 thr, 2 CTAs/SM ---------
// GEMM1: T = silu(A[E,K1] @ B1 + bias1)  -> TQ (fp16 quad layout, smem)
// GEMM2: per EPI on  T @ B2 + bias2  (K=256); B via coalesced LDG.64 (L2)
// EPI: 2 = Ch = u*silu,  3 = Ch = (Ch + u*silu)/sqrt(2),
//      4 = no write; out[rcv[row]] += dot((Ch+u*silu)/sqrt2, Wout)*u*inv
template<int EPI>
__global__ __launch_bounds__(256, 2) void fgemm(
    const __half* __restrict__ A1, int sA1, int ntA1,
    const __half* __restrict__ A2,
    const uint2* __restrict__ B1, int nt1,
    const float* __restrict__ bias1,
    const uint2* __restrict__ B2,
    const float* __restrict__ bias2,
    const float* __restrict__ u, __half* __restrict__ Ch,
    const float* __restrict__ Wout, const int* __restrict__ rcv,
    float* __restrict__ out)
{
    extern __shared__ uint32_t smw[];
    uint32_t sb = smem_u32(smw);
    int tid = threadIdx.x, lane = tid & 31, wid = tid >> 5;
    int t3 = lane & 3, r1 = lane >> 2;
    int warp_n = wid;                 // 1 x 8 warp grid, 64x32 warp tile
    int rowBase = blockIdx.x * 64;

    auto load_A = [&](int kt, int buf) {
        uint32_t stBase = sb + buf * STGA_W * 4;
        const __half* Ap;
        int strideH;
        if (kt < ntA1) { Ap = A1 + (size_t)rowBase * sA1 + kt * 32; strideH = sA1; }
        else           { Ap = A2 + (size_t)rowBase * 32;            strideH = 32;  }
        int r = tid >> 2, q = tid & 3;
        cp16(stBase + (r * AW + q * 4) * 4, Ap + (size_t)r * strideH + q * 8);
        CP_COMMIT();
    };

    float acc[4][4][4];
    auto zero_acc = [&]() {
        #pragma unroll
        for (int i = 0; i < 4; i++)
            #pragma unroll
            for (int j = 0; j < 4; j++)
                #pragma unroll
                for (int q = 0; q < 4; q++) acc[i][j][q] = 0.f;
    };

    // ================= GEMM1 (A staged fp16, B coalesced LDG.64) =================
    zero_acc();
    load_A(0, 0);
    if (nt1 > 1) load_A(1, 1);
    for (int kt = 0; kt < nt1; kt++) {
        if (kt + 1 < nt1) CP_WAIT(1); else CP_WAIT(0);
        __syncthreads();
        if (kt + 2 < nt1) load_A(kt + 2, (kt + 2) % 3);
        const uint32_t* As = smw + (kt % 3) * STGA_W;
        #pragma unroll
        for (int s = 0; s < 2; s++) {
            uint32_t a[4][4];
            uint2 bq[4];
            int bidx = ((kt * 2 + s) * 8 + warp_n) * 128 + lane;
            #pragma unroll
            for (int j = 0; j < 4; j++) bq[j] = __ldg(&B1[bidx + j * 32]);
            int cw = s * 8 + t3;
            #pragma unroll
            for (int i = 0; i < 4; i++) {
                int rb = i * 16 + r1;
                a[i][0] = As[rb * AW + cw];
                a[i][1] = As[(rb + 8) * AW + cw];
                a[i][2] = As[rb * AW + cw + 4];
                a[i][3] = As[(rb + 8) * AW + cw + 4];
            }
            #pragma unroll
            for (int i = 0; i < 4; i++)
                #pragma unroll
                for (int j = 0; j < 4; j++)
                    mma16(acc[i][j], a[i], (const uint32_t*)&bq[j]);
        }
    }

    // GEMM1 epilogue: silu+bias -> TQ fp16 quads (thread-local pack, no shuffles)
    #pragma unroll
    for (int i = 0; i < 4; i++) {
        int p = i * 8 + r1;
        #pragma unroll
        for (int jp = 0; jp < 2; jp++) {
            int j0 = 2 * jp;
            int col0 = warp_n * 32 + j0 * 8 + 2 * t3;
            int col1 = col0 + 8;
            float b00 = __ldg(bias1 + col0), b01 = __ldg(bias1 + col0 + 1);
            float b10 = __ldg(bias1 + col1), b11 = __ldg(bias1 + col1 + 1);
            uint4 v;
            v.x = packh2(silu_f(acc[i][j0][0] + b00),  silu_f(acc[i][j0][1] + b01));
            v.y = packh2(silu_f(acc[i][j0][2] + b00),  silu_f(acc[i][j0][3] + b01));
            v.z = packh2(silu_f(acc[i][j0+1][0] + b10), silu_f(acc[i][j0+1][1] + b11));
            v.w = packh2(silu_f(acc[i][j0+1][2] + b10), silu_f(acc[i][j0+1][3] + b11));
            int kq = (warp_n * 2 + jp) * 4 + t3;
            *(uint4*)&smw[TQ_W + (kq * TQP + p) * 4] = v;
        }
    }
    __syncthreads();

    // ================= GEMM2 (A = TQ quads LDS.128, B prefetch LDG.64) ==========
    zero_acc();
    {
        uint2 bq[4], bqn[4];
        int bi0 = warp_n * 128 + lane;
        #pragma unroll
        for (int j = 0; j < 4; j++) bq[j] = __ldg(&B2[bi0 + j * 32]);
        for (int ss = 0; ss < 16; ss++) {
            if (ss + 1 < 16) {
                int bn = ((ss + 1) * 8 + warp_n) * 128 + lane;
                #pragma unroll
                for (int j = 0; j < 4; j++) bqn[j] = __ldg(&B2[bn + j * 32]);
            }
            uint4 aq[4];
            int kq = ss * 4 + t3;
            #pragma unroll
            for (int i = 0; i < 4; i++)
                aq[i] = *(const uint4*)&smw[TQ_W + (kq * TQP + i * 8 + r1) * 4];
            #pragma unroll
            for (int i = 0; i < 4; i++)
                #pragma unroll
                for (int j = 0; j < 4; j++)
                    mma16(acc[i][j], (const uint32_t*)&aq[i], (const uint32_t*)&bq[j]);
            #pragma unroll
            for (int j = 0; j < 4; j++) bq[j] = bqn[j];
        }
    }

    // ---- final epilogue (fp16 residual I/O) ----
    const float RS2 = 0.7071067811865476f;
    float wo0[4], wo1[4];
    if (EPI == 4) {
        #pragma unroll
        for (int j = 0; j < 4; j++) {
            int col = warp_n * 32 + j * 8 + 2 * t3;
            wo0[j] = __ldg(Wout + col);
            wo1[j] = __ldg(Wout + col + 1);
        }
    }
    #pragma unroll
    for (int i = 0; i < 4; i++) {
        int ra = rowBase + i * 16 + r1;
        int rb = ra + 8;
        float ua = u[ra], ub = u[rb];
        float pa = 0.f, pb = 0.f;
        #pragma unroll
        for (int j = 0; j < 4; j++) {
            int col = warp_n * 32 + j * 8 + 2 * t3;
            float b0 = __ldg(bias2 + col), b1 = __ldg(bias2 + col + 1);
            float o0 = ua * silu_f(acc[i][j][0] + b0);
            float o1 = ua * silu_f(acc[i][j][1] + b1);
            float o2 = ub * silu_f(acc[i][j][2] + b0);
            float o3 = ub * silu_f(acc[i][j][3] + b1);
            if (EPI == 2) {
                *(uint32_t*)(Ch + (size_t)ra * 256 + col) = packh2(o0, o1);
                *(uint32_t*)(Ch + (size_t)rb * 256 + col) = packh2(o2, o3);
            } else {
                float2 fa = unpackh2(*(const uint32_t*)(Ch + (size_t)ra * 256 + col));
                float2 fb = unpackh2(*(const uint32_t*)(Ch + (size_t)rb * 256 + col));
                o0 = (fa.x + o0) * RS2; o1 = (fa.y + o1) * RS2;
                o2 = (fb.x + o2) * RS2; o3 = (fb.y + o3) * RS2;
                if (EPI == 3) {
                    *(uint32_t*)(Ch + (size_t)ra * 256 + col) = packh2(o0, o1);
                    *(uint32_t*)(Ch + (size_t)rb * 256 + col) = packh2(o2, o3);
                } else {
                    pa += o0 * wo0[j] + o1 * wo1[j];
                    pb += o2 * wo0[j] + o3 * wo1[j];
                }
            }
        }
        if (EPI == 4) {
            pa += __shfl_xor_sync(0xffffffffu, pa, 1);
            pa += __shfl_xor_sync(0xffffffffu, pa, 2);
            pb += __shfl_xor_sync(0xffffffffu, pb, 1);
            pb += __shfl_xor_sync(0xffffffffu, pb, 2);
            if (t3 == 0) {
                atomicAdd(out + __ldg(rcv + ra), pa * ua * 0.25f);
                atomicAdd(out + __ldg(rcv + rb), pb * ub * 0.25f);
            }
        }
    }
}

// ---------------- weight prep: transpose + fp16 + lane-major uint2 packing ----------
__global__ void k_wprep3(const float* __restrict__ W0, __half* __restrict__ d0, int K0, int Kp0,
                         const float* __restrict__ W1, __half* __restrict__ d1, int K1, int Kp1,
                         const float* __restrict__ W2, __half* __restrict__ d2, int K2, int Kp2)
{
    int b = blockIdx.x;
    const float* W; __half* d; int K, Kp, rb;
    if (b < Kp0)            { W = W0; d = d0; K = K0; Kp = Kp0; rb = b; }
    else if (b < Kp0 + Kp1) { W = W1; d = d1; K = K1; Kp = Kp1; rb = b - Kp0; }
    else                    { W = W2; d = d2; K = K2; Kp = Kp2; rb = b - Kp0 - Kp1; }
    int f = rb * 256 + threadIdx.x;
    int u2 = f >> 2, q = f & 3;
    int ln = u2 & 31, jj = (u2 >> 5) & 3, nb = (u2 >> 7) & 7, ks = u2 >> 10;
    int n = nb * 32 + jj * 8 + (ln >> 2);
    int k = ks * 16 + 2 * (ln & 3) + (q & 1) + 8 * (q >> 1);
    d[f] = __float2half((k < K) ? W[(size_t)k * 256 + n] : 0.f);
}

// ---------------- geometry (writes fp16 features) ----------------
__global__ void k_geom(const float* __restrict__ vec, const float* __restrict__ attrs,
                       const int* __restrict__ snd, const int* __restrict__ rcv,
                       __half* __restrict__ feat, float* __restrict__ uo, float* __restrict__ Yo)
{
    int e = blockIdx.x * blockDim.x + threadIdx.x;
    if (e >= EE) return;
    float vx = vec[3*e+0], vy = vec[3*e+1], vz = vec[3*e+2];
    float d2 = vx*vx + vy*vy + vz*vz;
    float d  = sqrtf(d2);
    float d6 = d2 * d2 * d2;
    float env = 1.0f + d6 * (-28.0f + d * (48.0f - 21.0f * d));
    uo[e] = env;
    float invd = 1.0f / d;
    const float S2 = 1.4142135623730951f;
    __half2* hp = (__half2*)(feat + (size_t)e * 64);
    float bs[8];
    #pragma unroll
    for (int k = 1; k <= 8; k++)
        bs[k-1] = S2 * sinpif((float)k * d) * invd;
    #pragma unroll
    for (int q = 0; q < 4; q++)
        hp[q] = __floats2half2_rn(bs[2*q], bs[2*q+1]);
    int s = snd[e], r = rcv[e];
    #pragma unroll
    for (int i = 0; i < 8; i++)
        hp[4 + i] = __floats2half2_rn(attrs[s*16 + 2*i], attrs[s*16 + 2*i + 1]);
    #pragma unroll
    for (int i = 0; i < 8; i++)
        hp[12 + i] = __floats2half2_rn(attrs[r*16 + 2*i], attrs[r*16 + 2*i + 1]);
    #pragma unroll
    for (int i = 20; i < 32; i++) hp[i] = __floats2half2_rn(0.f, 0.f);

    float x = vx*invd, y = vy*invd, z = vz*invd;
    const float s3  = 1.7320508075688772f;
    const float s5  = 2.2360679774997896f;
    const float s15 = 3.8729833462074170f;
    const float s7  = 2.6457513110645907f;
    const float c33 = 2.0916500663351885f;
    const float c32 = 10.246950765959598f;
    const float c31 = 1.6201851746019649f;
    float* Yp = Yo + (size_t)e * 16;
    Yp[0]  = 1.0f;
    Yp[1]  = s3 * x;  Yp[2]  = s3 * y;  Yp[3]  = s3 * z;
    Yp[4]  = s15 * x * y;  Yp[5]  = s15 * y * z;
    Yp[6]  = 0.5f * s5 * (3.0f*z*z - 1.0f);
    Yp[7]  = s15 * x * z;
    Yp[8]  = 0.5f * s15 * (x*x - y*y);
    Yp[9]  = c33 * y * (3.0f*x*x - y*y);
    Yp[10] = c32 * x * y * z;
    Yp[11] = c31 * y * (5.0f*z*z - 1.0f);
    Yp[12] = 0.5f * s7 * (5.0f*z*z*z - 3.0f*z);
    Yp[13] = c31 * x * (5.0f*z*z - 1.0f);
    Yp[14] = 0.5f * c32 * z * (x*x - y*y);
    Yp[15] = c33 * x * (x*x - 3.0f*y*y);
}

// ---------------- (E,256)h @ (256,16) x2 sharing one xh read ----------
__global__ __launch_bounds__(128) void gemm_n16_dual(const __half* __restrict__ X,
                                                     const float* __restrict__ Wa,
                                                     const float* __restrict__ Wb,
                                                     float* __restrict__ Sa,
                                                     float* __restrict__ Sb)
{
    __shared__ __align__(16) float Ws[8192];
    int tid = threadIdx.x;
    #pragma unroll
    for (int i = 0; i < 8; i++)
        ((float4*)Ws)[tid + i * 128] = ((const float4*)Wa)[tid + i * 128];
    #pragma unroll
    for (int i = 0; i < 8; i++)
        ((float4*)(Ws + 4096))[tid + i * 128] = ((const float4*)Wb)[tid + i * 128];
    __syncthreads();
    size_t e = (size_t)blockIdx.x * 128 + tid;
    const uint2* xr = (const uint2*)(X + e * 256);   // 4 halfs per load
    float acca[16], accb[16];
    #pragma unroll
    for (int c = 0; c < 16; c++) { acca[c] = 0.f; accb[c] = 0.f; }
    #pragma unroll 2
    for (int k4 = 0; k4 < 64; k4++) {
        uint2 v = xr[k4];
        float2 f0 = unpackh2(v.x), f1 = unpackh2(v.y);
        float xs[4] = {f0.x, f0.y, f1.x, f1.y};
        #pragma unroll
        for (int j = 0; j < 4; j++) {
            const float4* wra = (const float4*)&Ws[(k4 * 4 + j) * 16];
            const float4* wrb = (const float4*)&Ws[4096 + (k4 * 4 + j) * 16];
            #pragma unroll
            for (int q = 0; q < 4; q++) {
                float4 wa = wra[q], wb = wrb[q];
                acca[q*4+0] += xs[j] * wa.x;  accb[q*4+0] += xs[j] * wb.x;
                acca[q*4+1] += xs[j] * wa.y;  accb[q*4+1] += xs[j] * wb.y;
                acca[q*4+2] += xs[j] * wa.z;  accb[q*4+2] += xs[j] * wb.z;
                acca[q*4+3] += xs[j] * wa.w;  accb[q*4+3] += xs[j] * wb.w;
            }
        }
    }
    float4* spa = (float4*)(Sa + e * 16);
    float4* spb = (float4*)(Sb + e * 16);
    #pragma unroll
    for (int q = 0; q < 4; q++) {
        spa[q] = make_float4(acca[q*4], acca[q*4+1], acca[q*4+2], acca[q*4+3]);
        spb[q] = make_float4(accb[q*4], accb[q*4+1], accb[q*4+2], accb[q*4+3]);
    }
}

// ---------------- single-output N=16 GEMM (layer-1 w, xh input) ----------------
__global__ __launch_bounds__(128) void gemm_n16(const __half* __restrict__ X,
                                                const float* __restrict__ W,
                                                float* __restrict__ S)
{
    __shared__ __align__(16) float Ws[4096];
    int tid = threadIdx.x;
    #pragma unroll
    for (int i = 0; i < 8; i++)
        ((float4*)Ws)[tid + i * 128] = ((const float4*)W)[tid + i * 128];
    __syncthreads();
    size_t e = (size_t)blockIdx.x * 128 + tid;
    const uint2* xr = (const uint2*)(X + e * 256);
    float acc[16];
    #pragma unroll
    for (int c = 0; c < 16; c++) acc[c] = 0.f;
    #pragma unroll 4
    for (int k4 = 0; k4 < 64; k4++) {
        uint2 v = xr[k4];
        float2 f0 = unpackh2(v.x), f1 = unpackh2(v.y);
        float xs[4] = {f0.x, f0.y, f1.x, f1.y};
        #pragma unroll
        for (int j = 0; j < 4; j++) {
            const float4* wr = (const float4*)&Ws[(k4 * 4 + j) * 16];
            #pragma unroll
            for (int q = 0; q < 4; q++) {
                float4 w = wr[q];
                acc[q*4+0] += xs[j] * w.x;
                acc[q*4+1] += xs[j] * w.y;
                acc[q*4+2] += xs[j] * w.z;
                acc[q*4+3] += xs[j] * w.w;
            }
        }
    }
    float4* sp = (float4*)(S + e * 16);
    #pragma unroll
    for (int q = 0; q < 4; q++)
        sp[q] = make_float4(acc[q*4], acc[q*4+1], acc[q*4+2], acc[q*4+3]);
}

__global__ void k_zero4(float4* p, int n4)
{
    int i = blockIdx.x * blockDim.x + threadIdx.x;
    if (i < n4) p[i] = make_float4(0.f, 0.f, 0.f, 0.f);
}

// ---------------- segment_sum scatter: vector reds ----------
__global__ void k_scatter(const float* __restrict__ w, const float* __restrict__ Y,
                          const int* __restrict__ snd, float* __restrict__ wY)
{
    int idx = blockIdx.x * blockDim.x + threadIdx.x;   // e*16 + m
    int e = idx >> 4, m = idx & 15;
    float wv = w[idx];
    int s = snd[e];
    float* base = wY + (size_t)s * 256 + m * 16;
    const float4* Y4 = (const float4*)(Y + (size_t)e * 16);
    #pragma unroll
    for (int q = 0; q < 4; q++) {
        float4 y = Y4[q];
        red4(base + q * 4, wv * y.x, wv * y.y, wv * y.z, wv * y.w);
    }
}

// ---------------- layer-0 update (fp16 VV0 out) ----------------
__global__ __launch_bounds__(256)
void k_update0(const int* __restrict__ snd, const float* __restrict__ wY,
               const float* __restrict__ s16, const float* __restrict__ Y,
               float* __restrict__ V0, __half* __restrict__ VV0ph,
               const float* __restrict__ Wlsh)
{
    __shared__ float Wcol0[16];
    int tid = threadIdx.x;
    if (tid < 16) Wcol0[tid] = Wlsh[tid * 16];
    __syncthreads();
    int idx = blockIdx.x * 256 + tid;
    int e = idx >> 4, m = idx & 15;
    int s = snd[e];
    float xv = s16[idx];
    const float4* wyp = (const float4*)(wY + (size_t)s * 256 + m * 16);
    const float4* yp  = (const float4*)(Y + (size_t)e * 16);
    float vv[16];
    #pragma unroll
    for (int q = 0; q < 4; q++) {
        float4 a = wyp[q];
        float4 y = yp[q];
        vv[q*4+0] = 0.25f * a.x * xv * y.x;
        vv[q*4+1] = 0.25f * a.y * xv * y.y;
        vv[q*4+2] = 0.25f * a.z * xv * y.z;
        vv[q*4+3] = 0.25f * a.w * xv * y.w;
    }
    VV0ph[(size_t)e * 32 + m] = __float2half(vv[0]);
    VV0ph[(size_t)e * 32 + 16 + m] = __float2half(0.f);
    float o0 = 0.f;
    #pragma unroll
    for (int i = 0; i < 16; i++) o0 += vv[i] * Wcol0[i];
    V0[idx] = o0;
}

// ---------------- layer-1 update ----------------
__global__ __launch_bounds__(256)
void k_update1(const int* __restrict__ snd, const float* __restrict__ wY,
               const float* __restrict__ V0, __half* __restrict__ VV0ph)
{
    int idx = blockIdx.x * 256 + threadIdx.x;
    int e = idx >> 4, m = idx & 15;
    int s = snd[e];
    float wy0 = wY[(size_t)s * 256 + m * 16];
    VV0ph[(size_t)e * 32 + m] = __float2half(0.25f * wy0 * V0[idx]);
    VV0ph[(size_t)e * 32 + 16 + m] = __float2half(0.f);
}

// ---------------- host ----------------
extern "C" void kernel_launch(void* const* d_in, const int* in_sizes, int n_in,
                              void* d_out, int out_size)
{
    const float* attrs = (const float*)d_in[0];
    const float* vec   = (const float*)d_in[1];
    const int*   snd   = (const int*)d_in[2];
    const int*   rcv   = (const int*)d_in[3];
    const float* We0   = (const float*)d_in[4];
    const float* be0   = (const float*)d_in[5];
    const float* We1   = (const float*)d_in[6];
    const float* be1   = (const float*)d_in[7];
    const float* Wv0   = (const float*)d_in[8];
    const float* Wlw   = (const float*)d_in[9];
    const float* Wlsh  = (const float*)d_in[10];
    const float* Wly1  = (const float*)d_in[11];
    const float* bly1  = (const float*)d_in[12];
    const float* Wly2  = (const float*)d_in[13];
    const float* bly2  = (const float*)d_in[14];
    const float* Wout  = (const float*)d_in[15];
    float* out = (float*)d_out;

    __half *feath, *xh, *VV0ph, *Bt;
    float *uu, *Y, *s16, *w16, *V0, *wY;
    cudaGetSymbolAddress((void**)&feath, g_feath);
    cudaGetSymbolAddress((void**)&uu,    g_u);
    cudaGetSymbolAddress((void**)&Y,     g_Y);
    cudaGetSymbolAddress((void**)&xh,    g_xh);
    cudaGetSymbolAddress((void**)&s16,   g_s16);
    cudaGetSymbolAddress((void**)&w16,   g_w16);
    cudaGetSymbolAddress((void**)&V0,    g_V0);
    cudaGetSymbolAddress((void**)&VV0ph, g_VV0ph);
    cudaGetSymbolAddress((void**)&wY,    g_wY);
    cudaGetSymbolAddress((void**)&Bt,    g_Bt);

    // packed fp16 weight regions, sizes 256*Kp halfs
    __half* Bt_e0  = Bt + 0;        // Kp=64
    __half* Bt_e1  = Bt + 16384;    // Kp=256
    __half* Bt_l10 = Bt + 81920;    // Kp=288
    __half* Bt_l11 = Bt + 155648;   // Kp=288
    __half* Bt_l20 = Bt + 229376;   // Kp=256
    __half* Bt_l21 = Bt + 294912;   // Kp=256

    cudaFuncSetAttribute(fgemm<2>, cudaFuncAttributeMaxDynamicSharedMemorySize, FSM_BYTES);
    cudaFuncSetAttribute(fgemm<3>, cudaFuncAttributeMaxDynamicSharedMemorySize, FSM_BYTES);
    cudaFuncSetAttribute(fgemm<4>, cudaFuncAttributeMaxDynamicSharedMemorySize, FSM_BYTES);

    const int GB = EE / 64;   // 2048 CTAs

    k_geom<<<EE / 256, 256>>>(vec, attrs, snd, rcv, feath, uu, Y);               // 0
    k_wprep3<<<64 + 256 + 288, 256>>>(We0, Bt_e0, 40, 64,                        // 1
                                      We1, Bt_e1, 256, 256,
                                      Wly1, Bt_l10, 272, 288);
    k_wprep3<<<288 + 256 + 256, 256>>>(Wly1 + 272 * 256, Bt_l11, 272, 288,      // 2
                                       Wly2, Bt_l20, 256, 256,
                                       Wly2 + 256 * 256, Bt_l21, 256, 256);

    // e0 -> e1 fused                                                            // 3
    fgemm<2><<<GB, 256, FSM_BYTES>>>(feath, 64, 2, nullptr,
                                     (const uint2*)Bt_e0, 2, be0,
                                     (const uint2*)Bt_e1, be1, uu, xh,
                                     nullptr, nullptr, nullptr);

    // ---- layer 0 ----
    k_zero4<<<(NN * 256 / 4 + 255) / 256, 256>>>((float4*)wY, NN * 256 / 4);
    gemm_n16_dual<<<EE / 128, 128>>>(xh, Wv0, Wlw, s16, w16);
    k_scatter<<<EE * 16 / 256, 256>>>(w16, Y, snd, wY);
    k_update0<<<EE * 16 / 256, 256>>>(snd, wY, s16, Y, V0, VV0ph, Wlsh);
    fgemm<3><<<GB, 256, FSM_BYTES>>>(xh, 256, 8, VV0ph,
                                     (const uint2*)Bt_l10, 9, bly1,
                                     (const uint2*)Bt_l20, bly2, uu, xh,
                                     nullptr, nullptr, nullptr);

    // ---- layer 1 ----
    gemm_n16<<<EE / 128, 128>>>(xh, Wlw + 256 * 16, w16);
    k_zero4<<<(NN * 256 / 4 + 255) / 256, 256>>>((float4*)wY, NN * 256 / 4);
    k_scatter<<<EE * 16 / 256, 256>>>(w16, Y, snd, wY);
    k_update1<<<EE * 16 / 256, 256>>>(snd, wY, V0, VV0ph);
    k_zero4<<<(NN / 4 + 255) / 256, 256>>>((float4*)out, NN / 4);
    fgemm<4><<<GB, 256, FSM_BYTES>>>(xh, 256, 8, VV0ph,
                                     (const uint2*)Bt_l11, 9, bly1 + 256,
                                     (const uint2*)Bt_l21, bly2 + 256, uu, xh,
                                     Wout, rcv, out);
}